// round 6
// baseline (speedup 1.0000x reference)
#include <cuda_runtime.h>
#include <float.h>
#include <stdint.h>

// Problem constants (fixed by the dataset)
#define MAXN 20000
#define MAXE 320000
#define MAXEP (MAXE + MAXN)
#define D  64
#define H  10
#define HD 640
#define H1DIM 1500

// ----------------------------- scratch (static, allocation-free) ------------
__device__ __align__(16) float g_xl  [(size_t)MAXN * HD];
__device__ __align__(16) float g_x1  [(size_t)MAXN * HD];
__device__ __align__(16) float g_xw  [(size_t)MAXN * HD];
__device__ __align__(16) float g_asrc[(size_t)MAXN * H];
__device__ __align__(16) float g_adst[(size_t)MAXN * H];
__device__ __align__(16) float g_pmax[HD];
__device__ __align__(16) float g_psum[HD];
__device__ __align__(16) float g_h1  [H1DIM];
__device__ int g_cnt   [MAXN];
__device__ int g_rowptr[MAXN + 1];
__device__ int g_cursor[MAXN];
__device__ int g_csrc  [MAXEP];

// ----------------------------- init -----------------------------------------
__global__ void k_init(int* __restrict__ cnt, float* __restrict__ pmax,
                       float* __restrict__ psum, int N) {
    int i = blockIdx.x * blockDim.x + threadIdx.x;
    if (i < N) cnt[i] = 0;
    else if (i < N + HD) pmax[i - N] = 0.0f;
    else if (i < N + 2 * HD) psum[i - N - HD] = 0.0f;
}

// ----------------------------- CSR build -------------------------------------
__global__ void k_count(const int* __restrict__ ei, int* __restrict__ cnt, int E, int N) {
    int e = blockIdx.x * blockDim.x + threadIdx.x;
    int EP = E + N;
    if (e >= EP) return;
    int dst = (e < E) ? ei[E + e] : (e - E);
    atomicAdd(&cnt[dst], 1);
}

__global__ __launch_bounds__(1024)
void k_scan(const int* __restrict__ cnt, int* __restrict__ rowptr,
            int* __restrict__ cursor, int N, int EP) {
    __shared__ int sums[1024];
    int t = threadIdx.x;
    int per = (N + 1023) / 1024;
    int start = t * per;
    int end = min(start + per, N);
    int s = 0;
    for (int i = start; i < end; i++) s += cnt[i];
    sums[t] = s;
    __syncthreads();
    int mine = s;
    for (int off = 1; off < 1024; off <<= 1) {
        int o = (t >= off) ? sums[t - off] : 0;
        __syncthreads();
        sums[t] += o;
        __syncthreads();
    }
    int run = sums[t] - mine;
    for (int i = start; i < end; i++) {
        rowptr[i] = run;
        cursor[i] = run;
        run += cnt[i];
    }
    if (t == 0) rowptr[N] = EP;
}

__global__ void k_scatter(const int* __restrict__ ei, int* __restrict__ cursor,
                          int* __restrict__ csrc, int E, int N) {
    int e = blockIdx.x * blockDim.x + threadIdx.x;
    int EP = E + N;
    if (e >= EP) return;
    int src, dst;
    if (e < E) { src = ei[e]; dst = ei[E + e]; }
    else       { src = dst = e - E; }
    int pos = atomicAdd(&cursor[dst], 1);
    csrc[pos] = src;
}

// ----------------------------- SGEMM (fp32, GEMM1 + fused att epilogue) ------
#define BM 128
#define BN 128
#define BK 8
#define TM 8
#define TN 8
template <bool ATT>
__global__ __launch_bounds__(256)
void k_sgemm(const float* __restrict__ A, const float* __restrict__ B,
             float* __restrict__ C, int M, int Nn, int K,
             const float* __restrict__ att_src, const float* __restrict__ att_dst,
             float* __restrict__ asrc, float* __restrict__ adst) {
    __shared__ float As[BK][BM];
    __shared__ float Bs[BK][BN];
    const int tid = threadIdx.x;
    const int nTilesX = Nn / BN;
    const int bx = blockIdx.x % nTilesX;
    const int by = blockIdx.x / nTilesX;
    const int rowBase = by * BM;
    const int colBase = bx * BN;
    const int tr = tid / 16;
    const int tc = tid % 16;

    const int aRow = tid >> 1;
    const int aCol = (tid & 1) * 4;
    const int bRow = tid >> 5;
    const int bCol = (tid & 31) * 4;

    float acc[TM][TN];
#pragma unroll
    for (int i = 0; i < TM; i++)
#pragma unroll
        for (int j = 0; j < TN; j++) acc[i][j] = 0.0f;

    float4 av, bv;
    {
        const int gr = rowBase + aRow;
        if (gr < M) av = *(const float4*)&A[(size_t)gr * K + aCol];
        else        av = make_float4(0.f, 0.f, 0.f, 0.f);
        bv = *(const float4*)&B[(size_t)bRow * Nn + colBase + bCol];
    }

    for (int k0 = 0; k0 < K; k0 += BK) {
        As[aCol + 0][aRow] = av.x;
        As[aCol + 1][aRow] = av.y;
        As[aCol + 2][aRow] = av.z;
        As[aCol + 3][aRow] = av.w;
        *(float4*)&Bs[bRow][bCol] = bv;
        __syncthreads();

        if (k0 + BK < K) {
            const int gr = rowBase + aRow;
            if (gr < M) av = *(const float4*)&A[(size_t)gr * K + k0 + BK + aCol];
            else        av = make_float4(0.f, 0.f, 0.f, 0.f);
            bv = *(const float4*)&B[(size_t)(k0 + BK + bRow) * Nn + colBase + bCol];
        }

#pragma unroll
        for (int k = 0; k < BK; k++) {
            float ar[TM], br[TN];
#pragma unroll
            for (int i = 0; i < TM; i++) ar[i] = As[k][tr * TM + i];
#pragma unroll
            for (int j = 0; j < TN; j++) br[j] = Bs[k][tc * TN + j];
#pragma unroll
            for (int i = 0; i < TM; i++)
#pragma unroll
                for (int j = 0; j < TN; j++) acc[i][j] += ar[i] * br[j];
        }
        __syncthreads();
    }

#pragma unroll
    for (int i = 0; i < TM; i++) {
        const int gr = rowBase + tr * TM + i;
        if (gr < M) {
#pragma unroll
            for (int j = 0; j < TN; j += 4) {
                *(float4*)&C[(size_t)gr * Nn + colBase + tc * TN + j] =
                    make_float4(acc[i][j], acc[i][j + 1], acc[i][j + 2], acc[i][j + 3]);
            }
        }
    }

    if (ATT) {
        const int hloc = tc >> 3;
        const int h = bx * 2 + hloc;
        const int cih = (tc & 7) * 8;
        float as[8], ad[8];
#pragma unroll
        for (int j = 0; j < 8; j++) {
            as[j] = att_src[h * D + cih + j];
            ad[j] = att_dst[h * D + cih + j];
        }
#pragma unroll
        for (int i = 0; i < TM; i++) {
            float ps = 0.f, pd = 0.f;
#pragma unroll
            for (int j = 0; j < TN; j++) { ps += acc[i][j] * as[j]; pd += acc[i][j] * ad[j]; }
            ps += __shfl_down_sync(0xffffffffu, ps, 4, 8);
            ps += __shfl_down_sync(0xffffffffu, ps, 2, 8);
            ps += __shfl_down_sync(0xffffffffu, ps, 1, 8);
            pd += __shfl_down_sync(0xffffffffu, pd, 4, 8);
            pd += __shfl_down_sync(0xffffffffu, pd, 2, 8);
            pd += __shfl_down_sync(0xffffffffu, pd, 1, 8);
            const int gr = rowBase + tr * TM + i;
            if ((tc & 7) == 0 && gr < M) {
                asrc[gr * H + h] = ps;
                adst[gr * H + h] = pd;
            }
        }
    }
}

// ----------------------------- tf32 tensor-core GEMM (GEMM2) ------------------
// Block tile 128x128x16, 4 warps (128 threads), warp tile 64x64.
#define GAPAD 20
#define GBPAD 136
__device__ __forceinline__ uint32_t f2tf32(float x) {
    uint32_t r;
    asm("cvt.rna.tf32.f32 %0, %1;" : "=r"(r) : "f"(x));
    return r;
}

__global__ __launch_bounds__(128)
void k_gemm_tf32(const float* __restrict__ A, const float* __restrict__ B,
                 float* __restrict__ C, int M, int Nn, int K) {
    __shared__ float As[2][128][GAPAD];
    __shared__ float Bs[2][16][GBPAD];
    const int tid = threadIdx.x;
    const int warp = tid >> 5, lane = tid & 31;
    const int wm = warp & 1, wn = warp >> 1;        // 2 x 2 warp grid, 64x64 tiles
    const int nTilesX = Nn / 128;
    const int bx = blockIdx.x % nTilesX;
    const int by = blockIdx.x / nTilesX;
    const int rowBase = by * 128, colBase = bx * 128;

    const int gID = lane >> 2;
    const int tIG = lane & 3;

    float acc[4][8][4];
#pragma unroll
    for (int mt = 0; mt < 4; mt++)
#pragma unroll
        for (int nt = 0; nt < 8; nt++)
#pragma unroll
            for (int r = 0; r < 4; r++) acc[mt][nt][r] = 0.0f;

    // staging: each of 128 threads loads A row=tid, 16 cols (4 float4)
    //          and B rows tid>>5 + {0,4,8,12}, cols (tid&31)*4
    const int aR  = tid;
    const int bR  = tid >> 5;        // 0..3
    const int bC4 = (tid & 31) * 4;

    float4 avr[4], bvr[4];
    {
        const int gr = rowBase + aR;
#pragma unroll
        for (int q = 0; q < 4; q++) {
            avr[q] = (gr < M) ? *(const float4*)&A[(size_t)gr * K + q * 4]
                              : make_float4(0.f, 0.f, 0.f, 0.f);
            bvr[q] = *(const float4*)&B[(size_t)(bR + q * 4) * Nn + colBase + bC4];
        }
    }

    int buf = 0;
    for (int k0 = 0; k0 < K; k0 += 16) {
        // stage current tile (convert to tf32 once)
#pragma unroll
        for (int q = 0; q < 4; q++) {
            As[buf][aR][q * 4 + 0] = __uint_as_float(f2tf32(avr[q].x));
            As[buf][aR][q * 4 + 1] = __uint_as_float(f2tf32(avr[q].y));
            As[buf][aR][q * 4 + 2] = __uint_as_float(f2tf32(avr[q].z));
            As[buf][aR][q * 4 + 3] = __uint_as_float(f2tf32(avr[q].w));
            int rb = bR + q * 4;
            Bs[buf][rb][bC4 + 0] = __uint_as_float(f2tf32(bvr[q].x));
            Bs[buf][rb][bC4 + 1] = __uint_as_float(f2tf32(bvr[q].y));
            Bs[buf][rb][bC4 + 2] = __uint_as_float(f2tf32(bvr[q].z));
            Bs[buf][rb][bC4 + 3] = __uint_as_float(f2tf32(bvr[q].w));
        }
        __syncthreads();

        // prefetch next tile into registers
        if (k0 + 16 < K) {
            const int gr = rowBase + aR;
#pragma unroll
            for (int q = 0; q < 4; q++) {
                avr[q] = (gr < M) ? *(const float4*)&A[(size_t)gr * K + k0 + 16 + q * 4]
                                  : make_float4(0.f, 0.f, 0.f, 0.f);
                bvr[q] = *(const float4*)&B[(size_t)(k0 + 16 + bR + q * 4) * Nn + colBase + bC4];
            }
        }

#pragma unroll
        for (int ks = 0; ks < 16; ks += 8) {
            uint32_t af[4][4];
#pragma unroll
            for (int mt = 0; mt < 4; mt++) {
                int r0 = wm * 64 + mt * 16 + gID;
                int kc = ks + tIG;
                af[mt][0] = __float_as_uint(As[buf][r0][kc]);
                af[mt][1] = __float_as_uint(As[buf][r0 + 8][kc]);
                af[mt][2] = __float_as_uint(As[buf][r0][kc + 4]);
                af[mt][3] = __float_as_uint(As[buf][r0 + 8][kc + 4]);
            }
#pragma unroll
            for (int nt = 0; nt < 8; nt++) {
                int col = wn * 64 + nt * 8 + gID;
                uint32_t b0 = __float_as_uint(Bs[buf][ks + tIG][col]);
                uint32_t b1 = __float_as_uint(Bs[buf][ks + tIG + 4][col]);
#pragma unroll
                for (int mt = 0; mt < 4; mt++) {
                    asm volatile(
                        "mma.sync.aligned.m16n8k8.row.col.f32.tf32.tf32.f32 "
                        "{%0,%1,%2,%3}, {%4,%5,%6,%7}, {%8,%9}, {%0,%1,%2,%3};\n"
                        : "+f"(acc[mt][nt][0]), "+f"(acc[mt][nt][1]),
                          "+f"(acc[mt][nt][2]), "+f"(acc[mt][nt][3])
                        : "r"(af[mt][0]), "r"(af[mt][1]), "r"(af[mt][2]), "r"(af[mt][3]),
                          "r"(b0), "r"(b1));
                }
            }
        }
        buf ^= 1;
    }

#pragma unroll
    for (int mt = 0; mt < 4; mt++) {
        int r0 = rowBase + wm * 64 + mt * 16 + gID;
#pragma unroll
        for (int nt = 0; nt < 8; nt++) {
            int c0 = colBase + wn * 64 + nt * 8 + tIG * 2;
            if (r0 < M)
                *(float2*)&C[(size_t)r0 * Nn + c0] = make_float2(acc[mt][nt][0], acc[mt][nt][1]);
            if (r0 + 8 < M)
                *(float2*)&C[(size_t)(r0 + 8) * Nn + c0] = make_float2(acc[mt][nt][2], acc[mt][nt][3]);
        }
    }
}

// ----------------------------- GAT: one warp per node (float4, 2x unroll) ----
__global__ __launch_bounds__(256)
void k_gat(const int* __restrict__ rowptr, const int* __restrict__ csrc,
           const float* __restrict__ xl,
           const float* __restrict__ asrc, const float* __restrict__ adst,
           const float* __restrict__ bias, float* __restrict__ x1, int N) {
    int w = (blockIdx.x * blockDim.x + threadIdx.x) >> 5;
    int lane = threadIdx.x & 31;
    if (w >= N) return;
    const int row = rowptr[w];
    const int end = rowptr[w + 1];

    const int h = lane % H;
    const int c = lane / H;
    const float adst_h = (lane < 30) ? adst[w * H + h] : 0.f;

    // phase 1: per-head max
    float m = -FLT_MAX;
    if (lane < 30) {
        for (int i = row + c; i < end; i += 3) {
            int s = csrc[i];
            float a = asrc[s * H + h] + adst_h;
            a = a > 0.f ? a : 0.2f * a;
            m = fmaxf(m, a);
        }
    }
    {
        float mA = __shfl_sync(0xffffffffu, m, lane + 10);
        float mB = __shfl_sync(0xffffffffu, m, lane + 20);
        m = fmaxf(m, fmaxf(mA, mB));
        m = __shfl_sync(0xffffffffu, m, h);
    }

    // phase 2: per-head sum of exp
    float den = 0.f;
    if (lane < 30) {
        for (int i = row + c; i < end; i += 3) {
            int s = csrc[i];
            float a = asrc[s * H + h] + adst_h;
            a = a > 0.f ? a : 0.2f * a;
            den += expf(a - m);
        }
    }
    {
        float dA = __shfl_sync(0xffffffffu, den, lane + 10);
        float dB = __shfl_sync(0xffffffffu, den, lane + 20);
        den += dA + dB;
    }
    const float invden = 1.0f / (den + 1e-16f);

    // phase 3: weighted aggregation (float4, 2 edges in flight)
    float4 acc4[5];
#pragma unroll
    for (int j = 0; j < 5; j++) acc4[j] = make_float4(0.f, 0.f, 0.f, 0.f);

    const int hsel = lane >> 4;
    int i = row;
    for (; i + 1 < end; i += 2) {
        int s0 = csrc[i];
        int s1 = csrc[i + 1];
        float wv0 = 0.f, wv1 = 0.f;
        if (lane < H) {
            float a0 = asrc[s0 * H + lane] + adst_h;
            float a1 = asrc[s1 * H + lane] + adst_h;
            a0 = a0 > 0.f ? a0 : 0.2f * a0;
            a1 = a1 > 0.f ? a1 : 0.2f * a1;
            wv0 = expf(a0 - m) * invden;
            wv1 = expf(a1 - m) * invden;
        }
        const float4* xs0 = (const float4*)(xl + (size_t)s0 * HD);
        const float4* xs1 = (const float4*)(xl + (size_t)s1 * HD);
        float4 v0[5], v1[5];
#pragma unroll
        for (int j = 0; j < 5; j++) { v0[j] = xs0[lane + 32 * j]; v1[j] = xs1[lane + 32 * j]; }
#pragma unroll
        for (int j = 0; j < 5; j++) {
            float w0 = __shfl_sync(0xffffffffu, wv0, 2 * j + hsel);
            float w1 = __shfl_sync(0xffffffffu, wv1, 2 * j + hsel);
            acc4[j].x += v0[j].x * w0 + v1[j].x * w1;
            acc4[j].y += v0[j].y * w0 + v1[j].y * w1;
            acc4[j].z += v0[j].z * w0 + v1[j].z * w1;
            acc4[j].w += v0[j].w * w0 + v1[j].w * w1;
        }
    }
    if (i < end) {
        int s = csrc[i];
        float wv = 0.f;
        if (lane < H) {
            float a = asrc[s * H + lane] + adst_h;
            a = a > 0.f ? a : 0.2f * a;
            wv = expf(a - m) * invden;
        }
        const float4* xs4 = (const float4*)(xl + (size_t)s * HD);
#pragma unroll
        for (int j = 0; j < 5; j++) {
            float wj = __shfl_sync(0xffffffffu, wv, 2 * j + hsel);
            float4 v = xs4[lane + 32 * j];
            acc4[j].x += v.x * wj;
            acc4[j].y += v.y * wj;
            acc4[j].z += v.z * wj;
            acc4[j].w += v.w * wj;
        }
    }

    float4* xo4 = (float4*)(x1 + (size_t)w * HD);
    const float4* b4 = (const float4*)bias;
#pragma unroll
    for (int j = 0; j < 5; j++) {
        int idx = lane + 32 * j;
        float4 bb = b4[idx];
        float4 v = acc4[j];
        v.x = fmaxf(v.x + bb.x, 0.f);
        v.y = fmaxf(v.y + bb.y, 0.f);
        v.z = fmaxf(v.z + bb.z, 0.f);
        v.w = fmaxf(v.w + bb.w, 0.f);
        xo4[idx] = v;
    }
}

// ----------------------------- GCN + fused global pooling --------------------
__global__ __launch_bounds__(256)
void k_gcn_pool(const int* __restrict__ rowptr, const int* __restrict__ csrc,
                const int* __restrict__ cnt, const float* __restrict__ xw,
                const float* __restrict__ bias,
                float* __restrict__ pmax, float* __restrict__ psum, int N) {
    __shared__ float smax[HD];
    __shared__ float ssum[HD];
    const int tid = threadIdx.x;
    for (int i = tid; i < HD; i += 256) { smax[i] = 0.f; ssum[i] = 0.f; }
    __syncthreads();

    const int w = (blockIdx.x * blockDim.x + tid) >> 5;
    const int lane = tid & 31;

    if (w < N) {
        const int row = rowptr[w];
        const int end = rowptr[w + 1];
        const float dn = rsqrtf((float)(end - row));

        float4 acc4[5];
#pragma unroll
        for (int j = 0; j < 5; j++) acc4[j] = make_float4(0.f, 0.f, 0.f, 0.f);

        int i = row;
        for (; i + 1 < end; i += 2) {
            int s0 = csrc[i];
            int s1 = csrc[i + 1];
            float n0 = dn * rsqrtf((float)cnt[s0]);
            float n1 = dn * rsqrtf((float)cnt[s1]);
            const float4* xs0 = (const float4*)(xw + (size_t)s0 * HD);
            const float4* xs1 = (const float4*)(xw + (size_t)s1 * HD);
            float4 v0[5], v1[5];
#pragma unroll
            for (int j = 0; j < 5; j++) { v0[j] = xs0[lane + 32 * j]; v1[j] = xs1[lane + 32 * j]; }
#pragma unroll
            for (int j = 0; j < 5; j++) {
                acc4[j].x += v0[j].x * n0 + v1[j].x * n1;
                acc4[j].y += v0[j].y * n0 + v1[j].y * n1;
                acc4[j].z += v0[j].z * n0 + v1[j].z * n1;
                acc4[j].w += v0[j].w * n0 + v1[j].w * n1;
            }
        }
        if (i < end) {
            int s = csrc[i];
            float nrm = dn * rsqrtf((float)cnt[s]);
            const float4* xs4 = (const float4*)(xw + (size_t)s * HD);
#pragma unroll
            for (int j = 0; j < 5; j++) {
                float4 v = xs4[lane + 32 * j];
                acc4[j].x += v.x * nrm;
                acc4[j].y += v.y * nrm;
                acc4[j].z += v.z * nrm;
                acc4[j].w += v.w * nrm;
            }
        }

        const float4* b4 = (const float4*)bias;
#pragma unroll
        for (int j = 0; j < 5; j++) {
            int idx = lane + 32 * j;
            float4 bb = b4[idx];
            float4 v = acc4[j];
            v.x = fmaxf(v.x + bb.x, 0.f);
            v.y = fmaxf(v.y + bb.y, 0.f);
            v.z = fmaxf(v.z + bb.z, 0.f);
            v.w = fmaxf(v.w + bb.w, 0.f);
            int col = idx * 4;
            atomicMax((int*)&smax[col + 0], __float_as_int(v.x));
            atomicMax((int*)&smax[col + 1], __float_as_int(v.y));
            atomicMax((int*)&smax[col + 2], __float_as_int(v.z));
            atomicMax((int*)&smax[col + 3], __float_as_int(v.w));
            atomicAdd(&ssum[col + 0], v.x);
            atomicAdd(&ssum[col + 1], v.y);
            atomicAdd(&ssum[col + 2], v.z);
            atomicAdd(&ssum[col + 3], v.w);
        }
    }
    __syncthreads();

    for (int i = tid; i < HD; i += 256) {
        atomicMax((int*)&pmax[i], __float_as_int(smax[i]));
        atomicAdd(&psum[i], ssum[i]);
    }
}

// ----------------------------- MLP -------------------------------------------
__global__ void k_mlp1(const float* __restrict__ pmax, const float* __restrict__ psum,
                       const float* __restrict__ W1, const float* __restrict__ b1,
                       float* __restrict__ h1, int N) {
    int j = blockIdx.x * blockDim.x + threadIdx.x;
    if (j >= H1DIM) return;
    float acc = b1[j];
    float invN = 1.0f / (float)N;
    for (int k = 0; k < HD; k++)
        acc += pmax[k] * W1[(size_t)k * H1DIM + j];
    for (int k = 0; k < HD; k++)
        acc += psum[k] * invN * W1[(size_t)(HD + k) * H1DIM + j];
    h1[j] = fmaxf(acc, 0.0f);
}

__global__ void k_mlp2(const float* __restrict__ h1, const float* __restrict__ W2,
                       const float* __restrict__ b2, float* __restrict__ out) {
    __shared__ float acc[10];
    int tid = threadIdx.x;
    if (tid < 10) acc[tid] = 0.0f;
    __syncthreads();
    float part[10];
#pragma unroll
    for (int j = 0; j < 10; j++) part[j] = 0.0f;
    for (int k = tid; k < H1DIM; k += 256) {
        float hv = h1[k];
#pragma unroll
        for (int j = 0; j < 10; j++) part[j] += hv * W2[k * 10 + j];
    }
#pragma unroll
    for (int j = 0; j < 10; j++) atomicAdd(&acc[j], part[j]);
    __syncthreads();
    if (tid < 10) out[tid] = acc[tid] + b2[tid];
}

// ----------------------------- launch -----------------------------------------
static inline int cdiv(int a, int b) { return (a + b - 1) / b; }

extern "C" void kernel_launch(void* const* d_in, const int* in_sizes, int n_in,
                              void* d_out, int out_size) {
    const float* x       = (const float*)d_in[0];
    const float* W_gat   = (const float*)d_in[1];
    const float* att_src = (const float*)d_in[2];
    const float* att_dst = (const float*)d_in[3];
    const float* b_gat   = (const float*)d_in[4];
    const float* W_gcn   = (const float*)d_in[5];
    const float* b_gcn   = (const float*)d_in[6];
    const float* W1      = (const float*)d_in[7];
    const float* b1      = (const float*)d_in[8];
    const float* W2      = (const float*)d_in[9];
    const float* b2      = (const float*)d_in[10];
    const int*   ei      = (const int*)d_in[11];

    const int N  = in_sizes[0] / D;
    const int E  = in_sizes[11] / 2;
    const int EP = E + N;
    float* out = (float*)d_out;

    float *p_xl, *p_x1, *p_xw, *p_asrc, *p_adst, *p_pmax, *p_psum, *p_h1;
    int *p_cnt, *p_rowptr, *p_cursor, *p_csrc;
    cudaGetSymbolAddress((void**)&p_xl,     g_xl);
    cudaGetSymbolAddress((void**)&p_x1,     g_x1);
    cudaGetSymbolAddress((void**)&p_xw,     g_xw);
    cudaGetSymbolAddress((void**)&p_asrc,   g_asrc);
    cudaGetSymbolAddress((void**)&p_adst,   g_adst);
    cudaGetSymbolAddress((void**)&p_pmax,   g_pmax);
    cudaGetSymbolAddress((void**)&p_psum,   g_psum);
    cudaGetSymbolAddress((void**)&p_h1,     g_h1);
    cudaGetSymbolAddress((void**)&p_cnt,    g_cnt);
    cudaGetSymbolAddress((void**)&p_rowptr, g_rowptr);
    cudaGetSymbolAddress((void**)&p_cursor, g_cursor);
    cudaGetSymbolAddress((void**)&p_csrc,   g_csrc);

    // init + CSR build
    k_init<<<cdiv(N + 2 * HD, 256), 256>>>(p_cnt, p_pmax, p_psum, N);
    k_count<<<cdiv(EP, 256), 256>>>(ei, p_cnt, E, N);
    k_scan<<<1, 1024>>>(p_cnt, p_rowptr, p_cursor, N, EP);
    k_scatter<<<cdiv(EP, 256), 256>>>(ei, p_cursor, p_csrc, E, N);
    // GEMM1 (fp32) + fused attention scores
    k_sgemm<true><<<cdiv(N, BM) * (HD / BN), 256>>>(x, W_gat, p_xl, N, HD, D,
                                                    att_src, att_dst, p_asrc, p_adst);
    // GAT softmax + aggregation
    k_gat<<<cdiv(N * 32, 256), 256>>>(p_rowptr, p_csrc, p_xl, p_asrc, p_adst,
                                      b_gat, p_x1, N);
    // GEMM2: tf32 tensor cores (double-buffered, 64x64 warp tiles)
    k_gemm_tf32<<<cdiv(N, 128) * (HD / 128), 128>>>(p_x1, W_gcn, p_xw, N, HD, HD);
    // GCN aggregation + fused global pooling
    k_gcn_pool<<<cdiv(N * 32, 256), 256>>>(p_rowptr, p_csrc, p_cnt, p_xw, b_gcn,
                                           p_pmax, p_psum, N);
    // MLP head
    k_mlp1<<<cdiv(H1DIM, 256), 256>>>(p_pmax, p_psum, W1, b1, p_h1, N);
    k_mlp2<<<1, 256>>>(p_h1, W2, b2, out);
}

// round 7
// speedup vs baseline: 1.0479x; 1.0479x over previous
#include <cuda_runtime.h>
#include <float.h>
#include <stdint.h>

// Problem constants (fixed by the dataset)
#define MAXN 20000
#define MAXE 320000
#define MAXEP (MAXE + MAXN)
#define D  64
#define H  10
#define HD 640
#define H1DIM 1500

// ----------------------------- scratch (static, allocation-free) ------------
__device__ __align__(16) float g_xl  [(size_t)MAXN * HD];
__device__ __align__(16) float g_x1  [(size_t)MAXN * HD];
__device__ __align__(16) float g_xw  [(size_t)MAXN * HD];
__device__ __align__(16) float g_asrc[(size_t)MAXN * H];
__device__ __align__(16) float g_adst[(size_t)MAXN * H];
__device__ __align__(16) float g_pmax[HD];
__device__ __align__(16) float g_psum[HD];
__device__ __align__(16) float g_h1  [H1DIM];
__device__ int g_cnt   [MAXN];
__device__ int g_rowptr[MAXN + 1];
__device__ int g_cursor[MAXN];
__device__ int g_csrc  [MAXEP];

// ----------------------------- init -----------------------------------------
__global__ void k_init(int* __restrict__ cnt, float* __restrict__ pmax,
                       float* __restrict__ psum, int N) {
    int i = blockIdx.x * blockDim.x + threadIdx.x;
    if (i < N) cnt[i] = 0;
    else if (i < N + HD) pmax[i - N] = 0.0f;
    else if (i < N + 2 * HD) psum[i - N - HD] = 0.0f;
}

// ----------------------------- CSR build -------------------------------------
__global__ void k_count(const int* __restrict__ ei, int* __restrict__ cnt, int E, int N) {
    int e = blockIdx.x * blockDim.x + threadIdx.x;
    int EP = E + N;
    if (e >= EP) return;
    int dst = (e < E) ? ei[E + e] : (e - E);
    atomicAdd(&cnt[dst], 1);
}

__global__ __launch_bounds__(1024)
void k_scan(const int* __restrict__ cnt, int* __restrict__ rowptr,
            int* __restrict__ cursor, int N, int EP) {
    __shared__ int sums[1024];
    int t = threadIdx.x;
    int per = (N + 1023) / 1024;
    int start = t * per;
    int end = min(start + per, N);
    int s = 0;
    for (int i = start; i < end; i++) s += cnt[i];
    sums[t] = s;
    __syncthreads();
    int mine = s;
    for (int off = 1; off < 1024; off <<= 1) {
        int o = (t >= off) ? sums[t - off] : 0;
        __syncthreads();
        sums[t] += o;
        __syncthreads();
    }
    int run = sums[t] - mine;
    for (int i = start; i < end; i++) {
        rowptr[i] = run;
        cursor[i] = run;
        run += cnt[i];
    }
    if (t == 0) rowptr[N] = EP;
}

__global__ void k_scatter(const int* __restrict__ ei, int* __restrict__ cursor,
                          int* __restrict__ csrc, int E, int N) {
    int e = blockIdx.x * blockDim.x + threadIdx.x;
    int EP = E + N;
    if (e >= EP) return;
    int src, dst;
    if (e < E) { src = ei[e]; dst = ei[E + e]; }
    else       { src = dst = e - E; }
    int pos = atomicAdd(&cursor[dst], 1);
    csrc[pos] = src;
}

// ----------------------------- SGEMM (fp32, GEMM1 + fused att epilogue) ------
#define BM 128
#define BN 128
#define BK 8
#define TM 8
#define TN 8
template <bool ATT>
__global__ __launch_bounds__(256)
void k_sgemm(const float* __restrict__ A, const float* __restrict__ B,
             float* __restrict__ C, int M, int Nn, int K,
             const float* __restrict__ att_src, const float* __restrict__ att_dst,
             float* __restrict__ asrc, float* __restrict__ adst) {
    __shared__ float As[BK][BM];
    __shared__ float Bs[BK][BN];
    const int tid = threadIdx.x;
    const int nTilesX = Nn / BN;
    const int bx = blockIdx.x % nTilesX;
    const int by = blockIdx.x / nTilesX;
    const int rowBase = by * BM;
    const int colBase = bx * BN;
    const int tr = tid / 16;
    const int tc = tid % 16;

    const int aRow = tid >> 1;
    const int aCol = (tid & 1) * 4;
    const int bRow = tid >> 5;
    const int bCol = (tid & 31) * 4;

    float acc[TM][TN];
#pragma unroll
    for (int i = 0; i < TM; i++)
#pragma unroll
        for (int j = 0; j < TN; j++) acc[i][j] = 0.0f;

    float4 av, bv;
    {
        const int gr = rowBase + aRow;
        if (gr < M) av = *(const float4*)&A[(size_t)gr * K + aCol];
        else        av = make_float4(0.f, 0.f, 0.f, 0.f);
        bv = *(const float4*)&B[(size_t)bRow * Nn + colBase + bCol];
    }

    for (int k0 = 0; k0 < K; k0 += BK) {
        As[aCol + 0][aRow] = av.x;
        As[aCol + 1][aRow] = av.y;
        As[aCol + 2][aRow] = av.z;
        As[aCol + 3][aRow] = av.w;
        *(float4*)&Bs[bRow][bCol] = bv;
        __syncthreads();

        if (k0 + BK < K) {
            const int gr = rowBase + aRow;
            if (gr < M) av = *(const float4*)&A[(size_t)gr * K + k0 + BK + aCol];
            else        av = make_float4(0.f, 0.f, 0.f, 0.f);
            bv = *(const float4*)&B[(size_t)(k0 + BK + bRow) * Nn + colBase + bCol];
        }

#pragma unroll
        for (int k = 0; k < BK; k++) {
            float ar[TM], br[TN];
#pragma unroll
            for (int i = 0; i < TM; i++) ar[i] = As[k][tr * TM + i];
#pragma unroll
            for (int j = 0; j < TN; j++) br[j] = Bs[k][tc * TN + j];
#pragma unroll
            for (int i = 0; i < TM; i++)
#pragma unroll
                for (int j = 0; j < TN; j++) acc[i][j] += ar[i] * br[j];
        }
        __syncthreads();
    }

#pragma unroll
    for (int i = 0; i < TM; i++) {
        const int gr = rowBase + tr * TM + i;
        if (gr < M) {
#pragma unroll
            for (int j = 0; j < TN; j += 4) {
                *(float4*)&C[(size_t)gr * Nn + colBase + tc * TN + j] =
                    make_float4(acc[i][j], acc[i][j + 1], acc[i][j + 2], acc[i][j + 3]);
            }
        }
    }

    if (ATT) {
        const int hloc = tc >> 3;
        const int h = bx * 2 + hloc;
        const int cih = (tc & 7) * 8;
        float as[8], ad[8];
#pragma unroll
        for (int j = 0; j < 8; j++) {
            as[j] = att_src[h * D + cih + j];
            ad[j] = att_dst[h * D + cih + j];
        }
#pragma unroll
        for (int i = 0; i < TM; i++) {
            float ps = 0.f, pd = 0.f;
#pragma unroll
            for (int j = 0; j < TN; j++) { ps += acc[i][j] * as[j]; pd += acc[i][j] * ad[j]; }
            ps += __shfl_down_sync(0xffffffffu, ps, 4, 8);
            ps += __shfl_down_sync(0xffffffffu, ps, 2, 8);
            ps += __shfl_down_sync(0xffffffffu, ps, 1, 8);
            pd += __shfl_down_sync(0xffffffffu, pd, 4, 8);
            pd += __shfl_down_sync(0xffffffffu, pd, 2, 8);
            pd += __shfl_down_sync(0xffffffffu, pd, 1, 8);
            const int gr = rowBase + tr * TM + i;
            if ((tc & 7) == 0 && gr < M) {
                asrc[gr * H + h] = ps;
                adst[gr * H + h] = pd;
            }
        }
    }
}

// ----------------------------- tf32 tensor-core GEMM (GEMM2) ------------------
// R5 configuration: block 128x128x16, 8 warps (256 threads), warp tile 32x64.
#define GAPAD 20
#define GBPAD 136
__device__ __forceinline__ uint32_t f2tf32(float x) {
    uint32_t r;
    asm("cvt.rna.tf32.f32 %0, %1;" : "=r"(r) : "f"(x));
    return r;
}

__global__ __launch_bounds__(256)
void k_gemm_tf32(const float* __restrict__ A, const float* __restrict__ B,
                 float* __restrict__ C, int M, int Nn, int K) {
    __shared__ float As[2][128][GAPAD];
    __shared__ float Bs[2][16][GBPAD];
    const int tid = threadIdx.x;
    const int warp = tid >> 5, lane = tid & 31;
    const int wm = warp & 3, wn = warp >> 2;        // 4 x 2 warp grid
    const int nTilesX = Nn / 128;
    const int bx = blockIdx.x % nTilesX;
    const int by = blockIdx.x / nTilesX;
    const int rowBase = by * 128, colBase = bx * 128;

    const int gID = lane >> 2;
    const int tIG = lane & 3;

    float acc[2][8][4];
#pragma unroll
    for (int mt = 0; mt < 2; mt++)
#pragma unroll
        for (int nt = 0; nt < 8; nt++)
#pragma unroll
            for (int r = 0; r < 4; r++) acc[mt][nt][r] = 0.0f;

    const int aR  = tid >> 2;
    const int aC4 = (tid & 3) * 4;
    const int bR  = tid >> 5;
    const int bC4 = lane * 4;

    float4 avr[2], bvr[2];
#pragma unroll
    for (int half = 0; half < 2; half++) {
        int gr = rowBase + aR + half * 64;
        avr[half] = (gr < M) ? *(const float4*)&A[(size_t)gr * K + aC4]
                             : make_float4(0.f, 0.f, 0.f, 0.f);
        bvr[half] = *(const float4*)&B[(size_t)(bR + half * 8) * Nn + colBase + bC4];
    }

    int buf = 0;
    for (int k0 = 0; k0 < K; k0 += 16) {
#pragma unroll
        for (int half = 0; half < 2; half++) {
            int r = aR + half * 64;
            As[buf][r][aC4 + 0] = __uint_as_float(f2tf32(avr[half].x));
            As[buf][r][aC4 + 1] = __uint_as_float(f2tf32(avr[half].y));
            As[buf][r][aC4 + 2] = __uint_as_float(f2tf32(avr[half].z));
            As[buf][r][aC4 + 3] = __uint_as_float(f2tf32(avr[half].w));
            int rb = bR + half * 8;
            Bs[buf][rb][bC4 + 0] = __uint_as_float(f2tf32(bvr[half].x));
            Bs[buf][rb][bC4 + 1] = __uint_as_float(f2tf32(bvr[half].y));
            Bs[buf][rb][bC4 + 2] = __uint_as_float(f2tf32(bvr[half].z));
            Bs[buf][rb][bC4 + 3] = __uint_as_float(f2tf32(bvr[half].w));
        }
        __syncthreads();

        if (k0 + 16 < K) {
#pragma unroll
            for (int half = 0; half < 2; half++) {
                int gr = rowBase + aR + half * 64;
                avr[half] = (gr < M) ? *(const float4*)&A[(size_t)gr * K + k0 + 16 + aC4]
                                     : make_float4(0.f, 0.f, 0.f, 0.f);
                bvr[half] = *(const float4*)&B[(size_t)(k0 + 16 + bR + half * 8) * Nn + colBase + bC4];
            }
        }

#pragma unroll
        for (int ks = 0; ks < 16; ks += 8) {
            uint32_t af[2][4];
#pragma unroll
            for (int mt = 0; mt < 2; mt++) {
                int r0 = wm * 32 + mt * 16 + gID;
                int kc = ks + tIG;
                af[mt][0] = __float_as_uint(As[buf][r0][kc]);
                af[mt][1] = __float_as_uint(As[buf][r0 + 8][kc]);
                af[mt][2] = __float_as_uint(As[buf][r0][kc + 4]);
                af[mt][3] = __float_as_uint(As[buf][r0 + 8][kc + 4]);
            }
#pragma unroll
            for (int nt = 0; nt < 8; nt++) {
                int col = wn * 64 + nt * 8 + gID;
                uint32_t b0 = __float_as_uint(Bs[buf][ks + tIG][col]);
                uint32_t b1 = __float_as_uint(Bs[buf][ks + tIG + 4][col]);
#pragma unroll
                for (int mt = 0; mt < 2; mt++) {
                    asm volatile(
                        "mma.sync.aligned.m16n8k8.row.col.f32.tf32.tf32.f32 "
                        "{%0,%1,%2,%3}, {%4,%5,%6,%7}, {%8,%9}, {%0,%1,%2,%3};\n"
                        : "+f"(acc[mt][nt][0]), "+f"(acc[mt][nt][1]),
                          "+f"(acc[mt][nt][2]), "+f"(acc[mt][nt][3])
                        : "r"(af[mt][0]), "r"(af[mt][1]), "r"(af[mt][2]), "r"(af[mt][3]),
                          "r"(b0), "r"(b1));
                }
            }
        }
        buf ^= 1;
    }

#pragma unroll
    for (int mt = 0; mt < 2; mt++) {
        int r0 = rowBase + wm * 32 + mt * 16 + gID;
#pragma unroll
        for (int nt = 0; nt < 8; nt++) {
            int c0 = colBase + wn * 64 + nt * 8 + tIG * 2;
            if (r0 < M)
                *(float2*)&C[(size_t)r0 * Nn + c0] = make_float2(acc[mt][nt][0], acc[mt][nt][1]);
            if (r0 + 8 < M)
                *(float2*)&C[(size_t)(r0 + 8) * Nn + c0] = make_float2(acc[mt][nt][2], acc[mt][nt][3]);
        }
    }
}

// ----------------------------- GAT: one warp per node ------------------------
// Online softmax (single pass over edges for m+den), float4 gathers, 2x unroll.
__global__ __launch_bounds__(256)
void k_gat(const int* __restrict__ rowptr, const int* __restrict__ csrc,
           const float* __restrict__ xl,
           const float* __restrict__ asrc, const float* __restrict__ adst,
           const float* __restrict__ bias, float* __restrict__ x1, int N) {
    int w = (blockIdx.x * blockDim.x + threadIdx.x) >> 5;
    int lane = threadIdx.x & 31;
    if (w >= N) return;
    const int row = rowptr[w];
    const int end = rowptr[w + 1];

    const int h = lane % H;       // head owned (lanes 0..29)
    const int c = lane / H;       // chunk 0..2
    const float adst_h = (lane < 30) ? adst[w * H + h] : 0.f;

    // ---- single-pass online softmax: per-lane running (m, den) ----
    float m = -FLT_MAX, den = 0.f;
    if (lane < 30) {
        for (int i = row + c; i < end; i += 3) {
            int s = csrc[i];
            float a = asrc[s * H + h] + adst_h;
            a = a > 0.f ? a : 0.2f * a;
            float nm = fmaxf(m, a);
            den = den * __expf(m - nm) + __expf(a - nm);
            m = nm;
        }
    }
    {   // combine the 3 lanes per head (lanes l, l+10, l+20) into lanes 0..9
        float mA = __shfl_sync(0xffffffffu, m,   lane + 10);
        float dA = __shfl_sync(0xffffffffu, den, lane + 10);
        float mB = __shfl_sync(0xffffffffu, m,   lane + 20);
        float dB = __shfl_sync(0xffffffffu, den, lane + 20);
        float M2 = fmaxf(m, fmaxf(mA, mB));
        den = den * __expf(m - M2) + dA * __expf(mA - M2) + dB * __expf(mB - M2);
        m = M2;                                   // lanes 0..9 now correct
    }
    const float invden = 1.0f / (den + 1e-16f);   // valid on lanes 0..9

    // ---- weighted aggregation (float4, 2 edges in flight) ----
    float4 acc4[5];
#pragma unroll
    for (int j = 0; j < 5; j++) acc4[j] = make_float4(0.f, 0.f, 0.f, 0.f);

    const int hsel = lane >> 4;
    int i = row;
    for (; i + 1 < end; i += 2) {
        int s0 = csrc[i];
        int s1 = csrc[i + 1];
        float wv0 = 0.f, wv1 = 0.f;
        if (lane < H) {
            float a0 = asrc[s0 * H + lane] + adst_h;
            float a1 = asrc[s1 * H + lane] + adst_h;
            a0 = a0 > 0.f ? a0 : 0.2f * a0;
            a1 = a1 > 0.f ? a1 : 0.2f * a1;
            wv0 = __expf(a0 - m) * invden;
            wv1 = __expf(a1 - m) * invden;
        }
        const float4* xs0 = (const float4*)(xl + (size_t)s0 * HD);
        const float4* xs1 = (const float4*)(xl + (size_t)s1 * HD);
        float4 v0[5], v1[5];
#pragma unroll
        for (int j = 0; j < 5; j++) { v0[j] = xs0[lane + 32 * j]; v1[j] = xs1[lane + 32 * j]; }
#pragma unroll
        for (int j = 0; j < 5; j++) {
            float w0 = __shfl_sync(0xffffffffu, wv0, 2 * j + hsel);
            float w1 = __shfl_sync(0xffffffffu, wv1, 2 * j + hsel);
            acc4[j].x += v0[j].x * w0 + v1[j].x * w1;
            acc4[j].y += v0[j].y * w0 + v1[j].y * w1;
            acc4[j].z += v0[j].z * w0 + v1[j].z * w1;
            acc4[j].w += v0[j].w * w0 + v1[j].w * w1;
        }
    }
    if (i < end) {
        int s = csrc[i];
        float wv = 0.f;
        if (lane < H) {
            float a = asrc[s * H + lane] + adst_h;
            a = a > 0.f ? a : 0.2f * a;
            wv = __expf(a - m) * invden;
        }
        const float4* xs4 = (const float4*)(xl + (size_t)s * HD);
#pragma unroll
        for (int j = 0; j < 5; j++) {
            float wj = __shfl_sync(0xffffffffu, wv, 2 * j + hsel);
            float4 v = xs4[lane + 32 * j];
            acc4[j].x += v.x * wj;
            acc4[j].y += v.y * wj;
            acc4[j].z += v.z * wj;
            acc4[j].w += v.w * wj;
        }
    }

    float4* xo4 = (float4*)(x1 + (size_t)w * HD);
    const float4* b4 = (const float4*)bias;
#pragma unroll
    for (int j = 0; j < 5; j++) {
        int idx = lane + 32 * j;
        float4 bb = b4[idx];
        float4 v = acc4[j];
        v.x = fmaxf(v.x + bb.x, 0.f);
        v.y = fmaxf(v.y + bb.y, 0.f);
        v.z = fmaxf(v.z + bb.z, 0.f);
        v.w = fmaxf(v.w + bb.w, 0.f);
        xo4[idx] = v;
    }
}

// ----------------------------- GCN + fused global pooling --------------------
__global__ __launch_bounds__(256)
void k_gcn_pool(const int* __restrict__ rowptr, const int* __restrict__ csrc,
                const int* __restrict__ cnt, const float* __restrict__ xw,
                const float* __restrict__ bias,
                float* __restrict__ pmax, float* __restrict__ psum, int N) {
    __shared__ float smax[HD];
    __shared__ float ssum[HD];
    const int tid = threadIdx.x;
    for (int i = tid; i < HD; i += 256) { smax[i] = 0.f; ssum[i] = 0.f; }
    __syncthreads();

    const int w = (blockIdx.x * blockDim.x + tid) >> 5;
    const int lane = tid & 31;

    if (w < N) {
        const int row = rowptr[w];
        const int end = rowptr[w + 1];
        const float dn = rsqrtf((float)(end - row));

        float4 acc4[5];
#pragma unroll
        for (int j = 0; j < 5; j++) acc4[j] = make_float4(0.f, 0.f, 0.f, 0.f);

        int i = row;
        for (; i + 1 < end; i += 2) {
            int s0 = csrc[i];
            int s1 = csrc[i + 1];
            float n0 = dn * rsqrtf((float)cnt[s0]);
            float n1 = dn * rsqrtf((float)cnt[s1]);
            const float4* xs0 = (const float4*)(xw + (size_t)s0 * HD);
            const float4* xs1 = (const float4*)(xw + (size_t)s1 * HD);
            float4 v0[5], v1[5];
#pragma unroll
            for (int j = 0; j < 5; j++) { v0[j] = xs0[lane + 32 * j]; v1[j] = xs1[lane + 32 * j]; }
#pragma unroll
            for (int j = 0; j < 5; j++) {
                acc4[j].x += v0[j].x * n0 + v1[j].x * n1;
                acc4[j].y += v0[j].y * n0 + v1[j].y * n1;
                acc4[j].z += v0[j].z * n0 + v1[j].z * n1;
                acc4[j].w += v0[j].w * n0 + v1[j].w * n1;
            }
        }
        if (i < end) {
            int s = csrc[i];
            float nrm = dn * rsqrtf((float)cnt[s]);
            const float4* xs4 = (const float4*)(xw + (size_t)s * HD);
#pragma unroll
            for (int j = 0; j < 5; j++) {
                float4 v = xs4[lane + 32 * j];
                acc4[j].x += v.x * nrm;
                acc4[j].y += v.y * nrm;
                acc4[j].z += v.z * nrm;
                acc4[j].w += v.w * nrm;
            }
        }

        const float4* b4 = (const float4*)bias;
#pragma unroll
        for (int j = 0; j < 5; j++) {
            int idx = lane + 32 * j;
            float4 bb = b4[idx];
            float4 v = acc4[j];
            v.x = fmaxf(v.x + bb.x, 0.f);
            v.y = fmaxf(v.y + bb.y, 0.f);
            v.z = fmaxf(v.z + bb.z, 0.f);
            v.w = fmaxf(v.w + bb.w, 0.f);
            int col = idx * 4;
            atomicMax((int*)&smax[col + 0], __float_as_int(v.x));
            atomicMax((int*)&smax[col + 1], __float_as_int(v.y));
            atomicMax((int*)&smax[col + 2], __float_as_int(v.z));
            atomicMax((int*)&smax[col + 3], __float_as_int(v.w));
            atomicAdd(&ssum[col + 0], v.x);
            atomicAdd(&ssum[col + 1], v.y);
            atomicAdd(&ssum[col + 2], v.z);
            atomicAdd(&ssum[col + 3], v.w);
        }
    }
    __syncthreads();

    for (int i = tid; i < HD; i += 256) {
        atomicMax((int*)&pmax[i], __float_as_int(smax[i]));
        atomicAdd(&psum[i], ssum[i]);
    }
}

// ----------------------------- MLP -------------------------------------------
__global__ void k_mlp1(const float* __restrict__ pmax, const float* __restrict__ psum,
                       const float* __restrict__ W1, const float* __restrict__ b1,
                       float* __restrict__ h1, int N) {
    int j = blockIdx.x * blockDim.x + threadIdx.x;
    if (j >= H1DIM) return;
    float acc = b1[j];
    float invN = 1.0f / (float)N;
    for (int k = 0; k < HD; k++)
        acc += pmax[k] * W1[(size_t)k * H1DIM + j];
    for (int k = 0; k < HD; k++)
        acc += psum[k] * invN * W1[(size_t)(HD + k) * H1DIM + j];
    h1[j] = fmaxf(acc, 0.0f);
}

__global__ void k_mlp2(const float* __restrict__ h1, const float* __restrict__ W2,
                       const float* __restrict__ b2, float* __restrict__ out) {
    __shared__ float acc[10];
    int tid = threadIdx.x;
    if (tid < 10) acc[tid] = 0.0f;
    __syncthreads();
    float part[10];
#pragma unroll
    for (int j = 0; j < 10; j++) part[j] = 0.0f;
    for (int k = tid; k < H1DIM; k += 256) {
        float hv = h1[k];
#pragma unroll
        for (int j = 0; j < 10; j++) part[j] += hv * W2[k * 10 + j];
    }
#pragma unroll
    for (int j = 0; j < 10; j++) atomicAdd(&acc[j], part[j]);
    __syncthreads();
    if (tid < 10) out[tid] = acc[tid] + b2[tid];
}

// ----------------------------- launch -----------------------------------------
static inline int cdiv(int a, int b) { return (a + b - 1) / b; }

extern "C" void kernel_launch(void* const* d_in, const int* in_sizes, int n_in,
                              void* d_out, int out_size) {
    const float* x       = (const float*)d_in[0];
    const float* W_gat   = (const float*)d_in[1];
    const float* att_src = (const float*)d_in[2];
    const float* att_dst = (const float*)d_in[3];
    const float* b_gat   = (const float*)d_in[4];
    const float* W_gcn   = (const float*)d_in[5];
    const float* b_gcn   = (const float*)d_in[6];
    const float* W1      = (const float*)d_in[7];
    const float* b1      = (const float*)d_in[8];
    const float* W2      = (const float*)d_in[9];
    const float* b2      = (const float*)d_in[10];
    const int*   ei      = (const int*)d_in[11];

    const int N  = in_sizes[0] / D;
    const int E  = in_sizes[11] / 2;
    const int EP = E + N;
    float* out = (float*)d_out;

    float *p_xl, *p_x1, *p_xw, *p_asrc, *p_adst, *p_pmax, *p_psum, *p_h1;
    int *p_cnt, *p_rowptr, *p_cursor, *p_csrc;
    cudaGetSymbolAddress((void**)&p_xl,     g_xl);
    cudaGetSymbolAddress((void**)&p_x1,     g_x1);
    cudaGetSymbolAddress((void**)&p_xw,     g_xw);
    cudaGetSymbolAddress((void**)&p_asrc,   g_asrc);
    cudaGetSymbolAddress((void**)&p_adst,   g_adst);
    cudaGetSymbolAddress((void**)&p_pmax,   g_pmax);
    cudaGetSymbolAddress((void**)&p_psum,   g_psum);
    cudaGetSymbolAddress((void**)&p_h1,     g_h1);
    cudaGetSymbolAddress((void**)&p_cnt,    g_cnt);
    cudaGetSymbolAddress((void**)&p_rowptr, g_rowptr);
    cudaGetSymbolAddress((void**)&p_cursor, g_cursor);
    cudaGetSymbolAddress((void**)&p_csrc,   g_csrc);

    // init + CSR build
    k_init<<<cdiv(N + 2 * HD, 256), 256>>>(p_cnt, p_pmax, p_psum, N);
    k_count<<<cdiv(EP, 256), 256>>>(ei, p_cnt, E, N);
    k_scan<<<1, 1024>>>(p_cnt, p_rowptr, p_cursor, N, EP);
    k_scatter<<<cdiv(EP, 256), 256>>>(ei, p_cursor, p_csrc, E, N);
    // GEMM1 (fp32) + fused attention scores
    k_sgemm<true><<<cdiv(N, BM) * (HD / BN), 256>>>(x, W_gat, p_xl, N, HD, D,
                                                    att_src, att_dst, p_asrc, p_adst);
    // GAT online-softmax + aggregation
    k_gat<<<cdiv(N * 32, 256), 256>>>(p_rowptr, p_csrc, p_xl, p_asrc, p_adst,
                                      b_gat, p_x1, N);
    // GEMM2: tf32 tensor cores (double-buffered, 8 warps, 32x64 warp tiles)
    k_gemm_tf32<<<cdiv(N, 128) * (HD / 128), 256>>>(p_x1, W_gcn, p_xw, N, HD, HD);
    // GCN aggregation + fused global pooling
    k_gcn_pool<<<cdiv(N * 32, 256), 256>>>(p_rowptr, p_csrc, p_cnt, p_xw, b_gcn,
                                           p_pmax, p_psum, N);
    // MLP head
    k_mlp1<<<cdiv(H1DIM, 256), 256>>>(p_pmax, p_psum, W1, b1, p_h1, N);
    k_mlp2<<<1, 256>>>(p_h1, W2, b2, out);
}

// round 8
// speedup vs baseline: 1.1445x; 1.0921x over previous
#include <cuda_runtime.h>
#include <float.h>
#include <stdint.h>

// Problem constants (fixed by the dataset)
#define MAXN 20000
#define MAXE 320000
#define MAXEP (MAXE + MAXN)
#define D  64
#define H  10
#define HD 640
#define H1DIM 1500

// ----------------------------- scratch (static, allocation-free) ------------
__device__ __align__(16) float g_xl  [(size_t)MAXN * HD];
__device__ __align__(16) float g_x1  [(size_t)MAXN * HD];
__device__ __align__(16) float g_xw  [(size_t)MAXN * HD];
__device__ __align__(16) float g_wt  [(size_t)HD * HD];    // W_gcn pre-rounded to tf32
__device__ __align__(16) float g_asrc[(size_t)MAXN * H];
__device__ __align__(16) float g_adst[(size_t)MAXN * H];
__device__ __align__(16) float g_pmax[HD];
__device__ __align__(16) float g_psum[HD];
__device__ __align__(16) float g_h1  [H1DIM];
__device__ int g_cnt   [MAXN];
__device__ int g_rowptr[MAXN + 1];
__device__ int g_cursor[MAXN];
__device__ int g_csrc  [MAXEP];

__device__ __forceinline__ uint32_t f2tf32(float x) {
    uint32_t r;
    asm("cvt.rna.tf32.f32 %0, %1;" : "=r"(r) : "f"(x));
    return r;
}
__device__ __forceinline__ float rnd_tf32(float x) {
    return __uint_as_float(f2tf32(x));
}

// ----------------------------- init -----------------------------------------
__global__ void k_init(int* __restrict__ cnt, float* __restrict__ pmax,
                       float* __restrict__ psum, int N) {
    int i = blockIdx.x * blockDim.x + threadIdx.x;
    if (i < N) cnt[i] = 0;
    else if (i < N + HD) pmax[i - N] = 0.0f;
    else if (i < N + 2 * HD) psum[i - N - HD] = 0.0f;
}

// W_gcn -> tf32-rounded copy (done once per replay; removes in-loop CVT in GEMM2)
__global__ void k_cvtw(const float* __restrict__ w, float* __restrict__ wt, int n) {
    int i = blockIdx.x * blockDim.x + threadIdx.x;
    if (i < n) wt[i] = rnd_tf32(w[i]);
}

// ----------------------------- CSR build -------------------------------------
__global__ void k_count(const int* __restrict__ ei, int* __restrict__ cnt, int E, int N) {
    int e = blockIdx.x * blockDim.x + threadIdx.x;
    int EP = E + N;
    if (e >= EP) return;
    int dst = (e < E) ? ei[E + e] : (e - E);
    atomicAdd(&cnt[dst], 1);
}

__global__ __launch_bounds__(1024)
void k_scan(const int* __restrict__ cnt, int* __restrict__ rowptr,
            int* __restrict__ cursor, int N, int EP) {
    __shared__ int sums[1024];
    int t = threadIdx.x;
    int per = (N + 1023) / 1024;
    int start = t * per;
    int end = min(start + per, N);
    int s = 0;
    for (int i = start; i < end; i++) s += cnt[i];
    sums[t] = s;
    __syncthreads();
    int mine = s;
    for (int off = 1; off < 1024; off <<= 1) {
        int o = (t >= off) ? sums[t - off] : 0;
        __syncthreads();
        sums[t] += o;
        __syncthreads();
    }
    int run = sums[t] - mine;
    for (int i = start; i < end; i++) {
        rowptr[i] = run;
        cursor[i] = run;
        run += cnt[i];
    }
    if (t == 0) rowptr[N] = EP;
}

__global__ void k_scatter(const int* __restrict__ ei, int* __restrict__ cursor,
                          int* __restrict__ csrc, int E, int N) {
    int e = blockIdx.x * blockDim.x + threadIdx.x;
    int EP = E + N;
    if (e >= EP) return;
    int src, dst;
    if (e < E) { src = ei[e]; dst = ei[E + e]; }
    else       { src = dst = e - E; }
    int pos = atomicAdd(&cursor[dst], 1);
    csrc[pos] = src;
}

// ----------------------------- tf32 tensor-core GEMM --------------------------
// Block 128x128x16, 8 warps (256 threads), warp tile 32x64, double-buffered.
// ATT: fused attention-score epilogue (GEMM1). Each warp's 64-col tile is one
//      head (h = bx*2 + wn); per-thread partial dot over its 16 cols, quad-reduced.
// CVT: round inputs to tf32 during staging (false when inputs pre-rounded).
#define GAPAD 20
#define GBPAD 136
template <bool ATT, bool CVT>
__global__ __launch_bounds__(256)
void k_gemm_tf32(const float* __restrict__ A, const float* __restrict__ B,
                 float* __restrict__ C, int M, int Nn, int K,
                 const float* __restrict__ att_src, const float* __restrict__ att_dst,
                 float* __restrict__ asrc, float* __restrict__ adst) {
    __shared__ float As[2][128][GAPAD];
    __shared__ float Bs[2][16][GBPAD];
    const int tid = threadIdx.x;
    const int warp = tid >> 5, lane = tid & 31;
    const int wm = warp & 3, wn = warp >> 2;        // 4 x 2 warp grid
    const int nTilesX = Nn / 128;
    const int bx = blockIdx.x % nTilesX;
    const int by = blockIdx.x / nTilesX;
    const int rowBase = by * 128, colBase = bx * 128;

    const int gID = lane >> 2;
    const int tIG = lane & 3;

    float acc[2][8][4];
#pragma unroll
    for (int mt = 0; mt < 2; mt++)
#pragma unroll
        for (int nt = 0; nt < 8; nt++)
#pragma unroll
            for (int r = 0; r < 4; r++) acc[mt][nt][r] = 0.0f;

    const int aR  = tid >> 2;
    const int aC4 = (tid & 3) * 4;
    const int bR  = tid >> 5;
    const int bC4 = lane * 4;

    float4 avr[2], bvr[2];
#pragma unroll
    for (int half = 0; half < 2; half++) {
        int gr = rowBase + aR + half * 64;
        avr[half] = (gr < M) ? *(const float4*)&A[(size_t)gr * K + aC4]
                             : make_float4(0.f, 0.f, 0.f, 0.f);
        bvr[half] = *(const float4*)&B[(size_t)(bR + half * 8) * Nn + colBase + bC4];
    }

    int buf = 0;
    for (int k0 = 0; k0 < K; k0 += 16) {
#pragma unroll
        for (int half = 0; half < 2; half++) {
            int r = aR + half * 64;
            As[buf][r][aC4 + 0] = CVT ? rnd_tf32(avr[half].x) : avr[half].x;
            As[buf][r][aC4 + 1] = CVT ? rnd_tf32(avr[half].y) : avr[half].y;
            As[buf][r][aC4 + 2] = CVT ? rnd_tf32(avr[half].z) : avr[half].z;
            As[buf][r][aC4 + 3] = CVT ? rnd_tf32(avr[half].w) : avr[half].w;
            int rb = bR + half * 8;
            Bs[buf][rb][bC4 + 0] = CVT ? rnd_tf32(bvr[half].x) : bvr[half].x;
            Bs[buf][rb][bC4 + 1] = CVT ? rnd_tf32(bvr[half].y) : bvr[half].y;
            Bs[buf][rb][bC4 + 2] = CVT ? rnd_tf32(bvr[half].z) : bvr[half].z;
            Bs[buf][rb][bC4 + 3] = CVT ? rnd_tf32(bvr[half].w) : bvr[half].w;
        }
        __syncthreads();

        if (k0 + 16 < K) {
#pragma unroll
            for (int half = 0; half < 2; half++) {
                int gr = rowBase + aR + half * 64;
                avr[half] = (gr < M) ? *(const float4*)&A[(size_t)gr * K + k0 + 16 + aC4]
                                     : make_float4(0.f, 0.f, 0.f, 0.f);
                bvr[half] = *(const float4*)&B[(size_t)(k0 + 16 + bR + half * 8) * Nn + colBase + bC4];
            }
        }

#pragma unroll
        for (int ks = 0; ks < 16; ks += 8) {
            uint32_t af[2][4];
#pragma unroll
            for (int mt = 0; mt < 2; mt++) {
                int r0 = wm * 32 + mt * 16 + gID;
                int kc = ks + tIG;
                af[mt][0] = __float_as_uint(As[buf][r0][kc]);
                af[mt][1] = __float_as_uint(As[buf][r0 + 8][kc]);
                af[mt][2] = __float_as_uint(As[buf][r0][kc + 4]);
                af[mt][3] = __float_as_uint(As[buf][r0 + 8][kc + 4]);
            }
#pragma unroll
            for (int nt = 0; nt < 8; nt++) {
                int col = wn * 64 + nt * 8 + gID;
                uint32_t b0 = __float_as_uint(Bs[buf][ks + tIG][col]);
                uint32_t b1 = __float_as_uint(Bs[buf][ks + tIG + 4][col]);
#pragma unroll
                for (int mt = 0; mt < 2; mt++) {
                    asm volatile(
                        "mma.sync.aligned.m16n8k8.row.col.f32.tf32.tf32.f32 "
                        "{%0,%1,%2,%3}, {%4,%5,%6,%7}, {%8,%9}, {%0,%1,%2,%3};\n"
                        : "+f"(acc[mt][nt][0]), "+f"(acc[mt][nt][1]),
                          "+f"(acc[mt][nt][2]), "+f"(acc[mt][nt][3])
                        : "r"(af[mt][0]), "r"(af[mt][1]), "r"(af[mt][2]), "r"(af[mt][3]),
                          "r"(b0), "r"(b1));
                }
            }
        }
        buf ^= 1;
    }

    // write C
#pragma unroll
    for (int mt = 0; mt < 2; mt++) {
        int r0 = rowBase + wm * 32 + mt * 16 + gID;
#pragma unroll
        for (int nt = 0; nt < 8; nt++) {
            int c0 = colBase + wn * 64 + nt * 8 + tIG * 2;
            if (r0 < M)
                *(float2*)&C[(size_t)r0 * Nn + c0] = make_float2(acc[mt][nt][0], acc[mt][nt][1]);
            if (r0 + 8 < M)
                *(float2*)&C[(size_t)(r0 + 8) * Nn + c0] = make_float2(acc[mt][nt][2], acc[mt][nt][3]);
        }
    }

    if (ATT) {
        // this warp's 64-col tile is head h; thread owns cols nt*8 + tIG*2 + {0,1}
        const int h = bx * 2 + wn;
        float as[16], ad[16];
#pragma unroll
        for (int nt = 0; nt < 8; nt++)
#pragma unroll
            for (int p = 0; p < 2; p++) {
                int cih = nt * 8 + tIG * 2 + p;
                as[nt * 2 + p] = att_src[h * D + cih];
                ad[nt * 2 + p] = att_dst[h * D + cih];
            }
#pragma unroll
        for (int mt = 0; mt < 2; mt++) {
#pragma unroll
            for (int pair = 0; pair < 2; pair++) {   // pair 0: row r0 (regs 0,1); pair 1: row r0+8 (regs 2,3)
                float ps = 0.f, pd = 0.f;
#pragma unroll
                for (int nt = 0; nt < 8; nt++)
#pragma unroll
                    for (int p = 0; p < 2; p++) {
                        float v = acc[mt][nt][pair * 2 + p];
                        ps += v * as[nt * 2 + p];
                        pd += v * ad[nt * 2 + p];
                    }
                // reduce across the 4-thread quad (tIG lanes)
                ps += __shfl_down_sync(0xffffffffu, ps, 2, 4);
                ps += __shfl_down_sync(0xffffffffu, ps, 1, 4);
                pd += __shfl_down_sync(0xffffffffu, pd, 2, 4);
                pd += __shfl_down_sync(0xffffffffu, pd, 1, 4);
                int gr = rowBase + wm * 32 + mt * 16 + gID + pair * 8;
                if (tIG == 0 && gr < M) {
                    asrc[gr * H + h] = ps;
                    adst[gr * H + h] = pd;
                }
            }
        }
    }
}

// ----------------------------- GAT: one warp per node ------------------------
// Online softmax, float4 gathers 2x unrolled; output rounded to tf32 (feeds GEMM2 only).
__global__ __launch_bounds__(256)
void k_gat(const int* __restrict__ rowptr, const int* __restrict__ csrc,
           const float* __restrict__ xl,
           const float* __restrict__ asrc, const float* __restrict__ adst,
           const float* __restrict__ bias, float* __restrict__ x1, int N) {
    int w = (blockIdx.x * blockDim.x + threadIdx.x) >> 5;
    int lane = threadIdx.x & 31;
    if (w >= N) return;
    const int row = rowptr[w];
    const int end = rowptr[w + 1];

    const int h = lane % H;
    const int c = lane / H;
    const float adst_h = (lane < 30) ? adst[w * H + h] : 0.f;

    // single-pass online softmax
    float m = -FLT_MAX, den = 0.f;
    if (lane < 30) {
        for (int i = row + c; i < end; i += 3) {
            int s = csrc[i];
            float a = asrc[s * H + h] + adst_h;
            a = a > 0.f ? a : 0.2f * a;
            float nm = fmaxf(m, a);
            den = den * __expf(m - nm) + __expf(a - nm);
            m = nm;
        }
    }
    {
        float mA = __shfl_sync(0xffffffffu, m,   lane + 10);
        float dA = __shfl_sync(0xffffffffu, den, lane + 10);
        float mB = __shfl_sync(0xffffffffu, m,   lane + 20);
        float dB = __shfl_sync(0xffffffffu, den, lane + 20);
        float M2 = fmaxf(m, fmaxf(mA, mB));
        den = den * __expf(m - M2) + dA * __expf(mA - M2) + dB * __expf(mB - M2);
        m = M2;
    }
    const float invden = 1.0f / (den + 1e-16f);

    float4 acc4[5];
#pragma unroll
    for (int j = 0; j < 5; j++) acc4[j] = make_float4(0.f, 0.f, 0.f, 0.f);

    const int hsel = lane >> 4;
    int i = row;
    for (; i + 1 < end; i += 2) {
        int s0 = csrc[i];
        int s1 = csrc[i + 1];
        float wv0 = 0.f, wv1 = 0.f;
        if (lane < H) {
            float a0 = asrc[s0 * H + lane] + adst_h;
            float a1 = asrc[s1 * H + lane] + adst_h;
            a0 = a0 > 0.f ? a0 : 0.2f * a0;
            a1 = a1 > 0.f ? a1 : 0.2f * a1;
            wv0 = __expf(a0 - m) * invden;
            wv1 = __expf(a1 - m) * invden;
        }
        const float4* xs0 = (const float4*)(xl + (size_t)s0 * HD);
        const float4* xs1 = (const float4*)(xl + (size_t)s1 * HD);
        float4 v0[5], v1[5];
#pragma unroll
        for (int j = 0; j < 5; j++) { v0[j] = xs0[lane + 32 * j]; v1[j] = xs1[lane + 32 * j]; }
#pragma unroll
        for (int j = 0; j < 5; j++) {
            float w0 = __shfl_sync(0xffffffffu, wv0, 2 * j + hsel);
            float w1 = __shfl_sync(0xffffffffu, wv1, 2 * j + hsel);
            acc4[j].x += v0[j].x * w0 + v1[j].x * w1;
            acc4[j].y += v0[j].y * w0 + v1[j].y * w1;
            acc4[j].z += v0[j].z * w0 + v1[j].z * w1;
            acc4[j].w += v0[j].w * w0 + v1[j].w * w1;
        }
    }
    if (i < end) {
        int s = csrc[i];
        float wv = 0.f;
        if (lane < H) {
            float a = asrc[s * H + lane] + adst_h;
            a = a > 0.f ? a : 0.2f * a;
            wv = __expf(a - m) * invden;
        }
        const float4* xs4 = (const float4*)(xl + (size_t)s * HD);
#pragma unroll
        for (int j = 0; j < 5; j++) {
            float wj = __shfl_sync(0xffffffffu, wv, 2 * j + hsel);
            float4 v = xs4[lane + 32 * j];
            acc4[j].x += v.x * wj;
            acc4[j].y += v.y * wj;
            acc4[j].z += v.z * wj;
            acc4[j].w += v.w * wj;
        }
    }

    float4* xo4 = (float4*)(x1 + (size_t)w * HD);
    const float4* b4 = (const float4*)bias;
#pragma unroll
    for (int j = 0; j < 5; j++) {
        int idx = lane + 32 * j;
        float4 bb = b4[idx];
        float4 v = acc4[j];
        v.x = rnd_tf32(fmaxf(v.x + bb.x, 0.f));   // pre-round for GEMM2
        v.y = rnd_tf32(fmaxf(v.y + bb.y, 0.f));
        v.z = rnd_tf32(fmaxf(v.z + bb.z, 0.f));
        v.w = rnd_tf32(fmaxf(v.w + bb.w, 0.f));
        xo4[idx] = v;
    }
}

// ----------------------------- GCN + fused global pooling --------------------
__global__ __launch_bounds__(256)
void k_gcn_pool(const int* __restrict__ rowptr, const int* __restrict__ csrc,
                const int* __restrict__ cnt, const float* __restrict__ xw,
                const float* __restrict__ bias,
                float* __restrict__ pmax, float* __restrict__ psum, int N) {
    __shared__ float smax[HD];
    __shared__ float ssum[HD];
    const int tid = threadIdx.x;
    for (int i = tid; i < HD; i += 256) { smax[i] = 0.f; ssum[i] = 0.f; }
    __syncthreads();

    const int w = (blockIdx.x * blockDim.x + tid) >> 5;
    const int lane = tid & 31;

    if (w < N) {
        const int row = rowptr[w];
        const int end = rowptr[w + 1];
        const float dn = rsqrtf((float)(end - row));

        float4 acc4[5];
#pragma unroll
        for (int j = 0; j < 5; j++) acc4[j] = make_float4(0.f, 0.f, 0.f, 0.f);

        int i = row;
        for (; i + 1 < end; i += 2) {
            int s0 = csrc[i];
            int s1 = csrc[i + 1];
            float n0 = dn * rsqrtf((float)cnt[s0]);
            float n1 = dn * rsqrtf((float)cnt[s1]);
            const float4* xs0 = (const float4*)(xw + (size_t)s0 * HD);
            const float4* xs1 = (const float4*)(xw + (size_t)s1 * HD);
            float4 v0[5], v1[5];
#pragma unroll
            for (int j = 0; j < 5; j++) { v0[j] = xs0[lane + 32 * j]; v1[j] = xs1[lane + 32 * j]; }
#pragma unroll
            for (int j = 0; j < 5; j++) {
                acc4[j].x += v0[j].x * n0 + v1[j].x * n1;
                acc4[j].y += v0[j].y * n0 + v1[j].y * n1;
                acc4[j].z += v0[j].z * n0 + v1[j].z * n1;
                acc4[j].w += v0[j].w * n0 + v1[j].w * n1;
            }
        }
        if (i < end) {
            int s = csrc[i];
            float nrm = dn * rsqrtf((float)cnt[s]);
            const float4* xs4 = (const float4*)(xw + (size_t)s * HD);
#pragma unroll
            for (int j = 0; j < 5; j++) {
                float4 v = xs4[lane + 32 * j];
                acc4[j].x += v.x * nrm;
                acc4[j].y += v.y * nrm;
                acc4[j].z += v.z * nrm;
                acc4[j].w += v.w * nrm;
            }
        }

        const float4* b4 = (const float4*)bias;
#pragma unroll
        for (int j = 0; j < 5; j++) {
            int idx = lane + 32 * j;
            float4 bb = b4[idx];
            float4 v = acc4[j];
            v.x = fmaxf(v.x + bb.x, 0.f);
            v.y = fmaxf(v.y + bb.y, 0.f);
            v.z = fmaxf(v.z + bb.z, 0.f);
            v.w = fmaxf(v.w + bb.w, 0.f);
            int col = idx * 4;
            atomicMax((int*)&smax[col + 0], __float_as_int(v.x));
            atomicMax((int*)&smax[col + 1], __float_as_int(v.y));
            atomicMax((int*)&smax[col + 2], __float_as_int(v.z));
            atomicMax((int*)&smax[col + 3], __float_as_int(v.w));
            atomicAdd(&ssum[col + 0], v.x);
            atomicAdd(&ssum[col + 1], v.y);
            atomicAdd(&ssum[col + 2], v.z);
            atomicAdd(&ssum[col + 3], v.w);
        }
    }
    __syncthreads();

    for (int i = tid; i < HD; i += 256) {
        atomicMax((int*)&pmax[i], __float_as_int(smax[i]));
        atomicAdd(&psum[i], ssum[i]);
    }
}

// ----------------------------- MLP -------------------------------------------
__global__ void k_mlp1(const float* __restrict__ pmax, const float* __restrict__ psum,
                       const float* __restrict__ W1, const float* __restrict__ b1,
                       float* __restrict__ h1, int N) {
    int j = blockIdx.x * blockDim.x + threadIdx.x;
    if (j >= H1DIM) return;
    float acc = b1[j];
    float invN = 1.0f / (float)N;
    for (int k = 0; k < HD; k++)
        acc += pmax[k] * W1[(size_t)k * H1DIM + j];
    for (int k = 0; k < HD; k++)
        acc += psum[k] * invN * W1[(size_t)(HD + k) * H1DIM + j];
    h1[j] = fmaxf(acc, 0.0f);
}

__global__ void k_mlp2(const float* __restrict__ h1, const float* __restrict__ W2,
                       const float* __restrict__ b2, float* __restrict__ out) {
    __shared__ float acc[10];
    int tid = threadIdx.x;
    if (tid < 10) acc[tid] = 0.0f;
    __syncthreads();
    float part[10];
#pragma unroll
    for (int j = 0; j < 10; j++) part[j] = 0.0f;
    for (int k = tid; k < H1DIM; k += 256) {
        float hv = h1[k];
#pragma unroll
        for (int j = 0; j < 10; j++) part[j] += hv * W2[k * 10 + j];
    }
#pragma unroll
    for (int j = 0; j < 10; j++) atomicAdd(&acc[j], part[j]);
    __syncthreads();
    if (tid < 10) out[tid] = acc[tid] + b2[tid];
}

// ----------------------------- launch -----------------------------------------
static inline int cdiv(int a, int b) { return (a + b - 1) / b; }

extern "C" void kernel_launch(void* const* d_in, const int* in_sizes, int n_in,
                              void* d_out, int out_size) {
    const float* x       = (const float*)d_in[0];
    const float* W_gat   = (const float*)d_in[1];
    const float* att_src = (const float*)d_in[2];
    const float* att_dst = (const float*)d_in[3];
    const float* b_gat   = (const float*)d_in[4];
    const float* W_gcn   = (const float*)d_in[5];
    const float* b_gcn   = (const float*)d_in[6];
    const float* W1      = (const float*)d_in[7];
    const float* b1      = (const float*)d_in[8];
    const float* W2      = (const float*)d_in[9];
    const float* b2      = (const float*)d_in[10];
    const int*   ei      = (const int*)d_in[11];

    const int N  = in_sizes[0] / D;
    const int E  = in_sizes[11] / 2;
    const int EP = E + N;
    float* out = (float*)d_out;

    float *p_xl, *p_x1, *p_xw, *p_wt, *p_asrc, *p_adst, *p_pmax, *p_psum, *p_h1;
    int *p_cnt, *p_rowptr, *p_cursor, *p_csrc;
    cudaGetSymbolAddress((void**)&p_xl,     g_xl);
    cudaGetSymbolAddress((void**)&p_x1,     g_x1);
    cudaGetSymbolAddress((void**)&p_xw,     g_xw);
    cudaGetSymbolAddress((void**)&p_wt,     g_wt);
    cudaGetSymbolAddress((void**)&p_asrc,   g_asrc);
    cudaGetSymbolAddress((void**)&p_adst,   g_adst);
    cudaGetSymbolAddress((void**)&p_pmax,   g_pmax);
    cudaGetSymbolAddress((void**)&p_psum,   g_psum);
    cudaGetSymbolAddress((void**)&p_h1,     g_h1);
    cudaGetSymbolAddress((void**)&p_cnt,    g_cnt);
    cudaGetSymbolAddress((void**)&p_rowptr, g_rowptr);
    cudaGetSymbolAddress((void**)&p_cursor, g_cursor);
    cudaGetSymbolAddress((void**)&p_csrc,   g_csrc);

    // init + CSR build + W pre-round (independent; fills pipeline)
    k_init<<<cdiv(N + 2 * HD, 256), 256>>>(p_cnt, p_pmax, p_psum, N);
    k_cvtw<<<cdiv(HD * HD, 256), 256>>>(W_gcn, p_wt, HD * HD);
    k_count<<<cdiv(EP, 256), 256>>>(ei, p_cnt, E, N);
    k_scan<<<1, 1024>>>(p_cnt, p_rowptr, p_cursor, N, EP);
    k_scatter<<<cdiv(EP, 256), 256>>>(ei, p_cursor, p_csrc, E, N);
    // GEMM1 (tf32 tensor cores) + fused attention scores
    k_gemm_tf32<true, true><<<cdiv(N, 128) * (HD / 128), 256>>>(
        x, W_gat, p_xl, N, HD, D, att_src, att_dst, p_asrc, p_adst);
    // GAT online-softmax + aggregation (emits tf32-rounded x1)
    k_gat<<<cdiv(N * 32, 256), 256>>>(p_rowptr, p_csrc, p_xl, p_asrc, p_adst,
                                      b_gat, p_x1, N);
    // GEMM2 (tf32 tensor cores, inputs pre-rounded -> no in-loop CVT)
    k_gemm_tf32<false, false><<<cdiv(N, 128) * (HD / 128), 256>>>(
        p_x1, p_wt, p_xw, N, HD, HD, nullptr, nullptr, nullptr, nullptr);
    // GCN aggregation + fused global pooling
    k_gcn_pool<<<cdiv(N * 32, 256), 256>>>(p_rowptr, p_csrc, p_cnt, p_xw, b_gcn,
                                           p_pmax, p_psum, N);
    // MLP head
    k_mlp1<<<cdiv(H1DIM, 256), 256>>>(p_pmax, p_psum, W1, b1, p_h1, N);
    k_mlp2<<<1, 256>>>(p_h1, W2, b2, out);
}

// round 9
// speedup vs baseline: 1.3987x; 1.2222x over previous
#include <cuda_runtime.h>
#include <float.h>
#include <stdint.h>

// Problem constants (fixed by the dataset)
#define MAXN 20000
#define MAXE 320000
#define MAXEP (MAXE + MAXN)
#define D  64
#define H  10
#define HD 640
#define H1DIM 1500

// ----------------------------- scratch (static, allocation-free) ------------
__device__ __align__(16) float g_xl  [(size_t)MAXN * HD];
__device__ __align__(16) float g_x1  [(size_t)MAXN * HD];
__device__ __align__(16) float g_xw  [(size_t)MAXN * HD];
__device__ __align__(16) float g_wt  [(size_t)HD * HD];    // W_gcn pre-rounded to tf32
__device__ __align__(16) float g_asrc[(size_t)MAXN * H];
__device__ __align__(16) float g_adst[(size_t)MAXN * H];
__device__ __align__(16) float g_pmax[HD];
__device__ __align__(16) float g_psum[HD];
__device__ __align__(16) float g_h1  [H1DIM];
__device__ __align__(16) int g_cnt   [MAXN];
__device__ __align__(16) int g_rowptr[MAXN + 1];
__device__ __align__(16) int g_cursor[MAXN];
__device__ __align__(16) int g_csrc  [MAXEP];

__device__ __forceinline__ uint32_t f2tf32(float x) {
    uint32_t r;
    asm("cvt.rna.tf32.f32 %0, %1;" : "=r"(r) : "f"(x));
    return r;
}
__device__ __forceinline__ float rnd_tf32(float x) {
    return __uint_as_float(f2tf32(x));
}

// ----------------------------- setup (init + W preround, one launch) ---------
__global__ void k_setup(int* __restrict__ cnt, float* __restrict__ pmax,
                        float* __restrict__ psum, float* __restrict__ h1,
                        const float* __restrict__ b1,
                        const float* __restrict__ w, float* __restrict__ wt, int N) {
    int i = blockIdx.x * blockDim.x + threadIdx.x;
    if (i < N) { cnt[i] = 0; return; }
    i -= N;
    if (i < HD) { pmax[i] = 0.f; return; }
    i -= HD;
    if (i < HD) { psum[i] = 0.f; return; }
    i -= HD;
    if (i < H1DIM) { h1[i] = b1[i]; return; }
    i -= H1DIM;
    if (i < HD * HD) wt[i] = rnd_tf32(w[i]);
}

// ----------------------------- CSR build -------------------------------------
__global__ void k_count(const int* __restrict__ ei, int* __restrict__ cnt, int E, int N) {
    int e = blockIdx.x * blockDim.x + threadIdx.x;
    int EP = E + N;
    if (e >= EP) return;
    int dst = (e < E) ? ei[E + e] : (e - E);
    atomicAdd(&cnt[dst], 1);
}

__global__ __launch_bounds__(1024)
void k_scan(const int* __restrict__ cnt, int* __restrict__ rowptr,
            int* __restrict__ cursor, int N, int EP) {
    __shared__ int sums[1024];
    const int t = threadIdx.x;
    const int per = (N + 1023) >> 10;                 // <= 20 for MAXN
    const int start = t * per;
    int vals[20];
    int cn = 0;
    const bool vec = (per % 4 == 0) && (start + per <= N);
    if (vec) {
#pragma unroll
        for (int q = 0; q < 5; q++) {
            if (q * 4 < per) {
                int4 v = *(const int4*)&cnt[start + q * 4];
                vals[q * 4 + 0] = v.x; vals[q * 4 + 1] = v.y;
                vals[q * 4 + 2] = v.z; vals[q * 4 + 3] = v.w;
            }
        }
        cn = per;
    } else if (start < N) {
        cn = min(per, N - start);
        for (int q = 0; q < cn; q++) vals[q] = cnt[start + q];
    }
    int s = 0;
    for (int q = 0; q < cn; q++) s += vals[q];
    sums[t] = s;
    __syncthreads();
    for (int off = 1; off < 1024; off <<= 1) {
        int o = (t >= off) ? sums[t - off] : 0;
        __syncthreads();
        sums[t] += o;
        __syncthreads();
    }
    int run = sums[t] - s;                            // exclusive prefix
    for (int q = 0; q < cn; q++) {                    // vals becomes offsets
        int tmp = vals[q];
        vals[q] = run;
        run += tmp;
    }
    if (vec) {
#pragma unroll
        for (int q = 0; q < 5; q++) {
            if (q * 4 < per) {
                int4 v = make_int4(vals[q * 4 + 0], vals[q * 4 + 1],
                                   vals[q * 4 + 2], vals[q * 4 + 3]);
                *(int4*)&rowptr[start + q * 4] = v;
                *(int4*)&cursor[start + q * 4] = v;
            }
        }
    } else {
        for (int q = 0; q < cn; q++) {
            rowptr[start + q] = vals[q];
            cursor[start + q] = vals[q];
        }
    }
    if (t == 0) rowptr[N] = EP;
}

__global__ void k_scatter(const int* __restrict__ ei, int* __restrict__ cursor,
                          int* __restrict__ csrc, int E, int N) {
    int e = blockIdx.x * blockDim.x + threadIdx.x;
    int EP = E + N;
    if (e >= EP) return;
    int src, dst;
    if (e < E) { src = ei[e]; dst = ei[E + e]; }
    else       { src = dst = e - E; }
    int pos = atomicAdd(&cursor[dst], 1);
    csrc[pos] = src;
}

// ----------------------------- tf32 tensor-core GEMM --------------------------
// Block 128x128x16, 8 warps (256 threads), warp tile 32x64, double-buffered.
#define GAPAD 20
#define GBPAD 136
template <bool ATT, bool CVT>
__global__ __launch_bounds__(256)
void k_gemm_tf32(const float* __restrict__ A, const float* __restrict__ B,
                 float* __restrict__ C, int M, int Nn, int K,
                 const float* __restrict__ att_src, const float* __restrict__ att_dst,
                 float* __restrict__ asrc, float* __restrict__ adst) {
    __shared__ float As[2][128][GAPAD];
    __shared__ float Bs[2][16][GBPAD];
    const int tid = threadIdx.x;
    const int warp = tid >> 5, lane = tid & 31;
    const int wm = warp & 3, wn = warp >> 2;        // 4 x 2 warp grid
    const int nTilesX = Nn / 128;
    const int bx = blockIdx.x % nTilesX;
    const int by = blockIdx.x / nTilesX;
    const int rowBase = by * 128, colBase = bx * 128;

    const int gID = lane >> 2;
    const int tIG = lane & 3;

    float acc[2][8][4];
#pragma unroll
    for (int mt = 0; mt < 2; mt++)
#pragma unroll
        for (int nt = 0; nt < 8; nt++)
#pragma unroll
            for (int r = 0; r < 4; r++) acc[mt][nt][r] = 0.0f;

    const int aR  = tid >> 2;
    const int aC4 = (tid & 3) * 4;
    const int bR  = tid >> 5;
    const int bC4 = lane * 4;

    float4 avr[2], bvr[2];
#pragma unroll
    for (int half = 0; half < 2; half++) {
        int gr = rowBase + aR + half * 64;
        avr[half] = (gr < M) ? *(const float4*)&A[(size_t)gr * K + aC4]
                             : make_float4(0.f, 0.f, 0.f, 0.f);
        bvr[half] = *(const float4*)&B[(size_t)(bR + half * 8) * Nn + colBase + bC4];
    }

    int buf = 0;
    for (int k0 = 0; k0 < K; k0 += 16) {
#pragma unroll
        for (int half = 0; half < 2; half++) {
            int r = aR + half * 64;
            As[buf][r][aC4 + 0] = CVT ? rnd_tf32(avr[half].x) : avr[half].x;
            As[buf][r][aC4 + 1] = CVT ? rnd_tf32(avr[half].y) : avr[half].y;
            As[buf][r][aC4 + 2] = CVT ? rnd_tf32(avr[half].z) : avr[half].z;
            As[buf][r][aC4 + 3] = CVT ? rnd_tf32(avr[half].w) : avr[half].w;
            int rb = bR + half * 8;
            Bs[buf][rb][bC4 + 0] = CVT ? rnd_tf32(bvr[half].x) : bvr[half].x;
            Bs[buf][rb][bC4 + 1] = CVT ? rnd_tf32(bvr[half].y) : bvr[half].y;
            Bs[buf][rb][bC4 + 2] = CVT ? rnd_tf32(bvr[half].z) : bvr[half].z;
            Bs[buf][rb][bC4 + 3] = CVT ? rnd_tf32(bvr[half].w) : bvr[half].w;
        }
        __syncthreads();

        if (k0 + 16 < K) {
#pragma unroll
            for (int half = 0; half < 2; half++) {
                int gr = rowBase + aR + half * 64;
                avr[half] = (gr < M) ? *(const float4*)&A[(size_t)gr * K + k0 + 16 + aC4]
                                     : make_float4(0.f, 0.f, 0.f, 0.f);
                bvr[half] = *(const float4*)&B[(size_t)(k0 + 16 + bR + half * 8) * Nn + colBase + bC4];
            }
        }

#pragma unroll
        for (int ks = 0; ks < 16; ks += 8) {
            uint32_t af[2][4];
#pragma unroll
            for (int mt = 0; mt < 2; mt++) {
                int r0 = wm * 32 + mt * 16 + gID;
                int kc = ks + tIG;
                af[mt][0] = __float_as_uint(As[buf][r0][kc]);
                af[mt][1] = __float_as_uint(As[buf][r0 + 8][kc]);
                af[mt][2] = __float_as_uint(As[buf][r0][kc + 4]);
                af[mt][3] = __float_as_uint(As[buf][r0 + 8][kc + 4]);
            }
#pragma unroll
            for (int nt = 0; nt < 8; nt++) {
                int col = wn * 64 + nt * 8 + gID;
                uint32_t b0 = __float_as_uint(Bs[buf][ks + tIG][col]);
                uint32_t b1 = __float_as_uint(Bs[buf][ks + tIG + 4][col]);
#pragma unroll
                for (int mt = 0; mt < 2; mt++) {
                    asm volatile(
                        "mma.sync.aligned.m16n8k8.row.col.f32.tf32.tf32.f32 "
                        "{%0,%1,%2,%3}, {%4,%5,%6,%7}, {%8,%9}, {%0,%1,%2,%3};\n"
                        : "+f"(acc[mt][nt][0]), "+f"(acc[mt][nt][1]),
                          "+f"(acc[mt][nt][2]), "+f"(acc[mt][nt][3])
                        : "r"(af[mt][0]), "r"(af[mt][1]), "r"(af[mt][2]), "r"(af[mt][3]),
                          "r"(b0), "r"(b1));
                }
            }
        }
        buf ^= 1;
    }

#pragma unroll
    for (int mt = 0; mt < 2; mt++) {
        int r0 = rowBase + wm * 32 + mt * 16 + gID;
#pragma unroll
        for (int nt = 0; nt < 8; nt++) {
            int c0 = colBase + wn * 64 + nt * 8 + tIG * 2;
            if (r0 < M)
                *(float2*)&C[(size_t)r0 * Nn + c0] = make_float2(acc[mt][nt][0], acc[mt][nt][1]);
            if (r0 + 8 < M)
                *(float2*)&C[(size_t)(r0 + 8) * Nn + c0] = make_float2(acc[mt][nt][2], acc[mt][nt][3]);
        }
    }

    if (ATT) {
        const int h = bx * 2 + wn;
        float as[16], ad[16];
#pragma unroll
        for (int nt = 0; nt < 8; nt++)
#pragma unroll
            for (int p = 0; p < 2; p++) {
                int cih = nt * 8 + tIG * 2 + p;
                as[nt * 2 + p] = att_src[h * D + cih];
                ad[nt * 2 + p] = att_dst[h * D + cih];
            }
#pragma unroll
        for (int mt = 0; mt < 2; mt++) {
#pragma unroll
            for (int pair = 0; pair < 2; pair++) {
                float ps = 0.f, pd = 0.f;
#pragma unroll
                for (int nt = 0; nt < 8; nt++)
#pragma unroll
                    for (int p = 0; p < 2; p++) {
                        float v = acc[mt][nt][pair * 2 + p];
                        ps += v * as[nt * 2 + p];
                        pd += v * ad[nt * 2 + p];
                    }
                ps += __shfl_down_sync(0xffffffffu, ps, 2, 4);
                ps += __shfl_down_sync(0xffffffffu, ps, 1, 4);
                pd += __shfl_down_sync(0xffffffffu, pd, 2, 4);
                pd += __shfl_down_sync(0xffffffffu, pd, 1, 4);
                int gr = rowBase + wm * 32 + mt * 16 + gID + pair * 8;
                if (tIG == 0 && gr < M) {
                    asrc[gr * H + h] = ps;
                    adst[gr * H + h] = pd;
                }
            }
        }
    }
}

// ----------------------------- GAT: one warp per node ------------------------
__global__ __launch_bounds__(256)
void k_gat(const int* __restrict__ rowptr, const int* __restrict__ csrc,
           const float* __restrict__ xl,
           const float* __restrict__ asrc, const float* __restrict__ adst,
           const float* __restrict__ bias, float* __restrict__ x1, int N) {
    int w = (blockIdx.x * blockDim.x + threadIdx.x) >> 5;
    int lane = threadIdx.x & 31;
    if (w >= N) return;
    const int row = rowptr[w];
    const int end = rowptr[w + 1];

    const int h = lane % H;
    const int c = lane / H;
    const float adst_h = (lane < 30) ? adst[w * H + h] : 0.f;

    float m = -FLT_MAX, den = 0.f;
    if (lane < 30) {
        for (int i = row + c; i < end; i += 3) {
            int s = csrc[i];
            float a = asrc[s * H + h] + adst_h;
            a = a > 0.f ? a : 0.2f * a;
            float nm = fmaxf(m, a);
            den = den * __expf(m - nm) + __expf(a - nm);
            m = nm;
        }
    }
    {
        float mA = __shfl_sync(0xffffffffu, m,   lane + 10);
        float dA = __shfl_sync(0xffffffffu, den, lane + 10);
        float mB = __shfl_sync(0xffffffffu, m,   lane + 20);
        float dB = __shfl_sync(0xffffffffu, den, lane + 20);
        float M2 = fmaxf(m, fmaxf(mA, mB));
        den = den * __expf(m - M2) + dA * __expf(mA - M2) + dB * __expf(mB - M2);
        m = M2;
    }
    const float invden = 1.0f / (den + 1e-16f);

    float4 acc4[5];
#pragma unroll
    for (int j = 0; j < 5; j++) acc4[j] = make_float4(0.f, 0.f, 0.f, 0.f);

    const int hsel = lane >> 4;
    int i = row;
    for (; i + 1 < end; i += 2) {
        int s0 = csrc[i];
        int s1 = csrc[i + 1];
        float wv0 = 0.f, wv1 = 0.f;
        if (lane < H) {
            float a0 = asrc[s0 * H + lane] + adst_h;
            float a1 = asrc[s1 * H + lane] + adst_h;
            a0 = a0 > 0.f ? a0 : 0.2f * a0;
            a1 = a1 > 0.f ? a1 : 0.2f * a1;
            wv0 = __expf(a0 - m) * invden;
            wv1 = __expf(a1 - m) * invden;
        }
        const float4* xs0 = (const float4*)(xl + (size_t)s0 * HD);
        const float4* xs1 = (const float4*)(xl + (size_t)s1 * HD);
        float4 v0[5], v1[5];
#pragma unroll
        for (int j = 0; j < 5; j++) { v0[j] = xs0[lane + 32 * j]; v1[j] = xs1[lane + 32 * j]; }
#pragma unroll
        for (int j = 0; j < 5; j++) {
            float w0 = __shfl_sync(0xffffffffu, wv0, 2 * j + hsel);
            float w1 = __shfl_sync(0xffffffffu, wv1, 2 * j + hsel);
            acc4[j].x += v0[j].x * w0 + v1[j].x * w1;
            acc4[j].y += v0[j].y * w0 + v1[j].y * w1;
            acc4[j].z += v0[j].z * w0 + v1[j].z * w1;
            acc4[j].w += v0[j].w * w0 + v1[j].w * w1;
        }
    }
    if (i < end) {
        int s = csrc[i];
        float wv = 0.f;
        if (lane < H) {
            float a = asrc[s * H + lane] + adst_h;
            a = a > 0.f ? a : 0.2f * a;
            wv = __expf(a - m) * invden;
        }
        const float4* xs4 = (const float4*)(xl + (size_t)s * HD);
#pragma unroll
        for (int j = 0; j < 5; j++) {
            float wj = __shfl_sync(0xffffffffu, wv, 2 * j + hsel);
            float4 v = xs4[lane + 32 * j];
            acc4[j].x += v.x * wj;
            acc4[j].y += v.y * wj;
            acc4[j].z += v.z * wj;
            acc4[j].w += v.w * wj;
        }
    }

    float4* xo4 = (float4*)(x1 + (size_t)w * HD);
    const float4* b4 = (const float4*)bias;
#pragma unroll
    for (int j = 0; j < 5; j++) {
        int idx = lane + 32 * j;
        float4 bb = b4[idx];
        float4 v = acc4[j];
        v.x = rnd_tf32(fmaxf(v.x + bb.x, 0.f));
        v.y = rnd_tf32(fmaxf(v.y + bb.y, 0.f));
        v.z = rnd_tf32(fmaxf(v.z + bb.z, 0.f));
        v.w = rnd_tf32(fmaxf(v.w + bb.w, 0.f));
        xo4[idx] = v;
    }
}

// ----------------------------- GCN + fused global pooling --------------------
__global__ __launch_bounds__(256)
void k_gcn_pool(const int* __restrict__ rowptr, const int* __restrict__ csrc,
                const int* __restrict__ cnt, const float* __restrict__ xw,
                const float* __restrict__ bias,
                float* __restrict__ pmax, float* __restrict__ psum, int N) {
    __shared__ float smax[HD];
    __shared__ float ssum[HD];
    const int tid = threadIdx.x;
    for (int i = tid; i < HD; i += 256) { smax[i] = 0.f; ssum[i] = 0.f; }
    __syncthreads();

    const int w = (blockIdx.x * blockDim.x + tid) >> 5;
    const int lane = tid & 31;

    if (w < N) {
        const int row = rowptr[w];
        const int end = rowptr[w + 1];
        const float dn = rsqrtf((float)(end - row));

        float4 acc4[5];
#pragma unroll
        for (int j = 0; j < 5; j++) acc4[j] = make_float4(0.f, 0.f, 0.f, 0.f);

        int i = row;
        for (; i + 1 < end; i += 2) {
            int s0 = csrc[i];
            int s1 = csrc[i + 1];
            float n0 = dn * rsqrtf((float)cnt[s0]);
            float n1 = dn * rsqrtf((float)cnt[s1]);
            const float4* xs0 = (const float4*)(xw + (size_t)s0 * HD);
            const float4* xs1 = (const float4*)(xw + (size_t)s1 * HD);
            float4 v0[5], v1[5];
#pragma unroll
            for (int j = 0; j < 5; j++) { v0[j] = xs0[lane + 32 * j]; v1[j] = xs1[lane + 32 * j]; }
#pragma unroll
            for (int j = 0; j < 5; j++) {
                acc4[j].x += v0[j].x * n0 + v1[j].x * n1;
                acc4[j].y += v0[j].y * n0 + v1[j].y * n1;
                acc4[j].z += v0[j].z * n0 + v1[j].z * n1;
                acc4[j].w += v0[j].w * n0 + v1[j].w * n1;
            }
        }
        if (i < end) {
            int s = csrc[i];
            float nrm = dn * rsqrtf((float)cnt[s]);
            const float4* xs4 = (const float4*)(xw + (size_t)s * HD);
#pragma unroll
            for (int j = 0; j < 5; j++) {
                float4 v = xs4[lane + 32 * j];
                acc4[j].x += v.x * nrm;
                acc4[j].y += v.y * nrm;
                acc4[j].z += v.z * nrm;
                acc4[j].w += v.w * nrm;
            }
        }

        const float4* b4 = (const float4*)bias;
#pragma unroll
        for (int j = 0; j < 5; j++) {
            int idx = lane + 32 * j;
            float4 bb = b4[idx];
            float4 v = acc4[j];
            v.x = fmaxf(v.x + bb.x, 0.f);
            v.y = fmaxf(v.y + bb.y, 0.f);
            v.z = fmaxf(v.z + bb.z, 0.f);
            v.w = fmaxf(v.w + bb.w, 0.f);
            int col = idx * 4;
            atomicMax((int*)&smax[col + 0], __float_as_int(v.x));
            atomicMax((int*)&smax[col + 1], __float_as_int(v.y));
            atomicMax((int*)&smax[col + 2], __float_as_int(v.z));
            atomicMax((int*)&smax[col + 3], __float_as_int(v.w));
            atomicAdd(&ssum[col + 0], v.x);
            atomicAdd(&ssum[col + 1], v.y);
            atomicAdd(&ssum[col + 2], v.z);
            atomicAdd(&ssum[col + 3], v.w);
        }
    }
    __syncthreads();

    for (int i = tid; i < HD; i += 256) {
        atomicMax((int*)&pmax[i], __float_as_int(smax[i]));
        atomicAdd(&psum[i], ssum[i]);
    }
}

// ----------------------------- MLP (k-split parallel) ------------------------
#define MLP_KSPLIT 10
#define MLP_JBLK   6
__global__ void k_mlp1(const float* __restrict__ pmax, const float* __restrict__ psum,
                       const float* __restrict__ W1, float* __restrict__ h1, int N) {
    const int jb = blockIdx.x % MLP_JBLK;
    const int s  = blockIdx.x / MLP_JBLK;
    const int j = jb * 256 + threadIdx.x;
    if (j >= H1DIM) return;
    const float invN = 1.0f / (float)N;
    const int k0 = s * (2 * HD / MLP_KSPLIT);   // 128 k per split
    float acc = 0.f;
#pragma unroll 4
    for (int k = k0; k < k0 + 2 * HD / MLP_KSPLIT; k++) {
        float v = (k < HD) ? pmax[k] : psum[k - HD] * invN;
        acc += v * W1[(size_t)k * H1DIM + j];
    }
    atomicAdd(&h1[j], acc);     // h1 pre-initialized to b1 in k_setup
}

__global__ void k_mlp2(const float* __restrict__ h1, const float* __restrict__ W2,
                       const float* __restrict__ b2, float* __restrict__ out) {
    __shared__ float acc[10];
    int tid = threadIdx.x;
    if (tid < 10) acc[tid] = 0.0f;
    __syncthreads();
    float part[10];
#pragma unroll
    for (int j = 0; j < 10; j++) part[j] = 0.0f;
    for (int k = tid; k < H1DIM; k += 256) {
        float hv = fmaxf(h1[k], 0.0f);          // relu folded here
#pragma unroll
        for (int j = 0; j < 10; j++) part[j] += hv * W2[k * 10 + j];
    }
#pragma unroll
    for (int j = 0; j < 10; j++) atomicAdd(&acc[j], part[j]);
    __syncthreads();
    if (tid < 10) out[tid] = acc[tid] + b2[tid];
}

// ----------------------------- launch -----------------------------------------
static inline int cdiv(int a, int b) { return (a + b - 1) / b; }

extern "C" void kernel_launch(void* const* d_in, const int* in_sizes, int n_in,
                              void* d_out, int out_size) {
    const float* x       = (const float*)d_in[0];
    const float* W_gat   = (const float*)d_in[1];
    const float* att_src = (const float*)d_in[2];
    const float* att_dst = (const float*)d_in[3];
    const float* b_gat   = (const float*)d_in[4];
    const float* W_gcn   = (const float*)d_in[5];
    const float* b_gcn   = (const float*)d_in[6];
    const float* W1      = (const float*)d_in[7];
    const float* b1      = (const float*)d_in[8];
    const float* W2      = (const float*)d_in[9];
    const float* b2      = (const float*)d_in[10];
    const int*   ei      = (const int*)d_in[11];

    const int N  = in_sizes[0] / D;
    const int E  = in_sizes[11] / 2;
    const int EP = E + N;
    float* out = (float*)d_out;

    float *p_xl, *p_x1, *p_xw, *p_wt, *p_asrc, *p_adst, *p_pmax, *p_psum, *p_h1;
    int *p_cnt, *p_rowptr, *p_cursor, *p_csrc;
    cudaGetSymbolAddress((void**)&p_xl,     g_xl);
    cudaGetSymbolAddress((void**)&p_x1,     g_x1);
    cudaGetSymbolAddress((void**)&p_xw,     g_xw);
    cudaGetSymbolAddress((void**)&p_wt,     g_wt);
    cudaGetSymbolAddress((void**)&p_asrc,   g_asrc);
    cudaGetSymbolAddress((void**)&p_adst,   g_adst);
    cudaGetSymbolAddress((void**)&p_pmax,   g_pmax);
    cudaGetSymbolAddress((void**)&p_psum,   g_psum);
    cudaGetSymbolAddress((void**)&p_h1,     g_h1);
    cudaGetSymbolAddress((void**)&p_cnt,    g_cnt);
    cudaGetSymbolAddress((void**)&p_rowptr, g_rowptr);
    cudaGetSymbolAddress((void**)&p_cursor, g_cursor);
    cudaGetSymbolAddress((void**)&p_csrc,   g_csrc);

    // setup (cnt/pool/h1 init + W_gcn tf32 preround) + CSR build
    const int setupN = N + 2 * HD + H1DIM + HD * HD;
    k_setup<<<cdiv(setupN, 256), 256>>>(p_cnt, p_pmax, p_psum, p_h1, b1, W_gcn, p_wt, N);
    k_count<<<cdiv(EP, 256), 256>>>(ei, p_cnt, E, N);
    k_scan<<<1, 1024>>>(p_cnt, p_rowptr, p_cursor, N, EP);
    k_scatter<<<cdiv(EP, 256), 256>>>(ei, p_cursor, p_csrc, E, N);
    // GEMM1 (tf32) + fused attention scores
    k_gemm_tf32<true, true><<<cdiv(N, 128) * (HD / 128), 256>>>(
        x, W_gat, p_xl, N, HD, D, att_src, att_dst, p_asrc, p_adst);
    // GAT online-softmax + aggregation (emits tf32-rounded x1)
    k_gat<<<cdiv(N * 32, 256), 256>>>(p_rowptr, p_csrc, p_xl, p_asrc, p_adst,
                                      b_gat, p_x1, N);
    // GEMM2 (tf32, inputs pre-rounded)
    k_gemm_tf32<false, false><<<cdiv(N, 128) * (HD / 128), 256>>>(
        p_x1, p_wt, p_xw, N, HD, HD, nullptr, nullptr, nullptr, nullptr);
    // GCN aggregation + fused global pooling
    k_gcn_pool<<<cdiv(N * 32, 256), 256>>>(p_rowptr, p_csrc, p_cnt, p_xw, b_gcn,
                                           p_pmax, p_psum, N);
    // MLP head
    k_mlp1<<<MLP_JBLK * MLP_KSPLIT, 256>>>(p_pmax, p_psum, W1, p_h1, N);
    k_mlp2<<<1, 256>>>(p_h1, W2, b2, out);
}

// round 11
// speedup vs baseline: 1.4227x; 1.0171x over previous
#include <cuda_runtime.h>
#include <float.h>
#include <stdint.h>

// Problem constants (fixed by the dataset)
#define MAXN 20000
#define MAXE 320000
#define MAXEP (MAXE + MAXN)
#define D  64
#define H  10
#define HD 640
#define H1DIM 1500

// ----------------------------- scratch (static, allocation-free) ------------
__device__ __align__(16) float g_xl  [(size_t)MAXN * HD];
__device__ __align__(16) float g_x1  [(size_t)MAXN * HD];
__device__ __align__(16) float g_xw  [(size_t)MAXN * HD];
__device__ __align__(16) float g_wt  [(size_t)HD * HD];    // W_gcn pre-rounded to tf32
__device__ __align__(16) float g_asrc[(size_t)MAXN * H];
__device__ __align__(16) float g_adst[(size_t)MAXN * H];
__device__ __align__(16) float g_pmax[HD];
__device__ __align__(16) float g_psum[HD];
__device__ __align__(16) float g_h1  [H1DIM];
__device__ __align__(16) int g_cnt   [MAXN];
__device__ __align__(16) int g_rowptr[MAXN + 1];
__device__ __align__(16) int g_cursor[MAXN];
__device__ __align__(16) int g_csrc  [MAXEP];

__device__ __forceinline__ uint32_t f2tf32(float x) {
    uint32_t r;
    asm("cvt.rna.tf32.f32 %0, %1;" : "=r"(r) : "f"(x));
    return r;
}
__device__ __forceinline__ float rnd_tf32(float x) {
    return __uint_as_float(f2tf32(x));
}
__device__ __forceinline__ uint32_t smem_u32(const void* p) {
    uint32_t a;
    asm("{ .reg .u64 t; cvta.to.shared.u64 t, %1; cvt.u32.u64 %0, t; }" : "=r"(a) : "l"(p));
    return a;
}
#define CP_ASYNC16(dst, src, sz) \
    asm volatile("cp.async.cg.shared.global [%0], [%1], 16, %2;" \
                 :: "r"(dst), "l"(src), "r"(sz) : "memory")
#define CP_COMMIT() asm volatile("cp.async.commit_group;" ::: "memory")
#define CP_WAIT(n)  asm volatile("cp.async.wait_group %0;" :: "n"(n) : "memory")

// ----------------------------- setup (init + W preround, one launch) ---------
__global__ void k_setup(int* __restrict__ cnt, float* __restrict__ pmax,
                        float* __restrict__ psum, float* __restrict__ h1,
                        const float* __restrict__ b1,
                        const float* __restrict__ w, float* __restrict__ wt, int N) {
    int i = blockIdx.x * blockDim.x + threadIdx.x;
    if (i < N) { cnt[i] = 0; return; }
    i -= N;
    if (i < HD) { pmax[i] = 0.f; return; }
    i -= HD;
    if (i < HD) { psum[i] = 0.f; return; }
    i -= HD;
    if (i < H1DIM) { h1[i] = b1[i]; return; }
    i -= H1DIM;
    if (i < HD * HD) wt[i] = rnd_tf32(w[i]);
}

// ----------------------------- CSR build -------------------------------------
__global__ void k_count(const int* __restrict__ ei, int* __restrict__ cnt, int E, int N) {
    int e = blockIdx.x * blockDim.x + threadIdx.x;
    int EP = E + N;
    if (e >= EP) return;
    int dst = (e < E) ? ei[E + e] : (e - E);
    atomicAdd(&cnt[dst], 1);
}

__global__ __launch_bounds__(1024)
void k_scan(const int* __restrict__ cnt, int* __restrict__ rowptr,
            int* __restrict__ cursor, int N, int EP) {
    __shared__ int sums[1024];
    const int t = threadIdx.x;
    const int per = (N + 1023) >> 10;
    const int start = t * per;
    int vals[20];
    int cn = 0;
    const bool vec = (per % 4 == 0) && (start + per <= N);
    if (vec) {
#pragma unroll
        for (int q = 0; q < 5; q++) {
            if (q * 4 < per) {
                int4 v = *(const int4*)&cnt[start + q * 4];
                vals[q * 4 + 0] = v.x; vals[q * 4 + 1] = v.y;
                vals[q * 4 + 2] = v.z; vals[q * 4 + 3] = v.w;
            }
        }
        cn = per;
    } else if (start < N) {
        cn = min(per, N - start);
        for (int q = 0; q < cn; q++) vals[q] = cnt[start + q];
    }
    int s = 0;
    for (int q = 0; q < cn; q++) s += vals[q];
    sums[t] = s;
    __syncthreads();
    for (int off = 1; off < 1024; off <<= 1) {
        int o = (t >= off) ? sums[t - off] : 0;
        __syncthreads();
        sums[t] += o;
        __syncthreads();
    }
    int run = sums[t] - s;
    for (int q = 0; q < cn; q++) {
        int tmp = vals[q];
        vals[q] = run;
        run += tmp;
    }
    if (vec) {
#pragma unroll
        for (int q = 0; q < 5; q++) {
            if (q * 4 < per) {
                int4 v = make_int4(vals[q * 4 + 0], vals[q * 4 + 1],
                                   vals[q * 4 + 2], vals[q * 4 + 3]);
                *(int4*)&rowptr[start + q * 4] = v;
                *(int4*)&cursor[start + q * 4] = v;
            }
        }
    } else {
        for (int q = 0; q < cn; q++) {
            rowptr[start + q] = vals[q];
            cursor[start + q] = vals[q];
        }
    }
    if (t == 0) rowptr[N] = EP;
}

__global__ void k_scatter(const int* __restrict__ ei, int* __restrict__ cursor,
                          int* __restrict__ csrc, int E, int N) {
    int e = blockIdx.x * blockDim.x + threadIdx.x;
    int EP = E + N;
    if (e >= EP) return;
    int src, dst;
    if (e < E) { src = ei[e]; dst = ei[E + e]; }
    else       { src = dst = e - E; }
    int pos = atomicAdd(&cursor[dst], 1);
    csrc[pos] = src;
}

// ----------------------------- tf32 mma.sync GEMM (GEMM1 + att epilogue) -----
#define GAPAD 20
#define GBPAD 136
template <bool ATT, bool CVT>
__global__ __launch_bounds__(256)
void k_gemm_tf32(const float* __restrict__ A, const float* __restrict__ B,
                 float* __restrict__ C, int M, int Nn, int K,
                 const float* __restrict__ att_src, const float* __restrict__ att_dst,
                 float* __restrict__ asrc, float* __restrict__ adst) {
    __shared__ float As[2][128][GAPAD];
    __shared__ float Bs[2][16][GBPAD];
    const int tid = threadIdx.x;
    const int warp = tid >> 5, lane = tid & 31;
    const int wm = warp & 3, wn = warp >> 2;
    const int nTilesX = Nn / 128;
    const int bx = blockIdx.x % nTilesX;
    const int by = blockIdx.x / nTilesX;
    const int rowBase = by * 128, colBase = bx * 128;

    const int gID = lane >> 2;
    const int tIG = lane & 3;

    float acc[2][8][4];
#pragma unroll
    for (int mt = 0; mt < 2; mt++)
#pragma unroll
        for (int nt = 0; nt < 8; nt++)
#pragma unroll
            for (int r = 0; r < 4; r++) acc[mt][nt][r] = 0.0f;

    const int aR  = tid >> 2;
    const int aC4 = (tid & 3) * 4;
    const int bR  = tid >> 5;
    const int bC4 = lane * 4;

    float4 avr[2], bvr[2];
#pragma unroll
    for (int half = 0; half < 2; half++) {
        int gr = rowBase + aR + half * 64;
        avr[half] = (gr < M) ? *(const float4*)&A[(size_t)gr * K + aC4]
                             : make_float4(0.f, 0.f, 0.f, 0.f);
        bvr[half] = *(const float4*)&B[(size_t)(bR + half * 8) * Nn + colBase + bC4];
    }

    int buf = 0;
    for (int k0 = 0; k0 < K; k0 += 16) {
#pragma unroll
        for (int half = 0; half < 2; half++) {
            int r = aR + half * 64;
            As[buf][r][aC4 + 0] = CVT ? rnd_tf32(avr[half].x) : avr[half].x;
            As[buf][r][aC4 + 1] = CVT ? rnd_tf32(avr[half].y) : avr[half].y;
            As[buf][r][aC4 + 2] = CVT ? rnd_tf32(avr[half].z) : avr[half].z;
            As[buf][r][aC4 + 3] = CVT ? rnd_tf32(avr[half].w) : avr[half].w;
            int rb = bR + half * 8;
            Bs[buf][rb][bC4 + 0] = CVT ? rnd_tf32(bvr[half].x) : bvr[half].x;
            Bs[buf][rb][bC4 + 1] = CVT ? rnd_tf32(bvr[half].y) : bvr[half].y;
            Bs[buf][rb][bC4 + 2] = CVT ? rnd_tf32(bvr[half].z) : bvr[half].z;
            Bs[buf][rb][bC4 + 3] = CVT ? rnd_tf32(bvr[half].w) : bvr[half].w;
        }
        __syncthreads();

        if (k0 + 16 < K) {
#pragma unroll
            for (int half = 0; half < 2; half++) {
                int gr = rowBase + aR + half * 64;
                avr[half] = (gr < M) ? *(const float4*)&A[(size_t)gr * K + k0 + 16 + aC4]
                                     : make_float4(0.f, 0.f, 0.f, 0.f);
                bvr[half] = *(const float4*)&B[(size_t)(k0 + 16 + bR + half * 8) * Nn + colBase + bC4];
            }
        }

#pragma unroll
        for (int ks = 0; ks < 16; ks += 8) {
            uint32_t af[2][4];
#pragma unroll
            for (int mt = 0; mt < 2; mt++) {
                int r0 = wm * 32 + mt * 16 + gID;
                int kc = ks + tIG;
                af[mt][0] = __float_as_uint(As[buf][r0][kc]);
                af[mt][1] = __float_as_uint(As[buf][r0 + 8][kc]);
                af[mt][2] = __float_as_uint(As[buf][r0][kc + 4]);
                af[mt][3] = __float_as_uint(As[buf][r0 + 8][kc + 4]);
            }
#pragma unroll
            for (int nt = 0; nt < 8; nt++) {
                int col = wn * 64 + nt * 8 + gID;
                uint32_t b0 = __float_as_uint(Bs[buf][ks + tIG][col]);
                uint32_t b1 = __float_as_uint(Bs[buf][ks + tIG + 4][col]);
#pragma unroll
                for (int mt = 0; mt < 2; mt++) {
                    asm volatile(
                        "mma.sync.aligned.m16n8k8.row.col.f32.tf32.tf32.f32 "
                        "{%0,%1,%2,%3}, {%4,%5,%6,%7}, {%8,%9}, {%0,%1,%2,%3};\n"
                        : "+f"(acc[mt][nt][0]), "+f"(acc[mt][nt][1]),
                          "+f"(acc[mt][nt][2]), "+f"(acc[mt][nt][3])
                        : "r"(af[mt][0]), "r"(af[mt][1]), "r"(af[mt][2]), "r"(af[mt][3]),
                          "r"(b0), "r"(b1));
                }
            }
        }
        buf ^= 1;
    }

#pragma unroll
    for (int mt = 0; mt < 2; mt++) {
        int r0 = rowBase + wm * 32 + mt * 16 + gID;
#pragma unroll
        for (int nt = 0; nt < 8; nt++) {
            int c0 = colBase + wn * 64 + nt * 8 + tIG * 2;
            if (r0 < M)
                *(float2*)&C[(size_t)r0 * Nn + c0] = make_float2(acc[mt][nt][0], acc[mt][nt][1]);
            if (r0 + 8 < M)
                *(float2*)&C[(size_t)(r0 + 8) * Nn + c0] = make_float2(acc[mt][nt][2], acc[mt][nt][3]);
        }
    }

    if (ATT) {
        const int h = bx * 2 + wn;
        float as[16], ad[16];
#pragma unroll
        for (int nt = 0; nt < 8; nt++)
#pragma unroll
            for (int p = 0; p < 2; p++) {
                int cih = nt * 8 + tIG * 2 + p;
                as[nt * 2 + p] = att_src[h * D + cih];
                ad[nt * 2 + p] = att_dst[h * D + cih];
            }
#pragma unroll
        for (int mt = 0; mt < 2; mt++) {
#pragma unroll
            for (int pair = 0; pair < 2; pair++) {
                float ps = 0.f, pd = 0.f;
#pragma unroll
                for (int nt = 0; nt < 8; nt++)
#pragma unroll
                    for (int p = 0; p < 2; p++) {
                        float v = acc[mt][nt][pair * 2 + p];
                        ps += v * as[nt * 2 + p];
                        pd += v * ad[nt * 2 + p];
                    }
                ps += __shfl_down_sync(0xffffffffu, ps, 2, 4);
                ps += __shfl_down_sync(0xffffffffu, ps, 1, 4);
                pd += __shfl_down_sync(0xffffffffu, pd, 2, 4);
                pd += __shfl_down_sync(0xffffffffu, pd, 1, 4);
                int gr = rowBase + wm * 32 + mt * 16 + gID + pair * 8;
                if (tIG == 0 && gr < M) {
                    asrc[gr * H + h] = ps;
                    adst[gr * H + h] = pd;
                }
            }
        }
    }
}

// ----------------------------- GEMM2: mma.sync tf32 + cp.async staging -------
// Inputs pre-rounded to tf32; staging is a pure 16B async copy.
__global__ __launch_bounds__(256)
void k_gemm2_cp(const float* __restrict__ A, const float* __restrict__ B,
                float* __restrict__ C, int M, int Nn, int K) {
    __shared__ __align__(16) float As[2][128][GAPAD];
    __shared__ __align__(16) float Bs[2][16][GBPAD];
    const int tid = threadIdx.x;
    const int warp = tid >> 5, lane = tid & 31;
    const int wm = warp & 3, wn = warp >> 2;
    const int nTilesX = Nn / 128;
    const int bx = blockIdx.x % nTilesX;
    const int by = blockIdx.x / nTilesX;
    const int rowBase = by * 128, colBase = bx * 128;

    const int gID = lane >> 2;
    const int tIG = lane & 3;

    float acc[2][8][4];
#pragma unroll
    for (int mt = 0; mt < 2; mt++)
#pragma unroll
        for (int nt = 0; nt < 8; nt++)
#pragma unroll
            for (int r = 0; r < 4; r++) acc[mt][nt][r] = 0.0f;

    const int aR  = tid >> 2;
    const int aC4 = (tid & 3) * 4;
    const int bR  = tid >> 5;
    const int bC4 = lane * 4;

    auto issue = [&](int b, int k0) {
#pragma unroll
        for (int half = 0; half < 2; half++) {
            int r = aR + half * 64;
            int gr = rowBase + r;
            uint32_t da = smem_u32(&As[b][r][aC4]);
            const float* sa = &A[(size_t)gr * K + k0 + aC4];
            int sz = (gr < M) ? 16 : 0;               // OOB rows zero-fill
            CP_ASYNC16(da, sa, sz);
            int rb = bR + half * 8;
            uint32_t db = smem_u32(&Bs[b][rb][bC4]);
            const float* sb = &B[(size_t)(k0 + rb) * Nn + colBase + bC4];
            CP_ASYNC16(db, sb, 16);
        }
        CP_COMMIT();
    };

    issue(0, 0);
    int buf = 0;
    for (int k0 = 0; k0 < K; k0 += 16) {
        const bool hasNext = (k0 + 16 < K);
        if (hasNext) {
            issue(buf ^ 1, k0 + 16);
            CP_WAIT(1);                               // current buffer done
        } else {
            CP_WAIT(0);
        }
        __syncthreads();

#pragma unroll
        for (int ks = 0; ks < 16; ks += 8) {
            uint32_t af[2][4];
#pragma unroll
            for (int mt = 0; mt < 2; mt++) {
                int r0 = wm * 32 + mt * 16 + gID;
                int kc = ks + tIG;
                af[mt][0] = __float_as_uint(As[buf][r0][kc]);
                af[mt][1] = __float_as_uint(As[buf][r0 + 8][kc]);
                af[mt][2] = __float_as_uint(As[buf][r0][kc + 4]);
                af[mt][3] = __float_as_uint(As[buf][r0 + 8][kc + 4]);
            }
#pragma unroll
            for (int nt = 0; nt < 8; nt++) {
                int col = wn * 64 + nt * 8 + gID;
                uint32_t b0 = __float_as_uint(Bs[buf][ks + tIG][col]);
                uint32_t b1 = __float_as_uint(Bs[buf][ks + tIG + 4][col]);
#pragma unroll
                for (int mt = 0; mt < 2; mt++) {
                    asm volatile(
                        "mma.sync.aligned.m16n8k8.row.col.f32.tf32.tf32.f32 "
                        "{%0,%1,%2,%3}, {%4,%5,%6,%7}, {%8,%9}, {%0,%1,%2,%3};\n"
                        : "+f"(acc[mt][nt][0]), "+f"(acc[mt][nt][1]),
                          "+f"(acc[mt][nt][2]), "+f"(acc[mt][nt][3])
                        : "r"(af[mt][0]), "r"(af[mt][1]), "r"(af[mt][2]), "r"(af[mt][3]),
                          "r"(b0), "r"(b1));
                }
            }
        }
        __syncthreads();          // protect buf before it is re-issued next iter
        buf ^= 1;
    }

#pragma unroll
    for (int mt = 0; mt < 2; mt++) {
        int r0 = rowBase + wm * 32 + mt * 16 + gID;
#pragma unroll
        for (int nt = 0; nt < 8; nt++) {
            int c0 = colBase + wn * 64 + nt * 8 + tIG * 2;
            if (r0 < M)
                *(float2*)&C[(size_t)r0 * Nn + c0] = make_float2(acc[mt][nt][0], acc[mt][nt][1]);
            if (r0 + 8 < M)
                *(float2*)&C[(size_t)(r0 + 8) * Nn + c0] = make_float2(acc[mt][nt][2], acc[mt][nt][3]);
        }
    }
}

// ----------------------------- GAT: one warp per node ------------------------
__global__ __launch_bounds__(256)
void k_gat(const int* __restrict__ rowptr, const int* __restrict__ csrc,
           const float* __restrict__ xl,
           const float* __restrict__ asrc, const float* __restrict__ adst,
           const float* __restrict__ bias, float* __restrict__ x1, int N) {
    int w = (blockIdx.x * blockDim.x + threadIdx.x) >> 5;
    int lane = threadIdx.x & 31;
    if (w >= N) return;
    const int row = rowptr[w];
    const int end = rowptr[w + 1];

    const int h = lane % H;
    const int c = lane / H;
    const float adst_h = (lane < 30) ? adst[w * H + h] : 0.f;

    float m = -FLT_MAX, den = 0.f;
    if (lane < 30) {
        for (int i = row + c; i < end; i += 3) {
            int s = csrc[i];
            float a = asrc[s * H + h] + adst_h;
            a = a > 0.f ? a : 0.2f * a;
            float nm = fmaxf(m, a);
            den = den * __expf(m - nm) + __expf(a - nm);
            m = nm;
        }
    }
    {
        float mA = __shfl_sync(0xffffffffu, m,   lane + 10);
        float dA = __shfl_sync(0xffffffffu, den, lane + 10);
        float mB = __shfl_sync(0xffffffffu, m,   lane + 20);
        float dB = __shfl_sync(0xffffffffu, den, lane + 20);
        float M2 = fmaxf(m, fmaxf(mA, mB));
        den = den * __expf(m - M2) + dA * __expf(mA - M2) + dB * __expf(mB - M2);
        m = M2;
    }
    const float invden = 1.0f / (den + 1e-16f);

    float4 acc4[5];
#pragma unroll
    for (int j = 0; j < 5; j++) acc4[j] = make_float4(0.f, 0.f, 0.f, 0.f);

    const int hsel = lane >> 4;
    int i = row;
    for (; i + 1 < end; i += 2) {
        int s0 = csrc[i];
        int s1 = csrc[i + 1];
        float wv0 = 0.f, wv1 = 0.f;
        if (lane < H) {
            float a0 = asrc[s0 * H + lane] + adst_h;
            float a1 = asrc[s1 * H + lane] + adst_h;
            a0 = a0 > 0.f ? a0 : 0.2f * a0;
            a1 = a1 > 0.f ? a1 : 0.2f * a1;
            wv0 = __expf(a0 - m) * invden;
            wv1 = __expf(a1 - m) * invden;
        }
        const float4* xs0 = (const float4*)(xl + (size_t)s0 * HD);
        const float4* xs1 = (const float4*)(xl + (size_t)s1 * HD);
        float4 v0[5], v1[5];
#pragma unroll
        for (int j = 0; j < 5; j++) { v0[j] = xs0[lane + 32 * j]; v1[j] = xs1[lane + 32 * j]; }
#pragma unroll
        for (int j = 0; j < 5; j++) {
            float w0 = __shfl_sync(0xffffffffu, wv0, 2 * j + hsel);
            float w1 = __shfl_sync(0xffffffffu, wv1, 2 * j + hsel);
            acc4[j].x += v0[j].x * w0 + v1[j].x * w1;
            acc4[j].y += v0[j].y * w0 + v1[j].y * w1;
            acc4[j].z += v0[j].z * w0 + v1[j].z * w1;
            acc4[j].w += v0[j].w * w0 + v1[j].w * w1;
        }
    }
    if (i < end) {
        int s = csrc[i];
        float wv = 0.f;
        if (lane < H) {
            float a = asrc[s * H + lane] + adst_h;
            a = a > 0.f ? a : 0.2f * a;
            wv = __expf(a - m) * invden;
        }
        const float4* xs4 = (const float4*)(xl + (size_t)s * HD);
#pragma unroll
        for (int j = 0; j < 5; j++) {
            float wj = __shfl_sync(0xffffffffu, wv, 2 * j + hsel);
            float4 v = xs4[lane + 32 * j];
            acc4[j].x += v.x * wj;
            acc4[j].y += v.y * wj;
            acc4[j].z += v.z * wj;
            acc4[j].w += v.w * wj;
        }
    }

    float4* xo4 = (float4*)(x1 + (size_t)w * HD);
    const float4* b4 = (const float4*)bias;
#pragma unroll
    for (int j = 0; j < 5; j++) {
        int idx = lane + 32 * j;
        float4 bb = b4[idx];
        float4 v = acc4[j];
        v.x = rnd_tf32(fmaxf(v.x + bb.x, 0.f));
        v.y = rnd_tf32(fmaxf(v.y + bb.y, 0.f));
        v.z = rnd_tf32(fmaxf(v.z + bb.z, 0.f));
        v.w = rnd_tf32(fmaxf(v.w + bb.w, 0.f));
        xo4[idx] = v;
    }
}

// ----------------------------- GCN + fused global pooling --------------------
__global__ __launch_bounds__(256)
void k_gcn_pool(const int* __restrict__ rowptr, const int* __restrict__ csrc,
                const int* __restrict__ cnt, const float* __restrict__ xw,
                const float* __restrict__ bias,
                float* __restrict__ pmax, float* __restrict__ psum, int N) {
    __shared__ float smax[HD];
    __shared__ float ssum[HD];
    const int tid = threadIdx.x;
    for (int i = tid; i < HD; i += 256) { smax[i] = 0.f; ssum[i] = 0.f; }
    __syncthreads();

    const int w = (blockIdx.x * blockDim.x + tid) >> 5;
    const int lane = tid & 31;

    if (w < N) {
        const int row = rowptr[w];
        const int end = rowptr[w + 1];
        const float dn = rsqrtf((float)(end - row));

        float4 acc4[5];
#pragma unroll
        for (int j = 0; j < 5; j++) acc4[j] = make_float4(0.f, 0.f, 0.f, 0.f);

        int i = row;
        for (; i + 1 < end; i += 2) {
            int s0 = csrc[i];
            int s1 = csrc[i + 1];
            float n0 = dn * rsqrtf((float)cnt[s0]);
            float n1 = dn * rsqrtf((float)cnt[s1]);
            const float4* xs0 = (const float4*)(xw + (size_t)s0 * HD);
            const float4* xs1 = (const float4*)(xw + (size_t)s1 * HD);
            float4 v0[5], v1[5];
#pragma unroll
            for (int j = 0; j < 5; j++) { v0[j] = xs0[lane + 32 * j]; v1[j] = xs1[lane + 32 * j]; }
#pragma unroll
            for (int j = 0; j < 5; j++) {
                acc4[j].x += v0[j].x * n0 + v1[j].x * n1;
                acc4[j].y += v0[j].y * n0 + v1[j].y * n1;
                acc4[j].z += v0[j].z * n0 + v1[j].z * n1;
                acc4[j].w += v0[j].w * n0 + v1[j].w * n1;
            }
        }
        if (i < end) {
            int s = csrc[i];
            float nrm = dn * rsqrtf((float)cnt[s]);
            const float4* xs4 = (const float4*)(xw + (size_t)s * HD);
#pragma unroll
            for (int j = 0; j < 5; j++) {
                float4 v = xs4[lane + 32 * j];
                acc4[j].x += v.x * nrm;
                acc4[j].y += v.y * nrm;
                acc4[j].z += v.z * nrm;
                acc4[j].w += v.w * nrm;
            }
        }

        const float4* b4 = (const float4*)bias;
#pragma unroll
        for (int j = 0; j < 5; j++) {
            int idx = lane + 32 * j;
            float4 bb = b4[idx];
            float4 v = acc4[j];
            v.x = fmaxf(v.x + bb.x, 0.f);
            v.y = fmaxf(v.y + bb.y, 0.f);
            v.z = fmaxf(v.z + bb.z, 0.f);
            v.w = fmaxf(v.w + bb.w, 0.f);
            int col = idx * 4;
            atomicMax((int*)&smax[col + 0], __float_as_int(v.x));
            atomicMax((int*)&smax[col + 1], __float_as_int(v.y));
            atomicMax((int*)&smax[col + 2], __float_as_int(v.z));
            atomicMax((int*)&smax[col + 3], __float_as_int(v.w));
            atomicAdd(&ssum[col + 0], v.x);
            atomicAdd(&ssum[col + 1], v.y);
            atomicAdd(&ssum[col + 2], v.z);
            atomicAdd(&ssum[col + 3], v.w);
        }
    }
    __syncthreads();

    for (int i = tid; i < HD; i += 256) {
        atomicMax((int*)&pmax[i], __float_as_int(smax[i]));
        atomicAdd(&psum[i], ssum[i]);
    }
}

// ----------------------------- MLP (k-split parallel) ------------------------
#define MLP_KSPLIT 10
#define MLP_JBLK   6
__global__ void k_mlp1(const float* __restrict__ pmax, const float* __restrict__ psum,
                       const float* __restrict__ W1, float* __restrict__ h1, int N) {
    const int jb = blockIdx.x % MLP_JBLK;
    const int s  = blockIdx.x / MLP_JBLK;
    const int j = jb * 256 + threadIdx.x;
    if (j >= H1DIM) return;
    const float invN = 1.0f / (float)N;
    const int k0 = s * (2 * HD / MLP_KSPLIT);
    float acc = 0.f;
#pragma unroll 4
    for (int k = k0; k < k0 + 2 * HD / MLP_KSPLIT; k++) {
        float v = (k < HD) ? pmax[k] : psum[k - HD] * invN;
        acc += v * W1[(size_t)k * H1DIM + j];
    }
    atomicAdd(&h1[j], acc);
}

__global__ void k_mlp2(const float* __restrict__ h1, const float* __restrict__ W2,
                       const float* __restrict__ b2, float* __restrict__ out) {
    __shared__ float acc[10];
    int tid = threadIdx.x;
    if (tid < 10) acc[tid] = 0.0f;
    __syncthreads();
    float part[10];
#pragma unroll
    for (int j = 0; j < 10; j++) part[j] = 0.0f;
    for (int k = tid; k < H1DIM; k += 256) {
        float hv = fmaxf(h1[k], 0.0f);
#pragma unroll
        for (int j = 0; j < 10; j++) part[j] += hv * W2[k * 10 + j];
    }
#pragma unroll
    for (int j = 0; j < 10; j++) atomicAdd(&acc[j], part[j]);
    __syncthreads();
    if (tid < 10) out[tid] = acc[tid] + b2[tid];
}

// ----------------------------- launch -----------------------------------------
static inline int cdiv(int a, int b) { return (a + b - 1) / b; }

extern "C" void kernel_launch(void* const* d_in, const int* in_sizes, int n_in,
                              void* d_out, int out_size) {
    const float* x       = (const float*)d_in[0];
    const float* W_gat   = (const float*)d_in[1];
    const float* att_src = (const float*)d_in[2];
    const float* att_dst = (const float*)d_in[3];
    const float* b_gat   = (const float*)d_in[4];
    const float* W_gcn   = (const float*)d_in[5];
    const float* b_gcn   = (const float*)d_in[6];
    const float* W1      = (const float*)d_in[7];
    const float* b1      = (const float*)d_in[8];
    const float* W2      = (const float*)d_in[9];
    const float* b2      = (const float*)d_in[10];
    const int*   ei      = (const int*)d_in[11];

    const int N  = in_sizes[0] / D;
    const int E  = in_sizes[11] / 2;
    const int EP = E + N;
    float* out = (float*)d_out;

    float *p_xl, *p_x1, *p_xw, *p_wt, *p_asrc, *p_adst, *p_pmax, *p_psum, *p_h1;
    int *p_cnt, *p_rowptr, *p_cursor, *p_csrc;
    cudaGetSymbolAddress((void**)&p_xl,     g_xl);
    cudaGetSymbolAddress((void**)&p_x1,     g_x1);
    cudaGetSymbolAddress((void**)&p_xw,     g_xw);
    cudaGetSymbolAddress((void**)&p_wt,     g_wt);
    cudaGetSymbolAddress((void**)&p_asrc,   g_asrc);
    cudaGetSymbolAddress((void**)&p_adst,   g_adst);
    cudaGetSymbolAddress((void**)&p_pmax,   g_pmax);
    cudaGetSymbolAddress((void**)&p_psum,   g_psum);
    cudaGetSymbolAddress((void**)&p_h1,     g_h1);
    cudaGetSymbolAddress((void**)&p_cnt,    g_cnt);
    cudaGetSymbolAddress((void**)&p_rowptr, g_rowptr);
    cudaGetSymbolAddress((void**)&p_cursor, g_cursor);
    cudaGetSymbolAddress((void**)&p_csrc,   g_csrc);

    // setup (cnt/pool/h1 init + W_gcn tf32 preround) + CSR build
    const int setupN = N + 2 * HD + H1DIM + HD * HD;
    k_setup<<<cdiv(setupN, 256), 256>>>(p_cnt, p_pmax, p_psum, p_h1, b1, W_gcn, p_wt, N);
    k_count<<<cdiv(EP, 256), 256>>>(ei, p_cnt, E, N);
    k_scan<<<1, 1024>>>(p_cnt, p_rowptr, p_cursor, N, EP);
    k_scatter<<<cdiv(EP, 256), 256>>>(ei, p_cursor, p_csrc, E, N);
    // GEMM1 (mma.sync tf32) + fused attention scores
    k_gemm_tf32<true, true><<<cdiv(N, 128) * (HD / 128), 256>>>(
        x, W_gat, p_xl, N, HD, D, att_src, att_dst, p_asrc, p_adst);
    // GAT online-softmax + aggregation (emits tf32-rounded x1)
    k_gat<<<cdiv(N * 32, 256), 256>>>(p_rowptr, p_csrc, p_xl, p_asrc, p_adst,
                                      b_gat, p_x1, N);
    // GEMM2 (mma.sync tf32, cp.async staging, inputs pre-rounded)
    k_gemm2_cp<<<cdiv(N, 128) * (HD / 128), 256>>>(p_x1, p_wt, p_xw, N, HD, HD);
    // GCN aggregation + fused global pooling
    k_gcn_pool<<<cdiv(N * 32, 256), 256>>>(p_rowptr, p_csrc, p_cnt, p_xw, b_gcn,
                                           p_pmax, p_psum, N);
    // MLP head
    k_mlp1<<<MLP_JBLK * MLP_KSPLIT, 256>>>(p_pmax, p_psum, W1, p_h1, N);
    k_mlp2<<<1, 256>>>(p_h1, W2, b2, out);
}

// round 12
// speedup vs baseline: 1.4246x; 1.0013x over previous
#include <cuda_runtime.h>
#include <float.h>
#include <stdint.h>

// Problem constants (fixed by the dataset)
#define MAXN 20000
#define MAXE 320000
#define MAXEP (MAXE + MAXN)
#define D  64
#define H  10
#define HD 640
#define H1DIM 1500

// ----------------------------- scratch (static, allocation-free) ------------
__device__ __align__(16) float g_xl  [(size_t)MAXN * HD];
__device__ __align__(16) float g_x1  [(size_t)MAXN * HD];
__device__ __align__(16) float g_xw  [(size_t)MAXN * HD];
__device__ __align__(16) float g_wt  [(size_t)HD * HD];    // W_gcn pre-rounded to tf32
__device__ __align__(16) float g_asrc[(size_t)MAXN * H];
__device__ __align__(16) float g_adst[(size_t)MAXN * H];
__device__ __align__(16) float g_pmax[HD];
__device__ __align__(16) float g_psum[HD];
__device__ __align__(16) float g_h1  [H1DIM];
__device__ __align__(16) int g_cnt   [MAXN];
__device__ __align__(16) int g_rowptr[MAXN + 1];
__device__ __align__(16) int g_cursor[MAXN];
__device__ __align__(16) int g_csrc  [MAXEP];

__device__ __forceinline__ uint32_t f2tf32(float x) {
    uint32_t r;
    asm("cvt.rna.tf32.f32 %0, %1;" : "=r"(r) : "f"(x));
    return r;
}
__device__ __forceinline__ float rnd_tf32(float x) {
    return __uint_as_float(f2tf32(x));
}
__device__ __forceinline__ uint32_t smem_u32(const void* p) {
    uint32_t a;
    asm("{ .reg .u64 t; cvta.to.shared.u64 t, %1; cvt.u32.u64 %0, t; }" : "=r"(a) : "l"(p));
    return a;
}
#define CP_ASYNC16(dst, src, sz) \
    asm volatile("cp.async.cg.shared.global [%0], [%1], 16, %2;" \
                 :: "r"(dst), "l"(src), "r"(sz) : "memory")
#define CP_COMMIT() asm volatile("cp.async.commit_group;" ::: "memory")
#define CP_WAIT(n)  asm volatile("cp.async.wait_group %0;" :: "n"(n) : "memory")

// ----------------------------- setup (init + W preround, one launch) ---------
__global__ void k_setup(int* __restrict__ cnt, float* __restrict__ pmax,
                        float* __restrict__ psum, float* __restrict__ h1,
                        const float* __restrict__ b1,
                        const float* __restrict__ w, float* __restrict__ wt, int N) {
    int i = blockIdx.x * blockDim.x + threadIdx.x;
    if (i < N) { cnt[i] = 0; return; }
    i -= N;
    if (i < HD) { pmax[i] = 0.f; return; }
    i -= HD;
    if (i < HD) { psum[i] = 0.f; return; }
    i -= HD;
    if (i < H1DIM) { h1[i] = b1[i]; return; }
    i -= H1DIM;
    if (i < HD * HD) wt[i] = rnd_tf32(w[i]);
}

// ----------------------------- CSR build -------------------------------------
__global__ void k_count(const int* __restrict__ ei, int* __restrict__ cnt, int E, int N) {
    int e = blockIdx.x * blockDim.x + threadIdx.x;
    int EP = E + N;
    if (e >= EP) return;
    int dst = (e < E) ? ei[E + e] : (e - E);
    atomicAdd(&cnt[dst], 1);
}

__global__ __launch_bounds__(1024)
void k_scan(const int* __restrict__ cnt, int* __restrict__ rowptr,
            int* __restrict__ cursor, int N, int EP) {
    __shared__ int sums[1024];
    const int t = threadIdx.x;
    const int per = (N + 1023) >> 10;
    const int start = t * per;
    int vals[20];
    int cn = 0;
    const bool vec = (per % 4 == 0) && (start + per <= N);
    if (vec) {
#pragma unroll
        for (int q = 0; q < 5; q++) {
            if (q * 4 < per) {
                int4 v = *(const int4*)&cnt[start + q * 4];
                vals[q * 4 + 0] = v.x; vals[q * 4 + 1] = v.y;
                vals[q * 4 + 2] = v.z; vals[q * 4 + 3] = v.w;
            }
        }
        cn = per;
    } else if (start < N) {
        cn = min(per, N - start);
        for (int q = 0; q < cn; q++) vals[q] = cnt[start + q];
    }
    int s = 0;
    for (int q = 0; q < cn; q++) s += vals[q];
    sums[t] = s;
    __syncthreads();
    for (int off = 1; off < 1024; off <<= 1) {
        int o = (t >= off) ? sums[t - off] : 0;
        __syncthreads();
        sums[t] += o;
        __syncthreads();
    }
    int run = sums[t] - s;
    for (int q = 0; q < cn; q++) {
        int tmp = vals[q];
        vals[q] = run;
        run += tmp;
    }
    if (vec) {
#pragma unroll
        for (int q = 0; q < 5; q++) {
            if (q * 4 < per) {
                int4 v = make_int4(vals[q * 4 + 0], vals[q * 4 + 1],
                                   vals[q * 4 + 2], vals[q * 4 + 3]);
                *(int4*)&rowptr[start + q * 4] = v;
                *(int4*)&cursor[start + q * 4] = v;
            }
        }
    } else {
        for (int q = 0; q < cn; q++) {
            rowptr[start + q] = vals[q];
            cursor[start + q] = vals[q];
        }
    }
    if (t == 0) rowptr[N] = EP;
}

__global__ void k_scatter(const int* __restrict__ ei, int* __restrict__ cursor,
                          int* __restrict__ csrc, int E, int N) {
    int e = blockIdx.x * blockDim.x + threadIdx.x;
    int EP = E + N;
    if (e >= EP) return;
    int src, dst;
    if (e < E) { src = ei[e]; dst = ei[E + e]; }
    else       { src = dst = e - E; }
    int pos = atomicAdd(&cursor[dst], 1);
    csrc[pos] = src;
}

// ----------------------------- tf32 mma.sync GEMM (GEMM1 + att epilogue) -----
#define GAPAD 20
#define GBPAD 136
template <bool ATT, bool CVT>
__global__ __launch_bounds__(256)
void k_gemm_tf32(const float* __restrict__ A, const float* __restrict__ B,
                 float* __restrict__ C, int M, int Nn, int K,
                 const float* __restrict__ att_src, const float* __restrict__ att_dst,
                 float* __restrict__ asrc, float* __restrict__ adst) {
    __shared__ float As[2][128][GAPAD];
    __shared__ float Bs[2][16][GBPAD];
    const int tid = threadIdx.x;
    const int warp = tid >> 5, lane = tid & 31;
    const int wm = warp & 3, wn = warp >> 2;
    const int nTilesX = Nn / 128;
    const int bx = blockIdx.x % nTilesX;
    const int by = blockIdx.x / nTilesX;
    const int rowBase = by * 128, colBase = bx * 128;

    const int gID = lane >> 2;
    const int tIG = lane & 3;

    float acc[2][8][4];
#pragma unroll
    for (int mt = 0; mt < 2; mt++)
#pragma unroll
        for (int nt = 0; nt < 8; nt++)
#pragma unroll
            for (int r = 0; r < 4; r++) acc[mt][nt][r] = 0.0f;

    const int aR  = tid >> 2;
    const int aC4 = (tid & 3) * 4;
    const int bR  = tid >> 5;
    const int bC4 = lane * 4;

    float4 avr[2], bvr[2];
#pragma unroll
    for (int half = 0; half < 2; half++) {
        int gr = rowBase + aR + half * 64;
        avr[half] = (gr < M) ? *(const float4*)&A[(size_t)gr * K + aC4]
                             : make_float4(0.f, 0.f, 0.f, 0.f);
        bvr[half] = *(const float4*)&B[(size_t)(bR + half * 8) * Nn + colBase + bC4];
    }

    int buf = 0;
    for (int k0 = 0; k0 < K; k0 += 16) {
#pragma unroll
        for (int half = 0; half < 2; half++) {
            int r = aR + half * 64;
            As[buf][r][aC4 + 0] = CVT ? rnd_tf32(avr[half].x) : avr[half].x;
            As[buf][r][aC4 + 1] = CVT ? rnd_tf32(avr[half].y) : avr[half].y;
            As[buf][r][aC4 + 2] = CVT ? rnd_tf32(avr[half].z) : avr[half].z;
            As[buf][r][aC4 + 3] = CVT ? rnd_tf32(avr[half].w) : avr[half].w;
            int rb = bR + half * 8;
            Bs[buf][rb][bC4 + 0] = CVT ? rnd_tf32(bvr[half].x) : bvr[half].x;
            Bs[buf][rb][bC4 + 1] = CVT ? rnd_tf32(bvr[half].y) : bvr[half].y;
            Bs[buf][rb][bC4 + 2] = CVT ? rnd_tf32(bvr[half].z) : bvr[half].z;
            Bs[buf][rb][bC4 + 3] = CVT ? rnd_tf32(bvr[half].w) : bvr[half].w;
        }
        __syncthreads();

        if (k0 + 16 < K) {
#pragma unroll
            for (int half = 0; half < 2; half++) {
                int gr = rowBase + aR + half * 64;
                avr[half] = (gr < M) ? *(const float4*)&A[(size_t)gr * K + k0 + 16 + aC4]
                                     : make_float4(0.f, 0.f, 0.f, 0.f);
                bvr[half] = *(const float4*)&B[(size_t)(k0 + 16 + bR + half * 8) * Nn + colBase + bC4];
            }
        }

#pragma unroll
        for (int ks = 0; ks < 16; ks += 8) {
            uint32_t af[2][4];
#pragma unroll
            for (int mt = 0; mt < 2; mt++) {
                int r0 = wm * 32 + mt * 16 + gID;
                int kc = ks + tIG;
                af[mt][0] = __float_as_uint(As[buf][r0][kc]);
                af[mt][1] = __float_as_uint(As[buf][r0 + 8][kc]);
                af[mt][2] = __float_as_uint(As[buf][r0][kc + 4]);
                af[mt][3] = __float_as_uint(As[buf][r0 + 8][kc + 4]);
            }
#pragma unroll
            for (int nt = 0; nt < 8; nt++) {
                int col = wn * 64 + nt * 8 + gID;
                uint32_t b0 = __float_as_uint(Bs[buf][ks + tIG][col]);
                uint32_t b1 = __float_as_uint(Bs[buf][ks + tIG + 4][col]);
#pragma unroll
                for (int mt = 0; mt < 2; mt++) {
                    asm volatile(
                        "mma.sync.aligned.m16n8k8.row.col.f32.tf32.tf32.f32 "
                        "{%0,%1,%2,%3}, {%4,%5,%6,%7}, {%8,%9}, {%0,%1,%2,%3};\n"
                        : "+f"(acc[mt][nt][0]), "+f"(acc[mt][nt][1]),
                          "+f"(acc[mt][nt][2]), "+f"(acc[mt][nt][3])
                        : "r"(af[mt][0]), "r"(af[mt][1]), "r"(af[mt][2]), "r"(af[mt][3]),
                          "r"(b0), "r"(b1));
                }
            }
        }
        __syncthreads();
        buf ^= 1;
    }

#pragma unroll
    for (int mt = 0; mt < 2; mt++) {
        int r0 = rowBase + wm * 32 + mt * 16 + gID;
#pragma unroll
        for (int nt = 0; nt < 8; nt++) {
            int c0 = colBase + wn * 64 + nt * 8 + tIG * 2;
            if (r0 < M)
                *(float2*)&C[(size_t)r0 * Nn + c0] = make_float2(acc[mt][nt][0], acc[mt][nt][1]);
            if (r0 + 8 < M)
                *(float2*)&C[(size_t)(r0 + 8) * Nn + c0] = make_float2(acc[mt][nt][2], acc[mt][nt][3]);
        }
    }

    if (ATT) {
        const int h = bx * 2 + wn;
        float as[16], ad[16];
#pragma unroll
        for (int nt = 0; nt < 8; nt++)
#pragma unroll
            for (int p = 0; p < 2; p++) {
                int cih = nt * 8 + tIG * 2 + p;
                as[nt * 2 + p] = att_src[h * D + cih];
                ad[nt * 2 + p] = att_dst[h * D + cih];
            }
#pragma unroll
        for (int mt = 0; mt < 2; mt++) {
#pragma unroll
            for (int pair = 0; pair < 2; pair++) {
                float ps = 0.f, pd = 0.f;
#pragma unroll
                for (int nt = 0; nt < 8; nt++)
#pragma unroll
                    for (int p = 0; p < 2; p++) {
                        float v = acc[mt][nt][pair * 2 + p];
                        ps += v * as[nt * 2 + p];
                        pd += v * ad[nt * 2 + p];
                    }
                ps += __shfl_down_sync(0xffffffffu, ps, 2, 4);
                ps += __shfl_down_sync(0xffffffffu, ps, 1, 4);
                pd += __shfl_down_sync(0xffffffffu, pd, 2, 4);
                pd += __shfl_down_sync(0xffffffffu, pd, 1, 4);
                int gr = rowBase + wm * 32 + mt * 16 + gID + pair * 8;
                if (tIG == 0 && gr < M) {
                    asrc[gr * H + h] = ps;
                    adst[gr * H + h] = pd;
                }
            }
        }
    }
}

// ----------------------------- GEMM2: mma.sync tf32 + 3-stage cp.async -------
// Inputs pre-rounded tf32. Dynamic smem: As[3][128][GAPAD] then Bs[3][16][GBPAD].
#define ASTRIDE (128 * GAPAD)
#define BSTRIDE (16 * GBPAD)
#define G2_SMEM ((3 * ASTRIDE + 3 * BSTRIDE) * (int)sizeof(float))
__global__ __launch_bounds__(256)
void k_gemm2_cp(const float* __restrict__ A, const float* __restrict__ B,
                float* __restrict__ C, int M, int Nn, int K) {
    extern __shared__ __align__(16) float dsm[];
    float* Asm = dsm;                 // [3][128][GAPAD]
    float* Bsm = dsm + 3 * ASTRIDE;   // [3][16][GBPAD]

    const int tid = threadIdx.x;
    const int warp = tid >> 5, lane = tid & 31;
    const int wm = warp & 3, wn = warp >> 2;
    const int nTilesX = Nn / 128;
    const int bx = blockIdx.x % nTilesX;
    const int by = blockIdx.x / nTilesX;
    const int rowBase = by * 128, colBase = bx * 128;

    const int gID = lane >> 2;
    const int tIG = lane & 3;

    float acc[2][8][4];
#pragma unroll
    for (int mt = 0; mt < 2; mt++)
#pragma unroll
        for (int nt = 0; nt < 8; nt++)
#pragma unroll
            for (int r = 0; r < 4; r++) acc[mt][nt][r] = 0.0f;

    const int aR  = tid >> 2;
    const int aC4 = (tid & 3) * 4;
    const int bR  = tid >> 5;
    const int bC4 = lane * 4;

    auto issue = [&](int st, int k0) {
        float* As = Asm + st * ASTRIDE;
        float* Bs = Bsm + st * BSTRIDE;
#pragma unroll
        for (int half = 0; half < 2; half++) {
            int r = aR + half * 64;
            int gr = rowBase + r;
            uint32_t da = smem_u32(&As[r * GAPAD + aC4]);
            const float* sa = &A[(size_t)gr * K + k0 + aC4];
            int sz = (gr < M) ? 16 : 0;
            CP_ASYNC16(da, sa, sz);
            int rb = bR + half * 8;
            uint32_t db = smem_u32(&Bs[rb * GBPAD + bC4]);
            const float* sb = &B[(size_t)(k0 + rb) * Nn + colBase + bC4];
            CP_ASYNC16(db, sb, 16);
        }
        CP_COMMIT();
    };

    const int NCH = K / 16;           // 40
    issue(0, 0);
    issue(1, 16);
    for (int ch = 0; ch < NCH; ch++) {
        CP_WAIT(1);                   // stage ch landed
        __syncthreads();              // also releases buffer (ch-1)%3 readers
        if (ch + 2 < NCH) issue((ch + 2) % 3, (ch + 2) * 16);

        const float* As = Asm + (ch % 3) * ASTRIDE;
        const float* Bs = Bsm + (ch % 3) * BSTRIDE;
#pragma unroll
        for (int ks = 0; ks < 16; ks += 8) {
            uint32_t af[2][4];
#pragma unroll
            for (int mt = 0; mt < 2; mt++) {
                int r0 = wm * 32 + mt * 16 + gID;
                int kc = ks + tIG;
                af[mt][0] = __float_as_uint(As[r0 * GAPAD + kc]);
                af[mt][1] = __float_as_uint(As[(r0 + 8) * GAPAD + kc]);
                af[mt][2] = __float_as_uint(As[r0 * GAPAD + kc + 4]);
                af[mt][3] = __float_as_uint(As[(r0 + 8) * GAPAD + kc + 4]);
            }
#pragma unroll
            for (int nt = 0; nt < 8; nt++) {
                int col = wn * 64 + nt * 8 + gID;
                uint32_t b0 = __float_as_uint(Bs[(ks + tIG) * GBPAD + col]);
                uint32_t b1 = __float_as_uint(Bs[(ks + tIG + 4) * GBPAD + col]);
#pragma unroll
                for (int mt = 0; mt < 2; mt++) {
                    asm volatile(
                        "mma.sync.aligned.m16n8k8.row.col.f32.tf32.tf32.f32 "
                        "{%0,%1,%2,%3}, {%4,%5,%6,%7}, {%8,%9}, {%0,%1,%2,%3};\n"
                        : "+f"(acc[mt][nt][0]), "+f"(acc[mt][nt][1]),
                          "+f"(acc[mt][nt][2]), "+f"(acc[mt][nt][3])
                        : "r"(af[mt][0]), "r"(af[mt][1]), "r"(af[mt][2]), "r"(af[mt][3]),
                          "r"(b0), "r"(b1));
                }
            }
        }
    }

#pragma unroll
    for (int mt = 0; mt < 2; mt++) {
        int r0 = rowBase + wm * 32 + mt * 16 + gID;
#pragma unroll
        for (int nt = 0; nt < 8; nt++) {
            int c0 = colBase + wn * 64 + nt * 8 + tIG * 2;
            if (r0 < M)
                *(float2*)&C[(size_t)r0 * Nn + c0] = make_float2(acc[mt][nt][0], acc[mt][nt][1]);
            if (r0 + 8 < M)
                *(float2*)&C[(size_t)(r0 + 8) * Nn + c0] = make_float2(acc[mt][nt][2], acc[mt][nt][3]);
        }
    }
}

// ----------------------------- GAT: one warp per node ------------------------
__global__ __launch_bounds__(256)
void k_gat(const int* __restrict__ rowptr, const int* __restrict__ csrc,
           const float* __restrict__ xl,
           const float* __restrict__ asrc, const float* __restrict__ adst,
           const float* __restrict__ bias, float* __restrict__ x1, int N) {
    int w = (blockIdx.x * blockDim.x + threadIdx.x) >> 5;
    int lane = threadIdx.x & 31;
    if (w >= N) return;
    const int row = rowptr[w];
    const int end = rowptr[w + 1];

    const int h = lane % H;
    const int c = lane / H;
    const float adst_h = (lane < 30) ? adst[w * H + h] : 0.f;

    float m = -FLT_MAX, den = 0.f;
    if (lane < 30) {
        for (int i = row + c; i < end; i += 3) {
            int s = csrc[i];
            float a = asrc[s * H + h] + adst_h;
            a = a > 0.f ? a : 0.2f * a;
            float nm = fmaxf(m, a);
            den = den * __expf(m - nm) + __expf(a - nm);
            m = nm;
        }
    }
    {
        float mA = __shfl_sync(0xffffffffu, m,   lane + 10);
        float dA = __shfl_sync(0xffffffffu, den, lane + 10);
        float mB = __shfl_sync(0xffffffffu, m,   lane + 20);
        float dB = __shfl_sync(0xffffffffu, den, lane + 20);
        float M2 = fmaxf(m, fmaxf(mA, mB));
        den = den * __expf(m - M2) + dA * __expf(mA - M2) + dB * __expf(mB - M2);
        m = M2;
    }
    const float invden = 1.0f / (den + 1e-16f);

    float4 acc4[5];
#pragma unroll
    for (int j = 0; j < 5; j++) acc4[j] = make_float4(0.f, 0.f, 0.f, 0.f);

    const int hsel = lane >> 4;
    int i = row;
    for (; i + 1 < end; i += 2) {
        int s0 = csrc[i];
        int s1 = csrc[i + 1];
        float wv0 = 0.f, wv1 = 0.f;
        if (lane < H) {
            float a0 = asrc[s0 * H + lane] + adst_h;
            float a1 = asrc[s1 * H + lane] + adst_h;
            a0 = a0 > 0.f ? a0 : 0.2f * a0;
            a1 = a1 > 0.f ? a1 : 0.2f * a1;
            wv0 = __expf(a0 - m) * invden;
            wv1 = __expf(a1 - m) * invden;
        }
        const float4* xs0 = (const float4*)(xl + (size_t)s0 * HD);
        const float4* xs1 = (const float4*)(xl + (size_t)s1 * HD);
        float4 v0[5], v1[5];
#pragma unroll
        for (int j = 0; j < 5; j++) { v0[j] = xs0[lane + 32 * j]; v1[j] = xs1[lane + 32 * j]; }
#pragma unroll
        for (int j = 0; j < 5; j++) {
            float w0 = __shfl_sync(0xffffffffu, wv0, 2 * j + hsel);
            float w1 = __shfl_sync(0xffffffffu, wv1, 2 * j + hsel);
            acc4[j].x += v0[j].x * w0 + v1[j].x * w1;
            acc4[j].y += v0[j].y * w0 + v1[j].y * w1;
            acc4[j].z += v0[j].z * w0 + v1[j].z * w1;
            acc4[j].w += v0[j].w * w0 + v1[j].w * w1;
        }
    }
    if (i < end) {
        int s = csrc[i];
        float wv = 0.f;
        if (lane < H) {
            float a = asrc[s * H + lane] + adst_h;
            a = a > 0.f ? a : 0.2f * a;
            wv = __expf(a - m) * invden;
        }
        const float4* xs4 = (const float4*)(xl + (size_t)s * HD);
#pragma unroll
        for (int j = 0; j < 5; j++) {
            float wj = __shfl_sync(0xffffffffu, wv, 2 * j + hsel);
            float4 v = xs4[lane + 32 * j];
            acc4[j].x += v.x * wj;
            acc4[j].y += v.y * wj;
            acc4[j].z += v.z * wj;
            acc4[j].w += v.w * wj;
        }
    }

    float4* xo4 = (float4*)(x1 + (size_t)w * HD);
    const float4* b4 = (const float4*)bias;
#pragma unroll
    for (int j = 0; j < 5; j++) {
        int idx = lane + 32 * j;
        float4 bb = b4[idx];
        float4 v = acc4[j];
        v.x = rnd_tf32(fmaxf(v.x + bb.x, 0.f));
        v.y = rnd_tf32(fmaxf(v.y + bb.y, 0.f));
        v.z = rnd_tf32(fmaxf(v.z + bb.z, 0.f));
        v.w = rnd_tf32(fmaxf(v.w + bb.w, 0.f));
        xo4[idx] = v;
    }
}

// ----------------------------- GCN + fused global pooling --------------------
__global__ __launch_bounds__(256)
void k_gcn_pool(const int* __restrict__ rowptr, const int* __restrict__ csrc,
                const int* __restrict__ cnt, const float* __restrict__ xw,
                const float* __restrict__ bias,
                float* __restrict__ pmax, float* __restrict__ psum, int N) {
    __shared__ float smax[HD];
    __shared__ float ssum[HD];
    const int tid = threadIdx.x;
    for (int i = tid; i < HD; i += 256) { smax[i] = 0.f; ssum[i] = 0.f; }
    __syncthreads();

    const int w = (blockIdx.x * blockDim.x + tid) >> 5;
    const int lane = tid & 31;

    if (w < N) {
        const int row = rowptr[w];
        const int end = rowptr[w + 1];
        const float dn = rsqrtf((float)(end - row));

        float4 acc4[5];
#pragma unroll
        for (int j = 0; j < 5; j++) acc4[j] = make_float4(0.f, 0.f, 0.f, 0.f);

        int i = row;
        for (; i + 1 < end; i += 2) {
            int s0 = csrc[i];
            int s1 = csrc[i + 1];
            float n0 = dn * rsqrtf((float)cnt[s0]);
            float n1 = dn * rsqrtf((float)cnt[s1]);
            const float4* xs0 = (const float4*)(xw + (size_t)s0 * HD);
            const float4* xs1 = (const float4*)(xw + (size_t)s1 * HD);
            float4 v0[5], v1[5];
#pragma unroll
            for (int j = 0; j < 5; j++) { v0[j] = xs0[lane + 32 * j]; v1[j] = xs1[lane + 32 * j]; }
#pragma unroll
            for (int j = 0; j < 5; j++) {
                acc4[j].x += v0[j].x * n0 + v1[j].x * n1;
                acc4[j].y += v0[j].y * n0 + v1[j].y * n1;
                acc4[j].z += v0[j].z * n0 + v1[j].z * n1;
                acc4[j].w += v0[j].w * n0 + v1[j].w * n1;
            }
        }
        if (i < end) {
            int s = csrc[i];
            float nrm = dn * rsqrtf((float)cnt[s]);
            const float4* xs4 = (const float4*)(xw + (size_t)s * HD);
#pragma unroll
            for (int j = 0; j < 5; j++) {
                float4 v = xs4[lane + 32 * j];
                acc4[j].x += v.x * nrm;
                acc4[j].y += v.y * nrm;
                acc4[j].z += v.z * nrm;
                acc4[j].w += v.w * nrm;
            }
        }

        const float4* b4 = (const float4*)bias;
#pragma unroll
        for (int j = 0; j < 5; j++) {
            int idx = lane + 32 * j;
            float4 bb = b4[idx];
            float4 v = acc4[j];
            v.x = fmaxf(v.x + bb.x, 0.f);
            v.y = fmaxf(v.y + bb.y, 0.f);
            v.z = fmaxf(v.z + bb.z, 0.f);
            v.w = fmaxf(v.w + bb.w, 0.f);
            int col = idx * 4;
            atomicMax((int*)&smax[col + 0], __float_as_int(v.x));
            atomicMax((int*)&smax[col + 1], __float_as_int(v.y));
            atomicMax((int*)&smax[col + 2], __float_as_int(v.z));
            atomicMax((int*)&smax[col + 3], __float_as_int(v.w));
            atomicAdd(&ssum[col + 0], v.x);
            atomicAdd(&ssum[col + 1], v.y);
            atomicAdd(&ssum[col + 2], v.z);
            atomicAdd(&ssum[col + 3], v.w);
        }
    }
    __syncthreads();

    for (int i = tid; i < HD; i += 256) {
        atomicMax((int*)&pmax[i], __float_as_int(smax[i]));
        atomicAdd(&psum[i], ssum[i]);
    }
}

// ----------------------------- MLP (k-split parallel) ------------------------
#define MLP_KSPLIT 10
#define MLP_JBLK   6
__global__ void k_mlp1(const float* __restrict__ pmax, const float* __restrict__ psum,
                       const float* __restrict__ W1, float* __restrict__ h1, int N) {
    const int jb = blockIdx.x % MLP_JBLK;
    const int s  = blockIdx.x / MLP_JBLK;
    const int j = jb * 256 + threadIdx.x;
    if (j >= H1DIM) return;
    const float invN = 1.0f / (float)N;
    const int k0 = s * (2 * HD / MLP_KSPLIT);
    float acc = 0.f;
#pragma unroll 4
    for (int k = k0; k < k0 + 2 * HD / MLP_KSPLIT; k++) {
        float v = (k < HD) ? pmax[k] : psum[k - HD] * invN;
        acc += v * W1[(size_t)k * H1DIM + j];
    }
    atomicAdd(&h1[j], acc);
}

__global__ void k_mlp2(const float* __restrict__ h1, const float* __restrict__ W2,
                       const float* __restrict__ b2, float* __restrict__ out) {
    __shared__ float acc[10];
    int tid = threadIdx.x;
    if (tid < 10) acc[tid] = 0.0f;
    __syncthreads();
    float part[10];
#pragma unroll
    for (int j = 0; j < 10; j++) part[j] = 0.0f;
    for (int k = tid; k < H1DIM; k += 256) {
        float hv = fmaxf(h1[k], 0.0f);
#pragma unroll
        for (int j = 0; j < 10; j++) part[j] += hv * W2[k * 10 + j];
    }
#pragma unroll
    for (int j = 0; j < 10; j++) atomicAdd(&acc[j], part[j]);
    __syncthreads();
    if (tid < 10) out[tid] = acc[tid] + b2[tid];
}

// ----------------------------- launch -----------------------------------------
static inline int cdiv(int a, int b) { return (a + b - 1) / b; }

extern "C" void kernel_launch(void* const* d_in, const int* in_sizes, int n_in,
                              void* d_out, int out_size) {
    const float* x       = (const float*)d_in[0];
    const float* W_gat   = (const float*)d_in[1];
    const float* att_src = (const float*)d_in[2];
    const float* att_dst = (const float*)d_in[3];
    const float* b_gat   = (const float*)d_in[4];
    const float* W_gcn   = (const float*)d_in[5];
    const float* b_gcn   = (const float*)d_in[6];
    const float* W1      = (const float*)d_in[7];
    const float* b1      = (const float*)d_in[8];
    const float* W2      = (const float*)d_in[9];
    const float* b2      = (const float*)d_in[10];
    const int*   ei      = (const int*)d_in[11];

    const int N  = in_sizes[0] / D;
    const int E  = in_sizes[11] / 2;
    const int EP = E + N;
    float* out = (float*)d_out;

    float *p_xl, *p_x1, *p_xw, *p_wt, *p_asrc, *p_adst, *p_pmax, *p_psum, *p_h1;
    int *p_cnt, *p_rowptr, *p_cursor, *p_csrc;
    cudaGetSymbolAddress((void**)&p_xl,     g_xl);
    cudaGetSymbolAddress((void**)&p_x1,     g_x1);
    cudaGetSymbolAddress((void**)&p_xw,     g_xw);
    cudaGetSymbolAddress((void**)&p_wt,     g_wt);
    cudaGetSymbolAddress((void**)&p_asrc,   g_asrc);
    cudaGetSymbolAddress((void**)&p_adst,   g_adst);
    cudaGetSymbolAddress((void**)&p_pmax,   g_pmax);
    cudaGetSymbolAddress((void**)&p_psum,   g_psum);
    cudaGetSymbolAddress((void**)&p_h1,     g_h1);
    cudaGetSymbolAddress((void**)&p_cnt,    g_cnt);
    cudaGetSymbolAddress((void**)&p_rowptr, g_rowptr);
    cudaGetSymbolAddress((void**)&p_cursor, g_cursor);
    cudaGetSymbolAddress((void**)&p_csrc,   g_csrc);

    // side stream + events for GEMM1 || CSR overlap (created per call; NOT
    // destroyed here — destruction mid-capture would invalidate the graph.
    // No device memory involved; replay cost is unaffected.)
    cudaStream_t s2;
    cudaStreamCreate(&s2);
    cudaEvent_t evF, evJ;
    cudaEventCreateWithFlags(&evF, cudaEventDisableTiming);
    cudaEventCreateWithFlags(&evJ, cudaEventDisableTiming);

    // fork: GEMM1 (depends only on x/W_gat) runs on s2
    cudaEventRecord(evF, 0);
    cudaStreamWaitEvent(s2, evF, 0);
    k_gemm_tf32<true, true><<<cdiv(N, 128) * (HD / 128), 256, 0, s2>>>(
        x, W_gat, p_xl, N, HD, D, att_src, att_dst, p_asrc, p_adst);
    cudaEventRecord(evJ, s2);

    // main stream: setup + CSR build (independent of GEMM1)
    const int setupN = N + 2 * HD + H1DIM + HD * HD;
    k_setup<<<cdiv(setupN, 256), 256>>>(p_cnt, p_pmax, p_psum, p_h1, b1, W_gcn, p_wt, N);
    k_count<<<cdiv(EP, 256), 256>>>(ei, p_cnt, E, N);
    k_scan<<<1, 1024>>>(p_cnt, p_rowptr, p_cursor, N, EP);
    k_scatter<<<cdiv(EP, 256), 256>>>(ei, p_cursor, p_csrc, E, N);

    // join: k_gat needs both CSR and GEMM1 outputs
    cudaStreamWaitEvent(0, evJ, 0);
    k_gat<<<cdiv(N * 32, 256), 256>>>(p_rowptr, p_csrc, p_xl, p_asrc, p_adst,
                                      b_gat, p_x1, N);
    // GEMM2 (mma.sync tf32, 3-stage cp.async, inputs pre-rounded)
    cudaFuncSetAttribute(k_gemm2_cp, cudaFuncAttributeMaxDynamicSharedMemorySize, G2_SMEM);
    k_gemm2_cp<<<cdiv(N, 128) * (HD / 128), 256, G2_SMEM>>>(p_x1, p_wt, p_xw, N, HD, HD);
    // GCN aggregation + fused global pooling
    k_gcn_pool<<<cdiv(N * 32, 256), 256>>>(p_rowptr, p_csrc, p_cnt, p_xw, b_gcn,
                                           p_pmax, p_psum, N);
    // MLP head
    k_mlp1<<<MLP_JBLK * MLP_KSPLIT, 256>>>(p_pmax, p_psum, W1, p_h1, N);
    k_mlp2<<<1, 256>>>(p_h1, W2, b2, out);
}

// round 13
// speedup vs baseline: 1.4880x; 1.0445x over previous
#include <cuda_runtime.h>
#include <cuda_fp16.h>
#include <float.h>
#include <stdint.h>

// Problem constants (fixed by the dataset)
#define MAXN 20000
#define MAXE 320000
#define MAXEP (MAXE + MAXN)
#define D  64
#define H  10
#define HD 640
#define H1DIM 1500

// ----------------------------- scratch (static, allocation-free) ------------
__device__ __align__(16) __half g_xlh[(size_t)MAXN * HD];  // GAT features, fp16
__device__ __align__(16) float g_x1  [(size_t)MAXN * HD];
__device__ __align__(16) float g_xw  [(size_t)MAXN * HD];
__device__ __align__(16) float g_wt  [(size_t)HD * HD];    // W_gcn pre-rounded to tf32
__device__ __align__(16) float g_asrc[(size_t)MAXN * H];
__device__ __align__(16) float g_adst[(size_t)MAXN * H];
__device__ __align__(16) float g_pmax[HD];
__device__ __align__(16) float g_psum[HD];
__device__ __align__(16) float g_h1  [H1DIM];
__device__ __align__(16) int g_cnt   [MAXN];
__device__ __align__(16) int g_rowptr[MAXN + 1];
__device__ __align__(16) int g_cursor[MAXN];
__device__ __align__(16) int g_csrc  [MAXEP];

__device__ __forceinline__ uint32_t f2tf32(float x) {
    uint32_t r;
    asm("cvt.rna.tf32.f32 %0, %1;" : "=r"(r) : "f"(x));
    return r;
}
__device__ __forceinline__ float rnd_tf32(float x) {
    return __uint_as_float(f2tf32(x));
}
__device__ __forceinline__ uint32_t smem_u32(const void* p) {
    uint32_t a;
    asm("{ .reg .u64 t; cvta.to.shared.u64 t, %1; cvt.u32.u64 %0, t; }" : "=r"(a) : "l"(p));
    return a;
}
#define CP_ASYNC16(dst, src, sz) \
    asm volatile("cp.async.cg.shared.global [%0], [%1], 16, %2;" \
                 :: "r"(dst), "l"(src), "r"(sz) : "memory")
#define CP_COMMIT() asm volatile("cp.async.commit_group;" ::: "memory")
#define CP_WAIT(n)  asm volatile("cp.async.wait_group %0;" :: "n"(n) : "memory")

// ----------------------------- setup (init + W preround, one launch) ---------
__global__ void k_setup(int* __restrict__ cnt, float* __restrict__ pmax,
                        float* __restrict__ psum, float* __restrict__ h1,
                        const float* __restrict__ b1,
                        const float* __restrict__ w, float* __restrict__ wt, int N) {
    int i = blockIdx.x * blockDim.x + threadIdx.x;
    if (i < N) { cnt[i] = 0; return; }
    i -= N;
    if (i < HD) { pmax[i] = 0.f; return; }
    i -= HD;
    if (i < HD) { psum[i] = 0.f; return; }
    i -= HD;
    if (i < H1DIM) { h1[i] = b1[i]; return; }
    i -= H1DIM;
    if (i < HD * HD) wt[i] = rnd_tf32(w[i]);
}

// ----------------------------- CSR build -------------------------------------
__global__ void k_count(const int* __restrict__ ei, int* __restrict__ cnt, int E, int N) {
    int e = blockIdx.x * blockDim.x + threadIdx.x;
    int EP = E + N;
    if (e >= EP) return;
    int dst = (e < E) ? ei[E + e] : (e - E);
    atomicAdd(&cnt[dst], 1);
}

__global__ __launch_bounds__(1024)
void k_scan(const int* __restrict__ cnt, int* __restrict__ rowptr,
            int* __restrict__ cursor, int N, int EP) {
    __shared__ int sums[1024];
    const int t = threadIdx.x;
    const int per = (N + 1023) >> 10;
    const int start = t * per;
    int vals[20];
    int cn = 0;
    const bool vec = (per % 4 == 0) && (start + per <= N);
    if (vec) {
#pragma unroll
        for (int q = 0; q < 5; q++) {
            if (q * 4 < per) {
                int4 v = *(const int4*)&cnt[start + q * 4];
                vals[q * 4 + 0] = v.x; vals[q * 4 + 1] = v.y;
                vals[q * 4 + 2] = v.z; vals[q * 4 + 3] = v.w;
            }
        }
        cn = per;
    } else if (start < N) {
        cn = min(per, N - start);
        for (int q = 0; q < cn; q++) vals[q] = cnt[start + q];
    }
    int s = 0;
    for (int q = 0; q < cn; q++) s += vals[q];
    sums[t] = s;
    __syncthreads();
    for (int off = 1; off < 1024; off <<= 1) {
        int o = (t >= off) ? sums[t - off] : 0;
        __syncthreads();
        sums[t] += o;
        __syncthreads();
    }
    int run = sums[t] - s;
    for (int q = 0; q < cn; q++) {
        int tmp = vals[q];
        vals[q] = run;
        run += tmp;
    }
    if (vec) {
#pragma unroll
        for (int q = 0; q < 5; q++) {
            if (q * 4 < per) {
                int4 v = make_int4(vals[q * 4 + 0], vals[q * 4 + 1],
                                   vals[q * 4 + 2], vals[q * 4 + 3]);
                *(int4*)&rowptr[start + q * 4] = v;
                *(int4*)&cursor[start + q * 4] = v;
            }
        }
    } else {
        for (int q = 0; q < cn; q++) {
            rowptr[start + q] = vals[q];
            cursor[start + q] = vals[q];
        }
    }
    if (t == 0) rowptr[N] = EP;
}

__global__ void k_scatter(const int* __restrict__ ei, int* __restrict__ cursor,
                          int* __restrict__ csrc, int E, int N) {
    int e = blockIdx.x * blockDim.x + threadIdx.x;
    int EP = E + N;
    if (e >= EP) return;
    int src, dst;
    if (e < E) { src = ei[e]; dst = ei[E + e]; }
    else       { src = dst = e - E; }
    int pos = atomicAdd(&cursor[dst], 1);
    csrc[pos] = src;
}

// ----------------------------- tf32 mma.sync GEMM1 (half output + att) -------
#define GAPAD 20
#define GBPAD 136
__global__ __launch_bounds__(256)
void k_gemm1_h(const float* __restrict__ A, const float* __restrict__ B,
               __half* __restrict__ Ch, int M, int Nn, int K,
               const float* __restrict__ att_src, const float* __restrict__ att_dst,
               float* __restrict__ asrc, float* __restrict__ adst) {
    __shared__ float As[2][128][GAPAD];
    __shared__ float Bs[2][16][GBPAD];
    const int tid = threadIdx.x;
    const int warp = tid >> 5, lane = tid & 31;
    const int wm = warp & 3, wn = warp >> 2;
    const int nTilesX = Nn / 128;
    const int bx = blockIdx.x % nTilesX;
    const int by = blockIdx.x / nTilesX;
    const int rowBase = by * 128, colBase = bx * 128;

    const int gID = lane >> 2;
    const int tIG = lane & 3;

    float acc[2][8][4];
#pragma unroll
    for (int mt = 0; mt < 2; mt++)
#pragma unroll
        for (int nt = 0; nt < 8; nt++)
#pragma unroll
            for (int r = 0; r < 4; r++) acc[mt][nt][r] = 0.0f;

    const int aR  = tid >> 2;
    const int aC4 = (tid & 3) * 4;
    const int bR  = tid >> 5;
    const int bC4 = lane * 4;

    float4 avr[2], bvr[2];
#pragma unroll
    for (int half_ = 0; half_ < 2; half_++) {
        int gr = rowBase + aR + half_ * 64;
        avr[half_] = (gr < M) ? *(const float4*)&A[(size_t)gr * K + aC4]
                              : make_float4(0.f, 0.f, 0.f, 0.f);
        bvr[half_] = *(const float4*)&B[(size_t)(bR + half_ * 8) * Nn + colBase + bC4];
    }

    int buf = 0;
    for (int k0 = 0; k0 < K; k0 += 16) {
#pragma unroll
        for (int half_ = 0; half_ < 2; half_++) {
            int r = aR + half_ * 64;
            As[buf][r][aC4 + 0] = rnd_tf32(avr[half_].x);
            As[buf][r][aC4 + 1] = rnd_tf32(avr[half_].y);
            As[buf][r][aC4 + 2] = rnd_tf32(avr[half_].z);
            As[buf][r][aC4 + 3] = rnd_tf32(avr[half_].w);
            int rb = bR + half_ * 8;
            Bs[buf][rb][bC4 + 0] = rnd_tf32(bvr[half_].x);
            Bs[buf][rb][bC4 + 1] = rnd_tf32(bvr[half_].y);
            Bs[buf][rb][bC4 + 2] = rnd_tf32(bvr[half_].z);
            Bs[buf][rb][bC4 + 3] = rnd_tf32(bvr[half_].w);
        }
        __syncthreads();

        if (k0 + 16 < K) {
#pragma unroll
            for (int half_ = 0; half_ < 2; half_++) {
                int gr = rowBase + aR + half_ * 64;
                avr[half_] = (gr < M) ? *(const float4*)&A[(size_t)gr * K + k0 + 16 + aC4]
                                      : make_float4(0.f, 0.f, 0.f, 0.f);
                bvr[half_] = *(const float4*)&B[(size_t)(k0 + 16 + bR + half_ * 8) * Nn + colBase + bC4];
            }
        }

#pragma unroll
        for (int ks = 0; ks < 16; ks += 8) {
            uint32_t af[2][4];
#pragma unroll
            for (int mt = 0; mt < 2; mt++) {
                int r0 = wm * 32 + mt * 16 + gID;
                int kc = ks + tIG;
                af[mt][0] = __float_as_uint(As[buf][r0][kc]);
                af[mt][1] = __float_as_uint(As[buf][r0 + 8][kc]);
                af[mt][2] = __float_as_uint(As[buf][r0][kc + 4]);
                af[mt][3] = __float_as_uint(As[buf][r0 + 8][kc + 4]);
            }
#pragma unroll
            for (int nt = 0; nt < 8; nt++) {
                int col = wn * 64 + nt * 8 + gID;
                uint32_t b0 = __float_as_uint(Bs[buf][ks + tIG][col]);
                uint32_t b1 = __float_as_uint(Bs[buf][ks + tIG + 4][col]);
#pragma unroll
                for (int mt = 0; mt < 2; mt++) {
                    asm volatile(
                        "mma.sync.aligned.m16n8k8.row.col.f32.tf32.tf32.f32 "
                        "{%0,%1,%2,%3}, {%4,%5,%6,%7}, {%8,%9}, {%0,%1,%2,%3};\n"
                        : "+f"(acc[mt][nt][0]), "+f"(acc[mt][nt][1]),
                          "+f"(acc[mt][nt][2]), "+f"(acc[mt][nt][3])
                        : "r"(af[mt][0]), "r"(af[mt][1]), "r"(af[mt][2]), "r"(af[mt][3]),
                          "r"(b0), "r"(b1));
                }
            }
        }
        __syncthreads();
        buf ^= 1;
    }

    // write C as fp16 (half2 per register pair)
#pragma unroll
    for (int mt = 0; mt < 2; mt++) {
        int r0 = rowBase + wm * 32 + mt * 16 + gID;
#pragma unroll
        for (int nt = 0; nt < 8; nt++) {
            int c0 = colBase + wn * 64 + nt * 8 + tIG * 2;
            if (r0 < M)
                *(__half2*)&Ch[(size_t)r0 * Nn + c0] =
                    __floats2half2_rn(acc[mt][nt][0], acc[mt][nt][1]);
            if (r0 + 8 < M)
                *(__half2*)&Ch[(size_t)(r0 + 8) * Nn + c0] =
                    __floats2half2_rn(acc[mt][nt][2], acc[mt][nt][3]);
        }
    }

    // attention epilogue from exact fp32 accumulators
    {
        const int h = bx * 2 + wn;
        float as[16], ad[16];
#pragma unroll
        for (int nt = 0; nt < 8; nt++)
#pragma unroll
            for (int p = 0; p < 2; p++) {
                int cih = nt * 8 + tIG * 2 + p;
                as[nt * 2 + p] = att_src[h * D + cih];
                ad[nt * 2 + p] = att_dst[h * D + cih];
            }
#pragma unroll
        for (int mt = 0; mt < 2; mt++) {
#pragma unroll
            for (int pair = 0; pair < 2; pair++) {
                float ps = 0.f, pd = 0.f;
#pragma unroll
                for (int nt = 0; nt < 8; nt++)
#pragma unroll
                    for (int p = 0; p < 2; p++) {
                        float v = acc[mt][nt][pair * 2 + p];
                        ps += v * as[nt * 2 + p];
                        pd += v * ad[nt * 2 + p];
                    }
                ps += __shfl_down_sync(0xffffffffu, ps, 2, 4);
                ps += __shfl_down_sync(0xffffffffu, ps, 1, 4);
                pd += __shfl_down_sync(0xffffffffu, pd, 2, 4);
                pd += __shfl_down_sync(0xffffffffu, pd, 1, 4);
                int gr = rowBase + wm * 32 + mt * 16 + gID + pair * 8;
                if (tIG == 0 && gr < M) {
                    asrc[gr * H + h] = ps;
                    adst[gr * H + h] = pd;
                }
            }
        }
    }
}

// ----------------------------- GEMM2: mma.sync tf32 + 3-stage cp.async -------
#define ASTRIDE (128 * GAPAD)
#define BSTRIDE (16 * GBPAD)
#define G2_SMEM ((3 * ASTRIDE + 3 * BSTRIDE) * (int)sizeof(float))
__global__ __launch_bounds__(256)
void k_gemm2_cp(const float* __restrict__ A, const float* __restrict__ B,
                float* __restrict__ C, int M, int Nn, int K) {
    extern __shared__ __align__(16) float dsm[];
    float* Asm = dsm;
    float* Bsm = dsm + 3 * ASTRIDE;

    const int tid = threadIdx.x;
    const int warp = tid >> 5, lane = tid & 31;
    const int wm = warp & 3, wn = warp >> 2;
    const int nTilesX = Nn / 128;
    const int bx = blockIdx.x % nTilesX;
    const int by = blockIdx.x / nTilesX;
    const int rowBase = by * 128, colBase = bx * 128;

    const int gID = lane >> 2;
    const int tIG = lane & 3;

    float acc[2][8][4];
#pragma unroll
    for (int mt = 0; mt < 2; mt++)
#pragma unroll
        for (int nt = 0; nt < 8; nt++)
#pragma unroll
            for (int r = 0; r < 4; r++) acc[mt][nt][r] = 0.0f;

    const int aR  = tid >> 2;
    const int aC4 = (tid & 3) * 4;
    const int bR  = tid >> 5;
    const int bC4 = lane * 4;

    auto issue = [&](int st, int k0) {
        float* As = Asm + st * ASTRIDE;
        float* Bs = Bsm + st * BSTRIDE;
#pragma unroll
        for (int half_ = 0; half_ < 2; half_++) {
            int r = aR + half_ * 64;
            int gr = rowBase + r;
            uint32_t da = smem_u32(&As[r * GAPAD + aC4]);
            const float* sa = &A[(size_t)gr * K + k0 + aC4];
            int sz = (gr < M) ? 16 : 0;
            CP_ASYNC16(da, sa, sz);
            int rb = bR + half_ * 8;
            uint32_t db = smem_u32(&Bs[rb * GBPAD + bC4]);
            const float* sb = &B[(size_t)(k0 + rb) * Nn + colBase + bC4];
            CP_ASYNC16(db, sb, 16);
        }
        CP_COMMIT();
    };

    const int NCH = K / 16;
    issue(0, 0);
    issue(1, 16);
    for (int ch = 0; ch < NCH; ch++) {
        CP_WAIT(1);
        __syncthreads();
        if (ch + 2 < NCH) issue((ch + 2) % 3, (ch + 2) * 16);

        const float* As = Asm + (ch % 3) * ASTRIDE;
        const float* Bs = Bsm + (ch % 3) * BSTRIDE;
#pragma unroll
        for (int ks = 0; ks < 16; ks += 8) {
            uint32_t af[2][4];
#pragma unroll
            for (int mt = 0; mt < 2; mt++) {
                int r0 = wm * 32 + mt * 16 + gID;
                int kc = ks + tIG;
                af[mt][0] = __float_as_uint(As[r0 * GAPAD + kc]);
                af[mt][1] = __float_as_uint(As[(r0 + 8) * GAPAD + kc]);
                af[mt][2] = __float_as_uint(As[r0 * GAPAD + kc + 4]);
                af[mt][3] = __float_as_uint(As[(r0 + 8) * GAPAD + kc + 4]);
            }
#pragma unroll
            for (int nt = 0; nt < 8; nt++) {
                int col = wn * 64 + nt * 8 + gID;
                uint32_t b0 = __float_as_uint(Bs[(ks + tIG) * GBPAD + col]);
                uint32_t b1 = __float_as_uint(Bs[(ks + tIG + 4) * GBPAD + col]);
#pragma unroll
                for (int mt = 0; mt < 2; mt++) {
                    asm volatile(
                        "mma.sync.aligned.m16n8k8.row.col.f32.tf32.tf32.f32 "
                        "{%0,%1,%2,%3}, {%4,%5,%6,%7}, {%8,%9}, {%0,%1,%2,%3};\n"
                        : "+f"(acc[mt][nt][0]), "+f"(acc[mt][nt][1]),
                          "+f"(acc[mt][nt][2]), "+f"(acc[mt][nt][3])
                        : "r"(af[mt][0]), "r"(af[mt][1]), "r"(af[mt][2]), "r"(af[mt][3]),
                          "r"(b0), "r"(b1));
                }
            }
        }
    }

#pragma unroll
    for (int mt = 0; mt < 2; mt++) {
        int r0 = rowBase + wm * 32 + mt * 16 + gID;
#pragma unroll
        for (int nt = 0; nt < 8; nt++) {
            int c0 = colBase + wn * 64 + nt * 8 + tIG * 2;
            if (r0 < M)
                *(float2*)&C[(size_t)r0 * Nn + c0] = make_float2(acc[mt][nt][0], acc[mt][nt][1]);
            if (r0 + 8 < M)
                *(float2*)&C[(size_t)(r0 + 8) * Nn + c0] = make_float2(acc[mt][nt][2], acc[mt][nt][3]);
        }
    }
}

// ----------------------------- GAT: one warp per node (fp16 gather) ----------
__global__ __launch_bounds__(256)
void k_gat(const int* __restrict__ rowptr, const int* __restrict__ csrc,
           const __half* __restrict__ xlh,
           const float* __restrict__ asrc, const float* __restrict__ adst,
           const float* __restrict__ bias, float* __restrict__ x1, int N) {
    int w = (blockIdx.x * blockDim.x + threadIdx.x) >> 5;
    int lane = threadIdx.x & 31;
    if (w >= N) return;
    const int row = rowptr[w];
    const int end = rowptr[w + 1];

    const int h = lane % H;
    const int c = lane / H;
    const float adst_h = (lane < 30) ? adst[w * H + h] : 0.f;

    float m = -FLT_MAX, den = 0.f;
    if (lane < 30) {
        for (int i = row + c; i < end; i += 3) {
            int s = csrc[i];
            float a = asrc[s * H + h] + adst_h;
            a = a > 0.f ? a : 0.2f * a;
            float nm = fmaxf(m, a);
            den = den * __expf(m - nm) + __expf(a - nm);
            m = nm;
        }
    }
    {
        float mA = __shfl_sync(0xffffffffu, m,   lane + 10);
        float dA = __shfl_sync(0xffffffffu, den, lane + 10);
        float mB = __shfl_sync(0xffffffffu, m,   lane + 20);
        float dB = __shfl_sync(0xffffffffu, den, lane + 20);
        float M2 = fmaxf(m, fmaxf(mA, mB));
        den = den * __expf(m - M2) + dA * __expf(mA - M2) + dB * __expf(mB - M2);
        m = M2;
    }
    const float invden = 1.0f / (den + 1e-16f);

    // aggregation: each uint2 = 4 halfs = features [4*idx, 4*idx+3]; head = idx/16
    float4 acc4[5];
#pragma unroll
    for (int j = 0; j < 5; j++) acc4[j] = make_float4(0.f, 0.f, 0.f, 0.f);

    const int hsel = lane >> 4;
    int i = row;
    for (; i + 1 < end; i += 2) {
        int s0 = csrc[i];
        int s1 = csrc[i + 1];
        float wv0 = 0.f, wv1 = 0.f;
        if (lane < H) {
            float a0 = asrc[s0 * H + lane] + adst_h;
            float a1 = asrc[s1 * H + lane] + adst_h;
            a0 = a0 > 0.f ? a0 : 0.2f * a0;
            a1 = a1 > 0.f ? a1 : 0.2f * a1;
            wv0 = __expf(a0 - m) * invden;
            wv1 = __expf(a1 - m) * invden;
        }
        const uint2* xs0 = (const uint2*)(xlh + (size_t)s0 * HD);
        const uint2* xs1 = (const uint2*)(xlh + (size_t)s1 * HD);
        uint2 u0[5], u1[5];
#pragma unroll
        for (int j = 0; j < 5; j++) { u0[j] = xs0[lane + 32 * j]; u1[j] = xs1[lane + 32 * j]; }
#pragma unroll
        for (int j = 0; j < 5; j++) {
            float w0 = __shfl_sync(0xffffffffu, wv0, 2 * j + hsel);
            float w1 = __shfl_sync(0xffffffffu, wv1, 2 * j + hsel);
            float2 a0 = __half22float2(*(const __half2*)&u0[j].x);
            float2 b0 = __half22float2(*(const __half2*)&u0[j].y);
            float2 a1 = __half22float2(*(const __half2*)&u1[j].x);
            float2 b1 = __half22float2(*(const __half2*)&u1[j].y);
            acc4[j].x += a0.x * w0 + a1.x * w1;
            acc4[j].y += a0.y * w0 + a1.y * w1;
            acc4[j].z += b0.x * w0 + b1.x * w1;
            acc4[j].w += b0.y * w0 + b1.y * w1;
        }
    }
    if (i < end) {
        int s = csrc[i];
        float wv = 0.f;
        if (lane < H) {
            float a = asrc[s * H + lane] + adst_h;
            a = a > 0.f ? a : 0.2f * a;
            wv = __expf(a - m) * invden;
        }
        const uint2* xs = (const uint2*)(xlh + (size_t)s * HD);
#pragma unroll
        for (int j = 0; j < 5; j++) {
            float wj = __shfl_sync(0xffffffffu, wv, 2 * j + hsel);
            uint2 u = xs[lane + 32 * j];
            float2 a0 = __half22float2(*(const __half2*)&u.x);
            float2 b0 = __half22float2(*(const __half2*)&u.y);
            acc4[j].x += a0.x * wj;
            acc4[j].y += a0.y * wj;
            acc4[j].z += b0.x * wj;
            acc4[j].w += b0.y * wj;
        }
    }

    float4* xo4 = (float4*)(x1 + (size_t)w * HD);
    const float4* b4 = (const float4*)bias;
#pragma unroll
    for (int j = 0; j < 5; j++) {
        int idx = lane + 32 * j;
        float4 bb = b4[idx];
        float4 v = acc4[j];
        v.x = rnd_tf32(fmaxf(v.x + bb.x, 0.f));
        v.y = rnd_tf32(fmaxf(v.y + bb.y, 0.f));
        v.z = rnd_tf32(fmaxf(v.z + bb.z, 0.f));
        v.w = rnd_tf32(fmaxf(v.w + bb.w, 0.f));
        xo4[idx] = v;
    }
}

// ----------------------------- GCN + fused global pooling --------------------
__global__ __launch_bounds__(256)
void k_gcn_pool(const int* __restrict__ rowptr, const int* __restrict__ csrc,
                const int* __restrict__ cnt, const float* __restrict__ xw,
                const float* __restrict__ bias,
                float* __restrict__ pmax, float* __restrict__ psum, int N) {
    __shared__ float smax[HD];
    __shared__ float ssum[HD];
    const int tid = threadIdx.x;
    for (int i = tid; i < HD; i += 256) { smax[i] = 0.f; ssum[i] = 0.f; }
    __syncthreads();

    const int w = (blockIdx.x * blockDim.x + tid) >> 5;
    const int lane = tid & 31;

    if (w < N) {
        const int row = rowptr[w];
        const int end = rowptr[w + 1];
        const float dn = rsqrtf((float)(end - row));

        float4 acc4[5];
#pragma unroll
        for (int j = 0; j < 5; j++) acc4[j] = make_float4(0.f, 0.f, 0.f, 0.f);

        int i = row;
        for (; i + 1 < end; i += 2) {
            int s0 = csrc[i];
            int s1 = csrc[i + 1];
            float n0 = dn * rsqrtf((float)cnt[s0]);
            float n1 = dn * rsqrtf((float)cnt[s1]);
            const float4* xs0 = (const float4*)(xw + (size_t)s0 * HD);
            const float4* xs1 = (const float4*)(xw + (size_t)s1 * HD);
            float4 v0[5], v1[5];
#pragma unroll
            for (int j = 0; j < 5; j++) { v0[j] = xs0[lane + 32 * j]; v1[j] = xs1[lane + 32 * j]; }
#pragma unroll
            for (int j = 0; j < 5; j++) {
                acc4[j].x += v0[j].x * n0 + v1[j].x * n1;
                acc4[j].y += v0[j].y * n0 + v1[j].y * n1;
                acc4[j].z += v0[j].z * n0 + v1[j].z * n1;
                acc4[j].w += v0[j].w * n0 + v1[j].w * n1;
            }
        }
        if (i < end) {
            int s = csrc[i];
            float nrm = dn * rsqrtf((float)cnt[s]);
            const float4* xs4 = (const float4*)(xw + (size_t)s * HD);
#pragma unroll
            for (int j = 0; j < 5; j++) {
                float4 v = xs4[lane + 32 * j];
                acc4[j].x += v.x * nrm;
                acc4[j].y += v.y * nrm;
                acc4[j].z += v.z * nrm;
                acc4[j].w += v.w * nrm;
            }
        }

        const float4* b4 = (const float4*)bias;
#pragma unroll
        for (int j = 0; j < 5; j++) {
            int idx = lane + 32 * j;
            float4 bb = b4[idx];
            float4 v = acc4[j];
            v.x = fmaxf(v.x + bb.x, 0.f);
            v.y = fmaxf(v.y + bb.y, 0.f);
            v.z = fmaxf(v.z + bb.z, 0.f);
            v.w = fmaxf(v.w + bb.w, 0.f);
            int col = idx * 4;
            atomicMax((int*)&smax[col + 0], __float_as_int(v.x));
            atomicMax((int*)&smax[col + 1], __float_as_int(v.y));
            atomicMax((int*)&smax[col + 2], __float_as_int(v.z));
            atomicMax((int*)&smax[col + 3], __float_as_int(v.w));
            atomicAdd(&ssum[col + 0], v.x);
            atomicAdd(&ssum[col + 1], v.y);
            atomicAdd(&ssum[col + 2], v.z);
            atomicAdd(&ssum[col + 3], v.w);
        }
    }
    __syncthreads();

    for (int i = tid; i < HD; i += 256) {
        atomicMax((int*)&pmax[i], __float_as_int(smax[i]));
        atomicAdd(&psum[i], ssum[i]);
    }
}

// ----------------------------- MLP (k-split parallel) ------------------------
#define MLP_KSPLIT 10
#define MLP_JBLK   6
__global__ void k_mlp1(const float* __restrict__ pmax, const float* __restrict__ psum,
                       const float* __restrict__ W1, float* __restrict__ h1, int N) {
    const int jb = blockIdx.x % MLP_JBLK;
    const int s  = blockIdx.x / MLP_JBLK;
    const int j = jb * 256 + threadIdx.x;
    if (j >= H1DIM) return;
    const float invN = 1.0f / (float)N;
    const int k0 = s * (2 * HD / MLP_KSPLIT);
    float acc = 0.f;
#pragma unroll 4
    for (int k = k0; k < k0 + 2 * HD / MLP_KSPLIT; k++) {
        float v = (k < HD) ? pmax[k] : psum[k - HD] * invN;
        acc += v * W1[(size_t)k * H1DIM + j];
    }
    atomicAdd(&h1[j], acc);
}

__global__ void k_mlp2(const float* __restrict__ h1, const float* __restrict__ W2,
                       const float* __restrict__ b2, float* __restrict__ out) {
    __shared__ float acc[10];
    int tid = threadIdx.x;
    if (tid < 10) acc[tid] = 0.0f;
    __syncthreads();
    float part[10];
#pragma unroll
    for (int j = 0; j < 10; j++) part[j] = 0.0f;
    for (int k = tid; k < H1DIM; k += 256) {
        float hv = fmaxf(h1[k], 0.0f);
#pragma unroll
        for (int j = 0; j < 10; j++) part[j] += hv * W2[k * 10 + j];
    }
#pragma unroll
    for (int j = 0; j < 10; j++) atomicAdd(&acc[j], part[j]);
    __syncthreads();
    if (tid < 10) out[tid] = acc[tid] + b2[tid];
}

// ----------------------------- launch -----------------------------------------
static inline int cdiv(int a, int b) { return (a + b - 1) / b; }

extern "C" void kernel_launch(void* const* d_in, const int* in_sizes, int n_in,
                              void* d_out, int out_size) {
    const float* x       = (const float*)d_in[0];
    const float* W_gat   = (const float*)d_in[1];
    const float* att_src = (const float*)d_in[2];
    const float* att_dst = (const float*)d_in[3];
    const float* b_gat   = (const float*)d_in[4];
    const float* W_gcn   = (const float*)d_in[5];
    const float* b_gcn   = (const float*)d_in[6];
    const float* W1      = (const float*)d_in[7];
    const float* b1      = (const float*)d_in[8];
    const float* W2      = (const float*)d_in[9];
    const float* b2      = (const float*)d_in[10];
    const int*   ei      = (const int*)d_in[11];

    const int N  = in_sizes[0] / D;
    const int E  = in_sizes[11] / 2;
    const int EP = E + N;
    float* out = (float*)d_out;

    __half* p_xlh;
    float *p_x1, *p_xw, *p_wt, *p_asrc, *p_adst, *p_pmax, *p_psum, *p_h1;
    int *p_cnt, *p_rowptr, *p_cursor, *p_csrc;
    cudaGetSymbolAddress((void**)&p_xlh,    g_xlh);
    cudaGetSymbolAddress((void**)&p_x1,     g_x1);
    cudaGetSymbolAddress((void**)&p_xw,     g_xw);
    cudaGetSymbolAddress((void**)&p_wt,     g_wt);
    cudaGetSymbolAddress((void**)&p_asrc,   g_asrc);
    cudaGetSymbolAddress((void**)&p_adst,   g_adst);
    cudaGetSymbolAddress((void**)&p_pmax,   g_pmax);
    cudaGetSymbolAddress((void**)&p_psum,   g_psum);
    cudaGetSymbolAddress((void**)&p_h1,     g_h1);
    cudaGetSymbolAddress((void**)&p_cnt,    g_cnt);
    cudaGetSymbolAddress((void**)&p_rowptr, g_rowptr);
    cudaGetSymbolAddress((void**)&p_cursor, g_cursor);
    cudaGetSymbolAddress((void**)&p_csrc,   g_csrc);

    // side stream + events for GEMM1 || CSR overlap (leaked by design; capture-safe)
    cudaStream_t s2;
    cudaStreamCreate(&s2);
    cudaEvent_t evF, evJ;
    cudaEventCreateWithFlags(&evF, cudaEventDisableTiming);
    cudaEventCreateWithFlags(&evJ, cudaEventDisableTiming);

    // fork: GEMM1 (fp16 output + att scores) on s2
    cudaEventRecord(evF, 0);
    cudaStreamWaitEvent(s2, evF, 0);
    k_gemm1_h<<<cdiv(N, 128) * (HD / 128), 256, 0, s2>>>(
        x, W_gat, p_xlh, N, HD, D, att_src, att_dst, p_asrc, p_adst);
    cudaEventRecord(evJ, s2);

    // main stream: setup + CSR build
    const int setupN = N + 2 * HD + H1DIM + HD * HD;
    k_setup<<<cdiv(setupN, 256), 256>>>(p_cnt, p_pmax, p_psum, p_h1, b1, W_gcn, p_wt, N);
    k_count<<<cdiv(EP, 256), 256>>>(ei, p_cnt, E, N);
    k_scan<<<1, 1024>>>(p_cnt, p_rowptr, p_cursor, N, EP);
    k_scatter<<<cdiv(EP, 256), 256>>>(ei, p_cursor, p_csrc, E, N);

    // join: k_gat needs both CSR and GEMM1 outputs
    cudaStreamWaitEvent(0, evJ, 0);
    k_gat<<<cdiv(N * 32, 256), 256>>>(p_rowptr, p_csrc, p_xlh, p_asrc, p_adst,
                                      b_gat, p_x1, N);
    // GEMM2 (mma.sync tf32, 3-stage cp.async)
    cudaFuncSetAttribute(k_gemm2_cp, cudaFuncAttributeMaxDynamicSharedMemorySize, G2_SMEM);
    k_gemm2_cp<<<cdiv(N, 128) * (HD / 128), 256, G2_SMEM>>>(p_x1, p_wt, p_xw, N, HD, HD);
    // GCN aggregation + fused global pooling
    k_gcn_pool<<<cdiv(N * 32, 256), 256>>>(p_rowptr, p_csrc, p_cnt, p_xw, b_gcn,
                                           p_pmax, p_psum, N);
    // MLP head
    k_mlp1<<<MLP_JBLK * MLP_KSPLIT, 256>>>(p_pmax, p_psum, W1, p_h1, N);
    k_mlp2<<<1, 256>>>(p_h1, W2, b2, out);
}

// round 14
// speedup vs baseline: 1.5532x; 1.0438x over previous
#include <cuda_runtime.h>
#include <cuda_fp16.h>
#include <float.h>
#include <stdint.h>

// Problem constants (fixed by the dataset)
#define MAXN 20000
#define MAXE 320000
#define MAXEP (MAXE + MAXN)
#define D  64
#define H  10
#define HD 640
#define H1DIM 1500

// ----------------------------- scratch (static, allocation-free) ------------
__device__ __align__(16) __half g_xlh[(size_t)MAXN * HD];  // GAT features, fp16
__device__ __align__(16) float g_x1  [(size_t)MAXN * HD];
__device__ __align__(16) __half g_xwh[(size_t)MAXN * HD];  // GCN pre-agg feats, fp16
__device__ __align__(16) float g_wt  [(size_t)HD * HD];    // W_gcn pre-rounded to tf32
__device__ __align__(16) float g_asrc[(size_t)MAXN * H];
__device__ __align__(16) float g_adst[(size_t)MAXN * H];
__device__ __align__(16) float g_pmax[HD];
__device__ __align__(16) float g_psum[HD];
__device__ __align__(16) float g_h1  [H1DIM];
__device__ __align__(16) int g_cnt   [MAXN];
__device__ __align__(16) int g_rowptr[MAXN + 1];
__device__ __align__(16) int g_cursor[MAXN];
__device__ __align__(16) int g_csrc  [MAXEP];

__device__ __forceinline__ uint32_t f2tf32(float x) {
    uint32_t r;
    asm("cvt.rna.tf32.f32 %0, %1;" : "=r"(r) : "f"(x));
    return r;
}
__device__ __forceinline__ float rnd_tf32(float x) {
    return __uint_as_float(f2tf32(x));
}
__device__ __forceinline__ uint32_t smem_u32(const void* p) {
    uint32_t a;
    asm("{ .reg .u64 t; cvta.to.shared.u64 t, %1; cvt.u32.u64 %0, t; }" : "=r"(a) : "l"(p));
    return a;
}
#define CP_ASYNC16(dst, src, sz) \
    asm volatile("cp.async.cg.shared.global [%0], [%1], 16, %2;" \
                 :: "r"(dst), "l"(src), "r"(sz) : "memory")
#define CP_COMMIT() asm volatile("cp.async.commit_group;" ::: "memory")
#define CP_WAIT(n)  asm volatile("cp.async.wait_group %0;" :: "n"(n) : "memory")

// ----------------------------- setup (init + W preround, one launch) ---------
__global__ void k_setup(int* __restrict__ cnt, float* __restrict__ pmax,
                        float* __restrict__ psum, float* __restrict__ h1,
                        const float* __restrict__ b1,
                        const float* __restrict__ w, float* __restrict__ wt, int N) {
    int i = blockIdx.x * blockDim.x + threadIdx.x;
    if (i < N) { cnt[i] = 0; return; }
    i -= N;
    if (i < HD) { pmax[i] = 0.f; return; }
    i -= HD;
    if (i < HD) { psum[i] = 0.f; return; }
    i -= HD;
    if (i < H1DIM) { h1[i] = b1[i]; return; }
    i -= H1DIM;
    if (i < HD * HD) wt[i] = rnd_tf32(w[i]);
}

// ----------------------------- CSR build -------------------------------------
__global__ void k_count(const int* __restrict__ ei, int* __restrict__ cnt, int E, int N) {
    int e = blockIdx.x * blockDim.x + threadIdx.x;
    int EP = E + N;
    if (e >= EP) return;
    int dst = (e < E) ? ei[E + e] : (e - E);
    atomicAdd(&cnt[dst], 1);
}

__global__ __launch_bounds__(1024)
void k_scan(const int* __restrict__ cnt, int* __restrict__ rowptr,
            int* __restrict__ cursor, int N, int EP) {
    __shared__ int sums[1024];
    const int t = threadIdx.x;
    const int per = (N + 1023) >> 10;
    const int start = t * per;
    int vals[20];
    int cn = 0;
    const bool vec = (per % 4 == 0) && (start + per <= N);
    if (vec) {
#pragma unroll
        for (int q = 0; q < 5; q++) {
            if (q * 4 < per) {
                int4 v = *(const int4*)&cnt[start + q * 4];
                vals[q * 4 + 0] = v.x; vals[q * 4 + 1] = v.y;
                vals[q * 4 + 2] = v.z; vals[q * 4 + 3] = v.w;
            }
        }
        cn = per;
    } else if (start < N) {
        cn = min(per, N - start);
        for (int q = 0; q < cn; q++) vals[q] = cnt[start + q];
    }
    int s = 0;
    for (int q = 0; q < cn; q++) s += vals[q];
    sums[t] = s;
    __syncthreads();
    for (int off = 1; off < 1024; off <<= 1) {
        int o = (t >= off) ? sums[t - off] : 0;
        __syncthreads();
        sums[t] += o;
        __syncthreads();
    }
    int run = sums[t] - s;
    for (int q = 0; q < cn; q++) {
        int tmp = vals[q];
        vals[q] = run;
        run += tmp;
    }
    if (vec) {
#pragma unroll
        for (int q = 0; q < 5; q++) {
            if (q * 4 < per) {
                int4 v = make_int4(vals[q * 4 + 0], vals[q * 4 + 1],
                                   vals[q * 4 + 2], vals[q * 4 + 3]);
                *(int4*)&rowptr[start + q * 4] = v;
                *(int4*)&cursor[start + q * 4] = v;
            }
        }
    } else {
        for (int q = 0; q < cn; q++) {
            rowptr[start + q] = vals[q];
            cursor[start + q] = vals[q];
        }
    }
    if (t == 0) rowptr[N] = EP;
}

__global__ void k_scatter(const int* __restrict__ ei, int* __restrict__ cursor,
                          int* __restrict__ csrc, int E, int N) {
    int e = blockIdx.x * blockDim.x + threadIdx.x;
    int EP = E + N;
    if (e >= EP) return;
    int src, dst;
    if (e < E) { src = ei[e]; dst = ei[E + e]; }
    else       { src = dst = e - E; }
    int pos = atomicAdd(&cursor[dst], 1);
    csrc[pos] = src;
}

// ----------------------------- tf32 mma.sync GEMM1 (half output + att) -------
#define GAPAD 20
#define GBPAD 136
__global__ __launch_bounds__(256)
void k_gemm1_h(const float* __restrict__ A, const float* __restrict__ B,
               __half* __restrict__ Ch, int M, int Nn, int K,
               const float* __restrict__ att_src, const float* __restrict__ att_dst,
               float* __restrict__ asrc, float* __restrict__ adst) {
    __shared__ float As[2][128][GAPAD];
    __shared__ float Bs[2][16][GBPAD];
    const int tid = threadIdx.x;
    const int warp = tid >> 5, lane = tid & 31;
    const int wm = warp & 3, wn = warp >> 2;
    const int nTilesX = Nn / 128;
    const int bx = blockIdx.x % nTilesX;
    const int by = blockIdx.x / nTilesX;
    const int rowBase = by * 128, colBase = bx * 128;

    const int gID = lane >> 2;
    const int tIG = lane & 3;

    float acc[2][8][4];
#pragma unroll
    for (int mt = 0; mt < 2; mt++)
#pragma unroll
        for (int nt = 0; nt < 8; nt++)
#pragma unroll
            for (int r = 0; r < 4; r++) acc[mt][nt][r] = 0.0f;

    const int aR  = tid >> 2;
    const int aC4 = (tid & 3) * 4;
    const int bR  = tid >> 5;
    const int bC4 = lane * 4;

    float4 avr[2], bvr[2];
#pragma unroll
    for (int half_ = 0; half_ < 2; half_++) {
        int gr = rowBase + aR + half_ * 64;
        avr[half_] = (gr < M) ? *(const float4*)&A[(size_t)gr * K + aC4]
                              : make_float4(0.f, 0.f, 0.f, 0.f);
        bvr[half_] = *(const float4*)&B[(size_t)(bR + half_ * 8) * Nn + colBase + bC4];
    }

    int buf = 0;
    for (int k0 = 0; k0 < K; k0 += 16) {
#pragma unroll
        for (int half_ = 0; half_ < 2; half_++) {
            int r = aR + half_ * 64;
            As[buf][r][aC4 + 0] = rnd_tf32(avr[half_].x);
            As[buf][r][aC4 + 1] = rnd_tf32(avr[half_].y);
            As[buf][r][aC4 + 2] = rnd_tf32(avr[half_].z);
            As[buf][r][aC4 + 3] = rnd_tf32(avr[half_].w);
            int rb = bR + half_ * 8;
            Bs[buf][rb][bC4 + 0] = rnd_tf32(bvr[half_].x);
            Bs[buf][rb][bC4 + 1] = rnd_tf32(bvr[half_].y);
            Bs[buf][rb][bC4 + 2] = rnd_tf32(bvr[half_].z);
            Bs[buf][rb][bC4 + 3] = rnd_tf32(bvr[half_].w);
        }
        __syncthreads();

        if (k0 + 16 < K) {
#pragma unroll
            for (int half_ = 0; half_ < 2; half_++) {
                int gr = rowBase + aR + half_ * 64;
                avr[half_] = (gr < M) ? *(const float4*)&A[(size_t)gr * K + k0 + 16 + aC4]
                                      : make_float4(0.f, 0.f, 0.f, 0.f);
                bvr[half_] = *(const float4*)&B[(size_t)(k0 + 16 + bR + half_ * 8) * Nn + colBase + bC4];
            }
        }

#pragma unroll
        for (int ks = 0; ks < 16; ks += 8) {
            uint32_t af[2][4];
#pragma unroll
            for (int mt = 0; mt < 2; mt++) {
                int r0 = wm * 32 + mt * 16 + gID;
                int kc = ks + tIG;
                af[mt][0] = __float_as_uint(As[buf][r0][kc]);
                af[mt][1] = __float_as_uint(As[buf][r0 + 8][kc]);
                af[mt][2] = __float_as_uint(As[buf][r0][kc + 4]);
                af[mt][3] = __float_as_uint(As[buf][r0 + 8][kc + 4]);
            }
#pragma unroll
            for (int nt = 0; nt < 8; nt++) {
                int col = wn * 64 + nt * 8 + gID;
                uint32_t b0 = __float_as_uint(Bs[buf][ks + tIG][col]);
                uint32_t b1 = __float_as_uint(Bs[buf][ks + tIG + 4][col]);
#pragma unroll
                for (int mt = 0; mt < 2; mt++) {
                    asm volatile(
                        "mma.sync.aligned.m16n8k8.row.col.f32.tf32.tf32.f32 "
                        "{%0,%1,%2,%3}, {%4,%5,%6,%7}, {%8,%9}, {%0,%1,%2,%3};\n"
                        : "+f"(acc[mt][nt][0]), "+f"(acc[mt][nt][1]),
                          "+f"(acc[mt][nt][2]), "+f"(acc[mt][nt][3])
                        : "r"(af[mt][0]), "r"(af[mt][1]), "r"(af[mt][2]), "r"(af[mt][3]),
                          "r"(b0), "r"(b1));
                }
            }
        }
        __syncthreads();
        buf ^= 1;
    }

    // write C as fp16
#pragma unroll
    for (int mt = 0; mt < 2; mt++) {
        int r0 = rowBase + wm * 32 + mt * 16 + gID;
#pragma unroll
        for (int nt = 0; nt < 8; nt++) {
            int c0 = colBase + wn * 64 + nt * 8 + tIG * 2;
            if (r0 < M)
                *(__half2*)&Ch[(size_t)r0 * Nn + c0] =
                    __floats2half2_rn(acc[mt][nt][0], acc[mt][nt][1]);
            if (r0 + 8 < M)
                *(__half2*)&Ch[(size_t)(r0 + 8) * Nn + c0] =
                    __floats2half2_rn(acc[mt][nt][2], acc[mt][nt][3]);
        }
    }

    // attention epilogue from exact fp32 accumulators
    {
        const int h = bx * 2 + wn;
        float as[16], ad[16];
#pragma unroll
        for (int nt = 0; nt < 8; nt++)
#pragma unroll
            for (int p = 0; p < 2; p++) {
                int cih = nt * 8 + tIG * 2 + p;
                as[nt * 2 + p] = att_src[h * D + cih];
                ad[nt * 2 + p] = att_dst[h * D + cih];
            }
#pragma unroll
        for (int mt = 0; mt < 2; mt++) {
#pragma unroll
            for (int pair = 0; pair < 2; pair++) {
                float ps = 0.f, pd = 0.f;
#pragma unroll
                for (int nt = 0; nt < 8; nt++)
#pragma unroll
                    for (int p = 0; p < 2; p++) {
                        float v = acc[mt][nt][pair * 2 + p];
                        ps += v * as[nt * 2 + p];
                        pd += v * ad[nt * 2 + p];
                    }
                ps += __shfl_down_sync(0xffffffffu, ps, 2, 4);
                ps += __shfl_down_sync(0xffffffffu, ps, 1, 4);
                pd += __shfl_down_sync(0xffffffffu, pd, 2, 4);
                pd += __shfl_down_sync(0xffffffffu, pd, 1, 4);
                int gr = rowBase + wm * 32 + mt * 16 + gID + pair * 8;
                if (tIG == 0 && gr < M) {
                    asrc[gr * H + h] = ps;
                    adst[gr * H + h] = pd;
                }
            }
        }
    }
}

// ----------------------------- GEMM2: mma.sync tf32, cp.async, half out ------
#define ASTRIDE (128 * GAPAD)
#define BSTRIDE (16 * GBPAD)
#define G2_SMEM ((3 * ASTRIDE + 3 * BSTRIDE) * (int)sizeof(float))
__global__ __launch_bounds__(256)
void k_gemm2_cp(const float* __restrict__ A, const float* __restrict__ B,
                __half* __restrict__ Ch, int M, int Nn, int K) {
    extern __shared__ __align__(16) float dsm[];
    float* Asm = dsm;
    float* Bsm = dsm + 3 * ASTRIDE;

    const int tid = threadIdx.x;
    const int warp = tid >> 5, lane = tid & 31;
    const int wm = warp & 3, wn = warp >> 2;
    const int nTilesX = Nn / 128;
    const int bx = blockIdx.x % nTilesX;
    const int by = blockIdx.x / nTilesX;
    const int rowBase = by * 128, colBase = bx * 128;

    const int gID = lane >> 2;
    const int tIG = lane & 3;

    float acc[2][8][4];
#pragma unroll
    for (int mt = 0; mt < 2; mt++)
#pragma unroll
        for (int nt = 0; nt < 8; nt++)
#pragma unroll
            for (int r = 0; r < 4; r++) acc[mt][nt][r] = 0.0f;

    const int aR  = tid >> 2;
    const int aC4 = (tid & 3) * 4;
    const int bR  = tid >> 5;
    const int bC4 = lane * 4;

    auto issue = [&](int st, int k0) {
        float* As = Asm + st * ASTRIDE;
        float* Bs = Bsm + st * BSTRIDE;
#pragma unroll
        for (int half_ = 0; half_ < 2; half_++) {
            int r = aR + half_ * 64;
            int gr = rowBase + r;
            uint32_t da = smem_u32(&As[r * GAPAD + aC4]);
            const float* sa = &A[(size_t)gr * K + k0 + aC4];
            int sz = (gr < M) ? 16 : 0;
            CP_ASYNC16(da, sa, sz);
            int rb = bR + half_ * 8;
            uint32_t db = smem_u32(&Bs[rb * GBPAD + bC4]);
            const float* sb = &B[(size_t)(k0 + rb) * Nn + colBase + bC4];
            CP_ASYNC16(db, sb, 16);
        }
        CP_COMMIT();
    };

    const int NCH = K / 16;
    issue(0, 0);
    issue(1, 16);
    for (int ch = 0; ch < NCH; ch++) {
        CP_WAIT(1);
        __syncthreads();
        if (ch + 2 < NCH) issue((ch + 2) % 3, (ch + 2) * 16);

        const float* As = Asm + (ch % 3) * ASTRIDE;
        const float* Bs = Bsm + (ch % 3) * BSTRIDE;
#pragma unroll
        for (int ks = 0; ks < 16; ks += 8) {
            uint32_t af[2][4];
#pragma unroll
            for (int mt = 0; mt < 2; mt++) {
                int r0 = wm * 32 + mt * 16 + gID;
                int kc = ks + tIG;
                af[mt][0] = __float_as_uint(As[r0 * GAPAD + kc]);
                af[mt][1] = __float_as_uint(As[(r0 + 8) * GAPAD + kc]);
                af[mt][2] = __float_as_uint(As[r0 * GAPAD + kc + 4]);
                af[mt][3] = __float_as_uint(As[(r0 + 8) * GAPAD + kc + 4]);
            }
#pragma unroll
            for (int nt = 0; nt < 8; nt++) {
                int col = wn * 64 + nt * 8 + gID;
                uint32_t b0 = __float_as_uint(Bs[(ks + tIG) * GBPAD + col]);
                uint32_t b1 = __float_as_uint(Bs[(ks + tIG + 4) * GBPAD + col]);
#pragma unroll
                for (int mt = 0; mt < 2; mt++) {
                    asm volatile(
                        "mma.sync.aligned.m16n8k8.row.col.f32.tf32.tf32.f32 "
                        "{%0,%1,%2,%3}, {%4,%5,%6,%7}, {%8,%9}, {%0,%1,%2,%3};\n"
                        : "+f"(acc[mt][nt][0]), "+f"(acc[mt][nt][1]),
                          "+f"(acc[mt][nt][2]), "+f"(acc[mt][nt][3])
                        : "r"(af[mt][0]), "r"(af[mt][1]), "r"(af[mt][2]), "r"(af[mt][3]),
                          "r"(b0), "r"(b1));
                }
            }
        }
    }

#pragma unroll
    for (int mt = 0; mt < 2; mt++) {
        int r0 = rowBase + wm * 32 + mt * 16 + gID;
#pragma unroll
        for (int nt = 0; nt < 8; nt++) {
            int c0 = colBase + wn * 64 + nt * 8 + tIG * 2;
            if (r0 < M)
                *(__half2*)&Ch[(size_t)r0 * Nn + c0] =
                    __floats2half2_rn(acc[mt][nt][0], acc[mt][nt][1]);
            if (r0 + 8 < M)
                *(__half2*)&Ch[(size_t)(r0 + 8) * Nn + c0] =
                    __floats2half2_rn(acc[mt][nt][2], acc[mt][nt][3]);
        }
    }
}

// ----------------------------- GAT: one warp per node (fp16 gather) ----------
__global__ __launch_bounds__(256)
void k_gat(const int* __restrict__ rowptr, const int* __restrict__ csrc,
           const __half* __restrict__ xlh,
           const float* __restrict__ asrc, const float* __restrict__ adst,
           const float* __restrict__ bias, float* __restrict__ x1, int N) {
    int w = (blockIdx.x * blockDim.x + threadIdx.x) >> 5;
    int lane = threadIdx.x & 31;
    if (w >= N) return;
    const int row = rowptr[w];
    const int end = rowptr[w + 1];

    const int h = lane % H;
    const int c = lane / H;
    const float adst_h = (lane < 30) ? adst[w * H + h] : 0.f;

    float m = -FLT_MAX, den = 0.f;
    if (lane < 30) {
        for (int i = row + c; i < end; i += 3) {
            int s = csrc[i];
            float a = asrc[s * H + h] + adst_h;
            a = a > 0.f ? a : 0.2f * a;
            float nm = fmaxf(m, a);
            den = den * __expf(m - nm) + __expf(a - nm);
            m = nm;
        }
    }
    {
        float mA = __shfl_sync(0xffffffffu, m,   lane + 10);
        float dA = __shfl_sync(0xffffffffu, den, lane + 10);
        float mB = __shfl_sync(0xffffffffu, m,   lane + 20);
        float dB = __shfl_sync(0xffffffffu, den, lane + 20);
        float M2 = fmaxf(m, fmaxf(mA, mB));
        den = den * __expf(m - M2) + dA * __expf(mA - M2) + dB * __expf(mB - M2);
        m = M2;
    }
    const float invden = 1.0f / (den + 1e-16f);

    float4 acc4[5];
#pragma unroll
    for (int j = 0; j < 5; j++) acc4[j] = make_float4(0.f, 0.f, 0.f, 0.f);

    const int hsel = lane >> 4;
    int i = row;
    for (; i + 1 < end; i += 2) {
        int s0 = csrc[i];
        int s1 = csrc[i + 1];
        float wv0 = 0.f, wv1 = 0.f;
        if (lane < H) {
            float a0 = asrc[s0 * H + lane] + adst_h;
            float a1 = asrc[s1 * H + lane] + adst_h;
            a0 = a0 > 0.f ? a0 : 0.2f * a0;
            a1 = a1 > 0.f ? a1 : 0.2f * a1;
            wv0 = __expf(a0 - m) * invden;
            wv1 = __expf(a1 - m) * invden;
        }
        const uint2* xs0 = (const uint2*)(xlh + (size_t)s0 * HD);
        const uint2* xs1 = (const uint2*)(xlh + (size_t)s1 * HD);
        uint2 u0[5], u1[5];
#pragma unroll
        for (int j = 0; j < 5; j++) { u0[j] = xs0[lane + 32 * j]; u1[j] = xs1[lane + 32 * j]; }
#pragma unroll
        for (int j = 0; j < 5; j++) {
            float w0 = __shfl_sync(0xffffffffu, wv0, 2 * j + hsel);
            float w1 = __shfl_sync(0xffffffffu, wv1, 2 * j + hsel);
            float2 a0 = __half22float2(*(const __half2*)&u0[j].x);
            float2 b0 = __half22float2(*(const __half2*)&u0[j].y);
            float2 a1 = __half22float2(*(const __half2*)&u1[j].x);
            float2 b1 = __half22float2(*(const __half2*)&u1[j].y);
            acc4[j].x += a0.x * w0 + a1.x * w1;
            acc4[j].y += a0.y * w0 + a1.y * w1;
            acc4[j].z += b0.x * w0 + b1.x * w1;
            acc4[j].w += b0.y * w0 + b1.y * w1;
        }
    }
    if (i < end) {
        int s = csrc[i];
        float wv = 0.f;
        if (lane < H) {
            float a = asrc[s * H + lane] + adst_h;
            a = a > 0.f ? a : 0.2f * a;
            wv = __expf(a - m) * invden;
        }
        const uint2* xs = (const uint2*)(xlh + (size_t)s * HD);
#pragma unroll
        for (int j = 0; j < 5; j++) {
            float wj = __shfl_sync(0xffffffffu, wv, 2 * j + hsel);
            uint2 u = xs[lane + 32 * j];
            float2 a0 = __half22float2(*(const __half2*)&u.x);
            float2 b0 = __half22float2(*(const __half2*)&u.y);
            acc4[j].x += a0.x * wj;
            acc4[j].y += a0.y * wj;
            acc4[j].z += b0.x * wj;
            acc4[j].w += b0.y * wj;
        }
    }

    float4* xo4 = (float4*)(x1 + (size_t)w * HD);
    const float4* b4 = (const float4*)bias;
#pragma unroll
    for (int j = 0; j < 5; j++) {
        int idx = lane + 32 * j;
        float4 bb = b4[idx];
        float4 v = acc4[j];
        v.x = rnd_tf32(fmaxf(v.x + bb.x, 0.f));
        v.y = rnd_tf32(fmaxf(v.y + bb.y, 0.f));
        v.z = rnd_tf32(fmaxf(v.z + bb.z, 0.f));
        v.w = rnd_tf32(fmaxf(v.w + bb.w, 0.f));
        xo4[idx] = v;
    }
}

// ----------------------------- GCN + pooling (fp16 gather) -------------------
__global__ __launch_bounds__(256)
void k_gcn_pool(const int* __restrict__ rowptr, const int* __restrict__ csrc,
                const int* __restrict__ cnt, const __half* __restrict__ xwh,
                const float* __restrict__ bias,
                float* __restrict__ pmax, float* __restrict__ psum, int N) {
    __shared__ float smax[HD];
    __shared__ float ssum[HD];
    const int tid = threadIdx.x;
    for (int i = tid; i < HD; i += 256) { smax[i] = 0.f; ssum[i] = 0.f; }
    __syncthreads();

    const int w = (blockIdx.x * blockDim.x + tid) >> 5;
    const int lane = tid & 31;

    if (w < N) {
        const int row = rowptr[w];
        const int end = rowptr[w + 1];
        const float dn = rsqrtf((float)(end - row));

        float4 acc4[5];
#pragma unroll
        for (int j = 0; j < 5; j++) acc4[j] = make_float4(0.f, 0.f, 0.f, 0.f);

        int i = row;
        for (; i + 1 < end; i += 2) {
            int s0 = csrc[i];
            int s1 = csrc[i + 1];
            float n0 = dn * rsqrtf((float)cnt[s0]);
            float n1 = dn * rsqrtf((float)cnt[s1]);
            const uint2* xs0 = (const uint2*)(xwh + (size_t)s0 * HD);
            const uint2* xs1 = (const uint2*)(xwh + (size_t)s1 * HD);
            uint2 u0[5], u1[5];
#pragma unroll
            for (int j = 0; j < 5; j++) { u0[j] = xs0[lane + 32 * j]; u1[j] = xs1[lane + 32 * j]; }
#pragma unroll
            for (int j = 0; j < 5; j++) {
                float2 a0 = __half22float2(*(const __half2*)&u0[j].x);
                float2 b0 = __half22float2(*(const __half2*)&u0[j].y);
                float2 a1 = __half22float2(*(const __half2*)&u1[j].x);
                float2 b1 = __half22float2(*(const __half2*)&u1[j].y);
                acc4[j].x += a0.x * n0 + a1.x * n1;
                acc4[j].y += a0.y * n0 + a1.y * n1;
                acc4[j].z += b0.x * n0 + b1.x * n1;
                acc4[j].w += b0.y * n0 + b1.y * n1;
            }
        }
        if (i < end) {
            int s = csrc[i];
            float nrm = dn * rsqrtf((float)cnt[s]);
            const uint2* xs = (const uint2*)(xwh + (size_t)s * HD);
#pragma unroll
            for (int j = 0; j < 5; j++) {
                uint2 u = xs[lane + 32 * j];
                float2 a0 = __half22float2(*(const __half2*)&u.x);
                float2 b0 = __half22float2(*(const __half2*)&u.y);
                acc4[j].x += a0.x * nrm;
                acc4[j].y += a0.y * nrm;
                acc4[j].z += b0.x * nrm;
                acc4[j].w += b0.y * nrm;
            }
        }

        const float4* b4 = (const float4*)bias;
#pragma unroll
        for (int j = 0; j < 5; j++) {
            int idx = lane + 32 * j;
            float4 bb = b4[idx];
            float4 v = acc4[j];
            v.x = fmaxf(v.x + bb.x, 0.f);
            v.y = fmaxf(v.y + bb.y, 0.f);
            v.z = fmaxf(v.z + bb.z, 0.f);
            v.w = fmaxf(v.w + bb.w, 0.f);
            int col = idx * 4;
            atomicMax((int*)&smax[col + 0], __float_as_int(v.x));
            atomicMax((int*)&smax[col + 1], __float_as_int(v.y));
            atomicMax((int*)&smax[col + 2], __float_as_int(v.z));
            atomicMax((int*)&smax[col + 3], __float_as_int(v.w));
            atomicAdd(&ssum[col + 0], v.x);
            atomicAdd(&ssum[col + 1], v.y);
            atomicAdd(&ssum[col + 2], v.z);
            atomicAdd(&ssum[col + 3], v.w);
        }
    }
    __syncthreads();

    for (int i = tid; i < HD; i += 256) {
        atomicMax((int*)&pmax[i], __float_as_int(smax[i]));
        atomicAdd(&psum[i], ssum[i]);
    }
}

// ----------------------------- MLP (k-split parallel) ------------------------
#define MLP_KSPLIT 10
#define MLP_JBLK   6
__global__ void k_mlp1(const float* __restrict__ pmax, const float* __restrict__ psum,
                       const float* __restrict__ W1, float* __restrict__ h1, int N) {
    const int jb = blockIdx.x % MLP_JBLK;
    const int s  = blockIdx.x / MLP_JBLK;
    const int j = jb * 256 + threadIdx.x;
    if (j >= H1DIM) return;
    const float invN = 1.0f / (float)N;
    const int k0 = s * (2 * HD / MLP_KSPLIT);
    float acc = 0.f;
#pragma unroll 4
    for (int k = k0; k < k0 + 2 * HD / MLP_KSPLIT; k++) {
        float v = (k < HD) ? pmax[k] : psum[k - HD] * invN;
        acc += v * W1[(size_t)k * H1DIM + j];
    }
    atomicAdd(&h1[j], acc);
}

__global__ void k_mlp2(const float* __restrict__ h1, const float* __restrict__ W2,
                       const float* __restrict__ b2, float* __restrict__ out) {
    __shared__ float acc[10];
    int tid = threadIdx.x;
    if (tid < 10) acc[tid] = 0.0f;
    __syncthreads();
    float part[10];
#pragma unroll
    for (int j = 0; j < 10; j++) part[j] = 0.0f;
    for (int k = tid; k < H1DIM; k += 256) {
        float hv = fmaxf(h1[k], 0.0f);
#pragma unroll
        for (int j = 0; j < 10; j++) part[j] += hv * W2[k * 10 + j];
    }
#pragma unroll
    for (int j = 0; j < 10; j++) atomicAdd(&acc[j], part[j]);
    __syncthreads();
    if (tid < 10) out[tid] = acc[tid] + b2[tid];
}

// ----------------------------- launch -----------------------------------------
static inline int cdiv(int a, int b) { return (a + b - 1) / b; }

extern "C" void kernel_launch(void* const* d_in, const int* in_sizes, int n_in,
                              void* d_out, int out_size) {
    const float* x       = (const float*)d_in[0];
    const float* W_gat   = (const float*)d_in[1];
    const float* att_src = (const float*)d_in[2];
    const float* att_dst = (const float*)d_in[3];
    const float* b_gat   = (const float*)d_in[4];
    const float* W_gcn   = (const float*)d_in[5];
    const float* b_gcn   = (const float*)d_in[6];
    const float* W1      = (const float*)d_in[7];
    const float* b1      = (const float*)d_in[8];
    const float* W2      = (const float*)d_in[9];
    const float* b2      = (const float*)d_in[10];
    const int*   ei      = (const int*)d_in[11];

    const int N  = in_sizes[0] / D;
    const int E  = in_sizes[11] / 2;
    const int EP = E + N;
    float* out = (float*)d_out;

    __half *p_xlh, *p_xwh;
    float *p_x1, *p_wt, *p_asrc, *p_adst, *p_pmax, *p_psum, *p_h1;
    int *p_cnt, *p_rowptr, *p_cursor, *p_csrc;
    cudaGetSymbolAddress((void**)&p_xlh,    g_xlh);
    cudaGetSymbolAddress((void**)&p_xwh,    g_xwh);
    cudaGetSymbolAddress((void**)&p_x1,     g_x1);
    cudaGetSymbolAddress((void**)&p_wt,     g_wt);
    cudaGetSymbolAddress((void**)&p_asrc,   g_asrc);
    cudaGetSymbolAddress((void**)&p_adst,   g_adst);
    cudaGetSymbolAddress((void**)&p_pmax,   g_pmax);
    cudaGetSymbolAddress((void**)&p_psum,   g_psum);
    cudaGetSymbolAddress((void**)&p_h1,     g_h1);
    cudaGetSymbolAddress((void**)&p_cnt,    g_cnt);
    cudaGetSymbolAddress((void**)&p_rowptr, g_rowptr);
    cudaGetSymbolAddress((void**)&p_cursor, g_cursor);
    cudaGetSymbolAddress((void**)&p_csrc,   g_csrc);

    // side stream + events for GEMM1 || CSR overlap (leaked by design; capture-safe)
    cudaStream_t s2;
    cudaStreamCreate(&s2);
    cudaEvent_t evF, evJ;
    cudaEventCreateWithFlags(&evF, cudaEventDisableTiming);
    cudaEventCreateWithFlags(&evJ, cudaEventDisableTiming);

    // fork: GEMM1 (fp16 output + att scores) on s2
    cudaEventRecord(evF, 0);
    cudaStreamWaitEvent(s2, evF, 0);
    k_gemm1_h<<<cdiv(N, 128) * (HD / 128), 256, 0, s2>>>(
        x, W_gat, p_xlh, N, HD, D, att_src, att_dst, p_asrc, p_adst);
    cudaEventRecord(evJ, s2);

    // main stream: setup + CSR build
    const int setupN = N + 2 * HD + H1DIM + HD * HD;
    k_setup<<<cdiv(setupN, 256), 256>>>(p_cnt, p_pmax, p_psum, p_h1, b1, W_gcn, p_wt, N);
    k_count<<<cdiv(EP, 256), 256>>>(ei, p_cnt, E, N);
    k_scan<<<1, 1024>>>(p_cnt, p_rowptr, p_cursor, N, EP);
    k_scatter<<<cdiv(EP, 256), 256>>>(ei, p_cursor, p_csrc, E, N);

    // join: k_gat needs both CSR and GEMM1 outputs
    cudaStreamWaitEvent(0, evJ, 0);
    k_gat<<<cdiv(N * 32, 256), 256>>>(p_rowptr, p_csrc, p_xlh, p_asrc, p_adst,
                                      b_gat, p_x1, N);
    // GEMM2 (mma.sync tf32, 3-stage cp.async, fp16 output)
    cudaFuncSetAttribute(k_gemm2_cp, cudaFuncAttributeMaxDynamicSharedMemorySize, G2_SMEM);
    k_gemm2_cp<<<cdiv(N, 128) * (HD / 128), 256, G2_SMEM>>>(p_x1, p_wt, p_xwh, N, HD, HD);
    // GCN aggregation + fused global pooling (fp16 gather)
    k_gcn_pool<<<cdiv(N * 32, 256), 256>>>(p_rowptr, p_csrc, p_cnt, p_xwh, b_gcn,
                                           p_pmax, p_psum, N);
    // MLP head
    k_mlp1<<<MLP_JBLK * MLP_KSPLIT, 256>>>(p_pmax, p_psum, W1, p_h1, N);
    k_mlp2<<<1, 256>>>(p_h1, W2, b2, out);
}

// round 15
// speedup vs baseline: 1.8129x; 1.1672x over previous
#include <cuda_runtime.h>
#include <cuda_fp16.h>
#include <float.h>
#include <stdint.h>

// Problem constants (fixed by the dataset)
#define MAXN 20000
#define MAXE 320000
#define MAXEP (MAXE + MAXN)
#define D  64
#define H  10
#define HD 640
#define H1DIM 1500

// ----------------------------- scratch (static, allocation-free) ------------
__device__ __align__(16) __half g_xlh[(size_t)MAXN * HD];  // GAT features, fp16
__device__ __align__(16) __half g_x1h[(size_t)MAXN * HD];  // GAT output, fp16
__device__ __align__(16) __half g_xwh[(size_t)MAXN * HD];  // GCN pre-agg feats, fp16
__device__ __align__(16) __half g_wth[(size_t)HD * HD];    // W_gcn^T fp16: [n][k]
__device__ __align__(16) float g_asrc[(size_t)MAXN * H];
__device__ __align__(16) float g_adst[(size_t)MAXN * H];
__device__ __align__(16) float g_pmax[HD];
__device__ __align__(16) float g_psum[HD];
__device__ __align__(16) float g_h1  [H1DIM];
__device__ __align__(16) int g_cnt   [MAXN];
__device__ __align__(16) int g_rowptr[MAXN + 1];
__device__ __align__(16) int g_cursor[MAXN];
__device__ __align__(16) int g_csrc  [MAXEP];

__device__ __forceinline__ uint32_t f2tf32(float x) {
    uint32_t r;
    asm("cvt.rna.tf32.f32 %0, %1;" : "=r"(r) : "f"(x));
    return r;
}
__device__ __forceinline__ float rnd_tf32(float x) {
    return __uint_as_float(f2tf32(x));
}
__device__ __forceinline__ uint32_t smem_u32(const void* p) {
    uint32_t a;
    asm("{ .reg .u64 t; cvta.to.shared.u64 t, %1; cvt.u32.u64 %0, t; }" : "=r"(a) : "l"(p));
    return a;
}
#define CP_ASYNC16(dst, src, sz) \
    asm volatile("cp.async.cg.shared.global [%0], [%1], 16, %2;" \
                 :: "r"(dst), "l"(src), "r"(sz) : "memory")
#define CP_COMMIT() asm volatile("cp.async.commit_group;" ::: "memory")
#define CP_WAIT(n)  asm volatile("cp.async.wait_group %0;" :: "n"(n) : "memory")

// ----------------------------- setup (init + W^T fp16, one launch) -----------
__global__ void k_setup(int* __restrict__ cnt, float* __restrict__ pmax,
                        float* __restrict__ psum, float* __restrict__ h1,
                        const float* __restrict__ b1,
                        const float* __restrict__ w, __half* __restrict__ wth, int N) {
    int i = blockIdx.x * blockDim.x + threadIdx.x;
    if (i < N) { cnt[i] = 0; return; }
    i -= N;
    if (i < HD) { pmax[i] = 0.f; return; }
    i -= HD;
    if (i < HD) { psum[i] = 0.f; return; }
    i -= HD;
    if (i < H1DIM) { h1[i] = b1[i]; return; }
    i -= H1DIM;
    if (i < HD * HD) {
        int k = i / HD, n = i % HD;                 // coalesced read of w
        wth[(size_t)n * HD + k] = __float2half(w[i]);  // wth = W^T
    }
}

// ----------------------------- CSR build -------------------------------------
__global__ void k_count(const int* __restrict__ ei, int* __restrict__ cnt, int E, int N) {
    int e = blockIdx.x * blockDim.x + threadIdx.x;
    int EP = E + N;
    if (e >= EP) return;
    int dst = (e < E) ? ei[E + e] : (e - E);
    atomicAdd(&cnt[dst], 1);
}

__global__ __launch_bounds__(1024)
void k_scan(const int* __restrict__ cnt, int* __restrict__ rowptr,
            int* __restrict__ cursor, int N, int EP) {
    __shared__ int sums[1024];
    const int t = threadIdx.x;
    const int per = (N + 1023) >> 10;
    const int start = t * per;
    int vals[20];
    int cn = 0;
    const bool vec = (per % 4 == 0) && (start + per <= N);
    if (vec) {
#pragma unroll
        for (int q = 0; q < 5; q++) {
            if (q * 4 < per) {
                int4 v = *(const int4*)&cnt[start + q * 4];
                vals[q * 4 + 0] = v.x; vals[q * 4 + 1] = v.y;
                vals[q * 4 + 2] = v.z; vals[q * 4 + 3] = v.w;
            }
        }
        cn = per;
    } else if (start < N) {
        cn = min(per, N - start);
        for (int q = 0; q < cn; q++) vals[q] = cnt[start + q];
    }
    int s = 0;
    for (int q = 0; q < cn; q++) s += vals[q];
    sums[t] = s;
    __syncthreads();
    for (int off = 1; off < 1024; off <<= 1) {
        int o = (t >= off) ? sums[t - off] : 0;
        __syncthreads();
        sums[t] += o;
        __syncthreads();
    }
    int run = sums[t] - s;
    for (int q = 0; q < cn; q++) {
        int tmp = vals[q];
        vals[q] = run;
        run += tmp;
    }
    if (vec) {
#pragma unroll
        for (int q = 0; q < 5; q++) {
            if (q * 4 < per) {
                int4 v = make_int4(vals[q * 4 + 0], vals[q * 4 + 1],
                                   vals[q * 4 + 2], vals[q * 4 + 3]);
                *(int4*)&rowptr[start + q * 4] = v;
                *(int4*)&cursor[start + q * 4] = v;
            }
        }
    } else {
        for (int q = 0; q < cn; q++) {
            rowptr[start + q] = vals[q];
            cursor[start + q] = vals[q];
        }
    }
    if (t == 0) rowptr[N] = EP;
}

__global__ void k_scatter(const int* __restrict__ ei, int* __restrict__ cursor,
                          int* __restrict__ csrc, int E, int N) {
    int e = blockIdx.x * blockDim.x + threadIdx.x;
    int EP = E + N;
    if (e >= EP) return;
    int src, dst;
    if (e < E) { src = ei[e]; dst = ei[E + e]; }
    else       { src = dst = e - E; }
    int pos = atomicAdd(&cursor[dst], 1);
    csrc[pos] = src;
}

// ----------------------------- tf32 mma.sync GEMM1 (half output + att) -------
#define GAPAD 20
#define GBPAD 136
__global__ __launch_bounds__(256)
void k_gemm1_h(const float* __restrict__ A, const float* __restrict__ B,
               __half* __restrict__ Ch, int M, int Nn, int K,
               const float* __restrict__ att_src, const float* __restrict__ att_dst,
               float* __restrict__ asrc, float* __restrict__ adst) {
    __shared__ float As[2][128][GAPAD];
    __shared__ float Bs[2][16][GBPAD];
    const int tid = threadIdx.x;
    const int warp = tid >> 5, lane = tid & 31;
    const int wm = warp & 3, wn = warp >> 2;
    const int nTilesX = Nn / 128;
    const int bx = blockIdx.x % nTilesX;
    const int by = blockIdx.x / nTilesX;
    const int rowBase = by * 128, colBase = bx * 128;

    const int gID = lane >> 2;
    const int tIG = lane & 3;

    float acc[2][8][4];
#pragma unroll
    for (int mt = 0; mt < 2; mt++)
#pragma unroll
        for (int nt = 0; nt < 8; nt++)
#pragma unroll
            for (int r = 0; r < 4; r++) acc[mt][nt][r] = 0.0f;

    const int aR  = tid >> 2;
    const int aC4 = (tid & 3) * 4;
    const int bR  = tid >> 5;
    const int bC4 = lane * 4;

    float4 avr[2], bvr[2];
#pragma unroll
    for (int half_ = 0; half_ < 2; half_++) {
        int gr = rowBase + aR + half_ * 64;
        avr[half_] = (gr < M) ? *(const float4*)&A[(size_t)gr * K + aC4]
                              : make_float4(0.f, 0.f, 0.f, 0.f);
        bvr[half_] = *(const float4*)&B[(size_t)(bR + half_ * 8) * Nn + colBase + bC4];
    }

    int buf = 0;
    for (int k0 = 0; k0 < K; k0 += 16) {
#pragma unroll
        for (int half_ = 0; half_ < 2; half_++) {
            int r = aR + half_ * 64;
            As[buf][r][aC4 + 0] = rnd_tf32(avr[half_].x);
            As[buf][r][aC4 + 1] = rnd_tf32(avr[half_].y);
            As[buf][r][aC4 + 2] = rnd_tf32(avr[half_].z);
            As[buf][r][aC4 + 3] = rnd_tf32(avr[half_].w);
            int rb = bR + half_ * 8;
            Bs[buf][rb][bC4 + 0] = rnd_tf32(bvr[half_].x);
            Bs[buf][rb][bC4 + 1] = rnd_tf32(bvr[half_].y);
            Bs[buf][rb][bC4 + 2] = rnd_tf32(bvr[half_].z);
            Bs[buf][rb][bC4 + 3] = rnd_tf32(bvr[half_].w);
        }
        __syncthreads();

        if (k0 + 16 < K) {
#pragma unroll
            for (int half_ = 0; half_ < 2; half_++) {
                int gr = rowBase + aR + half_ * 64;
                avr[half_] = (gr < M) ? *(const float4*)&A[(size_t)gr * K + k0 + 16 + aC4]
                                      : make_float4(0.f, 0.f, 0.f, 0.f);
                bvr[half_] = *(const float4*)&B[(size_t)(k0 + 16 + bR + half_ * 8) * Nn + colBase + bC4];
            }
        }

#pragma unroll
        for (int ks = 0; ks < 16; ks += 8) {
            uint32_t af[2][4];
#pragma unroll
            for (int mt = 0; mt < 2; mt++) {
                int r0 = wm * 32 + mt * 16 + gID;
                int kc = ks + tIG;
                af[mt][0] = __float_as_uint(As[buf][r0][kc]);
                af[mt][1] = __float_as_uint(As[buf][r0 + 8][kc]);
                af[mt][2] = __float_as_uint(As[buf][r0][kc + 4]);
                af[mt][3] = __float_as_uint(As[buf][r0 + 8][kc + 4]);
            }
#pragma unroll
            for (int nt = 0; nt < 8; nt++) {
                int col = wn * 64 + nt * 8 + gID;
                uint32_t b0 = __float_as_uint(Bs[buf][ks + tIG][col]);
                uint32_t b1 = __float_as_uint(Bs[buf][ks + tIG + 4][col]);
#pragma unroll
                for (int mt = 0; mt < 2; mt++) {
                    asm volatile(
                        "mma.sync.aligned.m16n8k8.row.col.f32.tf32.tf32.f32 "
                        "{%0,%1,%2,%3}, {%4,%5,%6,%7}, {%8,%9}, {%0,%1,%2,%3};\n"
                        : "+f"(acc[mt][nt][0]), "+f"(acc[mt][nt][1]),
                          "+f"(acc[mt][nt][2]), "+f"(acc[mt][nt][3])
                        : "r"(af[mt][0]), "r"(af[mt][1]), "r"(af[mt][2]), "r"(af[mt][3]),
                          "r"(b0), "r"(b1));
                }
            }
        }
        __syncthreads();
        buf ^= 1;
    }

#pragma unroll
    for (int mt = 0; mt < 2; mt++) {
        int r0 = rowBase + wm * 32 + mt * 16 + gID;
#pragma unroll
        for (int nt = 0; nt < 8; nt++) {
            int c0 = colBase + wn * 64 + nt * 8 + tIG * 2;
            if (r0 < M)
                *(__half2*)&Ch[(size_t)r0 * Nn + c0] =
                    __floats2half2_rn(acc[mt][nt][0], acc[mt][nt][1]);
            if (r0 + 8 < M)
                *(__half2*)&Ch[(size_t)(r0 + 8) * Nn + c0] =
                    __floats2half2_rn(acc[mt][nt][2], acc[mt][nt][3]);
        }
    }

    {
        const int h = bx * 2 + wn;
        float as[16], ad[16];
#pragma unroll
        for (int nt = 0; nt < 8; nt++)
#pragma unroll
            for (int p = 0; p < 2; p++) {
                int cih = nt * 8 + tIG * 2 + p;
                as[nt * 2 + p] = att_src[h * D + cih];
                ad[nt * 2 + p] = att_dst[h * D + cih];
            }
#pragma unroll
        for (int mt = 0; mt < 2; mt++) {
#pragma unroll
            for (int pair = 0; pair < 2; pair++) {
                float ps = 0.f, pd = 0.f;
#pragma unroll
                for (int nt = 0; nt < 8; nt++)
#pragma unroll
                    for (int p = 0; p < 2; p++) {
                        float v = acc[mt][nt][pair * 2 + p];
                        ps += v * as[nt * 2 + p];
                        pd += v * ad[nt * 2 + p];
                    }
                ps += __shfl_down_sync(0xffffffffu, ps, 2, 4);
                ps += __shfl_down_sync(0xffffffffu, ps, 1, 4);
                pd += __shfl_down_sync(0xffffffffu, pd, 2, 4);
                pd += __shfl_down_sync(0xffffffffu, pd, 1, 4);
                int gr = rowBase + wm * 32 + mt * 16 + gID + pair * 8;
                if (tIG == 0 && gr < M) {
                    asrc[gr * H + h] = ps;
                    adst[gr * H + h] = pd;
                }
            }
        }
    }
}

// ----------------------------- GEMM2: fp16 mma.sync m16n8k16 + cp.async ------
// A = x1h [M][K] row-major fp16; Bt = wth [N][K] row-major fp16 (W^T).
// 128x128 CTA tile, K chunks of 32, 3-stage cp.async pipeline.
#define HSTRIDE 40                         // halfs per smem row (32 + 8 pad)
#define HTILE   (128 * HSTRIDE)            // halfs per stage per operand
#define G2H_SMEM (3 * 2 * HTILE * 2)       // bytes = 61440
__global__ __launch_bounds__(256)
void k_gemm2_h(const __half* __restrict__ A, const __half* __restrict__ Bt,
               __half* __restrict__ Ch, int M, int Nn, int K) {
    extern __shared__ __align__(16) __half hsm[];
    __half* Ah = hsm;                      // [3][128][HSTRIDE]
    __half* Bh = hsm + 3 * HTILE;          // [3][128][HSTRIDE]

    const int tid = threadIdx.x;
    const int warp = tid >> 5, lane = tid & 31;
    const int wm = warp & 3, wn = warp >> 2;
    const int nTilesX = Nn / 128;
    const int bx = blockIdx.x % nTilesX;
    const int by = blockIdx.x / nTilesX;
    const int rowBase = by * 128, colBase = bx * 128;

    const int gID = lane >> 2;
    const int tIG = lane & 3;

    float acc[2][8][4];
#pragma unroll
    for (int mt = 0; mt < 2; mt++)
#pragma unroll
        for (int nt = 0; nt < 8; nt++)
#pragma unroll
            for (int r = 0; r < 4; r++) acc[mt][nt][r] = 0.0f;

    // staging: 128 rows x 32 halfs (64 B) per operand per chunk;
    // 512 16B-transfers per operand, 2 per thread.
    auto issue = [&](int st, int kk) {
#pragma unroll
        for (int q = 0; q < 2; q++) {
            int f = tid + q * 256;             // 0..511
            int r = f >> 2;                    // row 0..127
            int c8 = (f & 3) * 8;              // half offset within row
            uint32_t da = smem_u32(&Ah[(size_t)st * HTILE + r * HSTRIDE + c8]);
            int gr = rowBase + r;
            const __half* sa = &A[(size_t)gr * K + kk + c8];
            CP_ASYNC16(da, sa, (gr < M) ? 16 : 0);
            uint32_t db = smem_u32(&Bh[(size_t)st * HTILE + r * HSTRIDE + c8]);
            const __half* sb = &Bt[(size_t)(colBase + r) * K + kk + c8];
            CP_ASYNC16(db, sb, 16);
        }
        CP_COMMIT();
    };

    const int NCH = K / 32;                    // 20
    issue(0, 0);
    issue(1, 32);
    for (int ch = 0; ch < NCH; ch++) {
        CP_WAIT(1);
        __syncthreads();
        if (ch + 2 < NCH) issue((ch + 2) % 3, (ch + 2) * 32);

        const __half* As = Ah + (size_t)(ch % 3) * HTILE;
        const __half* Bs = Bh + (size_t)(ch % 3) * HTILE;
#pragma unroll
        for (int ks = 0; ks < 32; ks += 16) {
            uint32_t af[2][4];
#pragma unroll
            for (int mt = 0; mt < 2; mt++) {
                int r0 = wm * 32 + mt * 16 + gID;
                int kc = ks + 2 * tIG;
                af[mt][0] = *(const uint32_t*)&As[r0 * HSTRIDE + kc];
                af[mt][1] = *(const uint32_t*)&As[(r0 + 8) * HSTRIDE + kc];
                af[mt][2] = *(const uint32_t*)&As[r0 * HSTRIDE + kc + 8];
                af[mt][3] = *(const uint32_t*)&As[(r0 + 8) * HSTRIDE + kc + 8];
            }
#pragma unroll
            for (int nt = 0; nt < 8; nt++) {
                int col = wn * 64 + nt * 8 + gID;
                int kc = ks + 2 * tIG;
                uint32_t b0 = *(const uint32_t*)&Bs[col * HSTRIDE + kc];
                uint32_t b1 = *(const uint32_t*)&Bs[col * HSTRIDE + kc + 8];
#pragma unroll
                for (int mt = 0; mt < 2; mt++) {
                    asm volatile(
                        "mma.sync.aligned.m16n8k16.row.col.f32.f16.f16.f32 "
                        "{%0,%1,%2,%3}, {%4,%5,%6,%7}, {%8,%9}, {%0,%1,%2,%3};\n"
                        : "+f"(acc[mt][nt][0]), "+f"(acc[mt][nt][1]),
                          "+f"(acc[mt][nt][2]), "+f"(acc[mt][nt][3])
                        : "r"(af[mt][0]), "r"(af[mt][1]), "r"(af[mt][2]), "r"(af[mt][3]),
                          "r"(b0), "r"(b1));
                }
            }
        }
    }

#pragma unroll
    for (int mt = 0; mt < 2; mt++) {
        int r0 = rowBase + wm * 32 + mt * 16 + gID;
#pragma unroll
        for (int nt = 0; nt < 8; nt++) {
            int c0 = colBase + wn * 64 + nt * 8 + tIG * 2;
            if (r0 < M)
                *(__half2*)&Ch[(size_t)r0 * Nn + c0] =
                    __floats2half2_rn(acc[mt][nt][0], acc[mt][nt][1]);
            if (r0 + 8 < M)
                *(__half2*)&Ch[(size_t)(r0 + 8) * Nn + c0] =
                    __floats2half2_rn(acc[mt][nt][2], acc[mt][nt][3]);
        }
    }
}

// ----------------------------- GAT: one warp per node (fp16 in/out) ----------
__global__ __launch_bounds__(256)
void k_gat(const int* __restrict__ rowptr, const int* __restrict__ csrc,
           const __half* __restrict__ xlh,
           const float* __restrict__ asrc, const float* __restrict__ adst,
           const float* __restrict__ bias, __half* __restrict__ x1h, int N) {
    int w = (blockIdx.x * blockDim.x + threadIdx.x) >> 5;
    int lane = threadIdx.x & 31;
    if (w >= N) return;
    const int row = rowptr[w];
    const int end = rowptr[w + 1];

    const int h = lane % H;
    const int c = lane / H;
    const float adst_h = (lane < 30) ? adst[w * H + h] : 0.f;

    float m = -FLT_MAX, den = 0.f;
    if (lane < 30) {
        for (int i = row + c; i < end; i += 3) {
            int s = csrc[i];
            float a = asrc[s * H + h] + adst_h;
            a = a > 0.f ? a : 0.2f * a;
            float nm = fmaxf(m, a);
            den = den * __expf(m - nm) + __expf(a - nm);
            m = nm;
        }
    }
    {
        float mA = __shfl_sync(0xffffffffu, m,   lane + 10);
        float dA = __shfl_sync(0xffffffffu, den, lane + 10);
        float mB = __shfl_sync(0xffffffffu, m,   lane + 20);
        float dB = __shfl_sync(0xffffffffu, den, lane + 20);
        float M2 = fmaxf(m, fmaxf(mA, mB));
        den = den * __expf(m - M2) + dA * __expf(mA - M2) + dB * __expf(mB - M2);
        m = M2;
    }
    const float invden = 1.0f / (den + 1e-16f);

    float4 acc4[5];
#pragma unroll
    for (int j = 0; j < 5; j++) acc4[j] = make_float4(0.f, 0.f, 0.f, 0.f);

    const int hsel = lane >> 4;
    int i = row;
    for (; i + 1 < end; i += 2) {
        int s0 = csrc[i];
        int s1 = csrc[i + 1];
        float wv0 = 0.f, wv1 = 0.f;
        if (lane < H) {
            float a0 = asrc[s0 * H + lane] + adst_h;
            float a1 = asrc[s1 * H + lane] + adst_h;
            a0 = a0 > 0.f ? a0 : 0.2f * a0;
            a1 = a1 > 0.f ? a1 : 0.2f * a1;
            wv0 = __expf(a0 - m) * invden;
            wv1 = __expf(a1 - m) * invden;
        }
        const uint2* xs0 = (const uint2*)(xlh + (size_t)s0 * HD);
        const uint2* xs1 = (const uint2*)(xlh + (size_t)s1 * HD);
        uint2 u0[5], u1[5];
#pragma unroll
        for (int j = 0; j < 5; j++) { u0[j] = xs0[lane + 32 * j]; u1[j] = xs1[lane + 32 * j]; }
#pragma unroll
        for (int j = 0; j < 5; j++) {
            float w0 = __shfl_sync(0xffffffffu, wv0, 2 * j + hsel);
            float w1 = __shfl_sync(0xffffffffu, wv1, 2 * j + hsel);
            float2 a0 = __half22float2(*(const __half2*)&u0[j].x);
            float2 b0 = __half22float2(*(const __half2*)&u0[j].y);
            float2 a1 = __half22float2(*(const __half2*)&u1[j].x);
            float2 b1 = __half22float2(*(const __half2*)&u1[j].y);
            acc4[j].x += a0.x * w0 + a1.x * w1;
            acc4[j].y += a0.y * w0 + a1.y * w1;
            acc4[j].z += b0.x * w0 + b1.x * w1;
            acc4[j].w += b0.y * w0 + b1.y * w1;
        }
    }
    if (i < end) {
        int s = csrc[i];
        float wv = 0.f;
        if (lane < H) {
            float a = asrc[s * H + lane] + adst_h;
            a = a > 0.f ? a : 0.2f * a;
            wv = __expf(a - m) * invden;
        }
        const uint2* xs = (const uint2*)(xlh + (size_t)s * HD);
#pragma unroll
        for (int j = 0; j < 5; j++) {
            float wj = __shfl_sync(0xffffffffu, wv, 2 * j + hsel);
            uint2 u = xs[lane + 32 * j];
            float2 a0 = __half22float2(*(const __half2*)&u.x);
            float2 b0 = __half22float2(*(const __half2*)&u.y);
            acc4[j].x += a0.x * wj;
            acc4[j].y += a0.y * wj;
            acc4[j].z += b0.x * wj;
            acc4[j].w += b0.y * wj;
        }
    }

    uint2* xo = (uint2*)(x1h + (size_t)w * HD);
    const float4* b4 = (const float4*)bias;
#pragma unroll
    for (int j = 0; j < 5; j++) {
        int idx = lane + 32 * j;
        float4 bb = b4[idx];
        float4 v = acc4[j];
        v.x = fmaxf(v.x + bb.x, 0.f);
        v.y = fmaxf(v.y + bb.y, 0.f);
        v.z = fmaxf(v.z + bb.z, 0.f);
        v.w = fmaxf(v.w + bb.w, 0.f);
        uint2 o;
        *(__half2*)&o.x = __floats2half2_rn(v.x, v.y);
        *(__half2*)&o.y = __floats2half2_rn(v.z, v.w);
        xo[idx] = o;
    }
}

// ----------------------------- GCN + pooling (fp16 gather) -------------------
__global__ __launch_bounds__(256)
void k_gcn_pool(const int* __restrict__ rowptr, const int* __restrict__ csrc,
                const int* __restrict__ cnt, const __half* __restrict__ xwh,
                const float* __restrict__ bias,
                float* __restrict__ pmax, float* __restrict__ psum, int N) {
    __shared__ float smax[HD];
    __shared__ float ssum[HD];
    const int tid = threadIdx.x;
    for (int i = tid; i < HD; i += 256) { smax[i] = 0.f; ssum[i] = 0.f; }
    __syncthreads();

    const int w = (blockIdx.x * blockDim.x + tid) >> 5;
    const int lane = tid & 31;

    if (w < N) {
        const int row = rowptr[w];
        const int end = rowptr[w + 1];
        const float dn = rsqrtf((float)(end - row));

        float4 acc4[5];
#pragma unroll
        for (int j = 0; j < 5; j++) acc4[j] = make_float4(0.f, 0.f, 0.f, 0.f);

        int i = row;
        for (; i + 1 < end; i += 2) {
            int s0 = csrc[i];
            int s1 = csrc[i + 1];
            float n0 = dn * rsqrtf((float)cnt[s0]);
            float n1 = dn * rsqrtf((float)cnt[s1]);
            const uint2* xs0 = (const uint2*)(xwh + (size_t)s0 * HD);
            const uint2* xs1 = (const uint2*)(xwh + (size_t)s1 * HD);
            uint2 u0[5], u1[5];
#pragma unroll
            for (int j = 0; j < 5; j++) { u0[j] = xs0[lane + 32 * j]; u1[j] = xs1[lane + 32 * j]; }
#pragma unroll
            for (int j = 0; j < 5; j++) {
                float2 a0 = __half22float2(*(const __half2*)&u0[j].x);
                float2 b0 = __half22float2(*(const __half2*)&u0[j].y);
                float2 a1 = __half22float2(*(const __half2*)&u1[j].x);
                float2 b1 = __half22float2(*(const __half2*)&u1[j].y);
                acc4[j].x += a0.x * n0 + a1.x * n1;
                acc4[j].y += a0.y * n0 + a1.y * n1;
                acc4[j].z += b0.x * n0 + b1.x * n1;
                acc4[j].w += b0.y * n0 + b1.y * n1;
            }
        }
        if (i < end) {
            int s = csrc[i];
            float nrm = dn * rsqrtf((float)cnt[s]);
            const uint2* xs = (const uint2*)(xwh + (size_t)s * HD);
#pragma unroll
            for (int j = 0; j < 5; j++) {
                uint2 u = xs[lane + 32 * j];
                float2 a0 = __half22float2(*(const __half2*)&u.x);
                float2 b0 = __half22float2(*(const __half2*)&u.y);
                acc4[j].x += a0.x * nrm;
                acc4[j].y += a0.y * nrm;
                acc4[j].z += b0.x * nrm;
                acc4[j].w += b0.y * nrm;
            }
        }

        const float4* b4 = (const float4*)bias;
#pragma unroll
        for (int j = 0; j < 5; j++) {
            int idx = lane + 32 * j;
            float4 bb = b4[idx];
            float4 v = acc4[j];
            v.x = fmaxf(v.x + bb.x, 0.f);
            v.y = fmaxf(v.y + bb.y, 0.f);
            v.z = fmaxf(v.z + bb.z, 0.f);
            v.w = fmaxf(v.w + bb.w, 0.f);
            int col = idx * 4;
            atomicMax((int*)&smax[col + 0], __float_as_int(v.x));
            atomicMax((int*)&smax[col + 1], __float_as_int(v.y));
            atomicMax((int*)&smax[col + 2], __float_as_int(v.z));
            atomicMax((int*)&smax[col + 3], __float_as_int(v.w));
            atomicAdd(&ssum[col + 0], v.x);
            atomicAdd(&ssum[col + 1], v.y);
            atomicAdd(&ssum[col + 2], v.z);
            atomicAdd(&ssum[col + 3], v.w);
        }
    }
    __syncthreads();

    for (int i = tid; i < HD; i += 256) {
        atomicMax((int*)&pmax[i], __float_as_int(smax[i]));
        atomicAdd(&psum[i], ssum[i]);
    }
}

// ----------------------------- MLP (k-split parallel) ------------------------
#define MLP_KSPLIT 10
#define MLP_JBLK   6
__global__ void k_mlp1(const float* __restrict__ pmax, const float* __restrict__ psum,
                       const float* __restrict__ W1, float* __restrict__ h1, int N) {
    const int jb = blockIdx.x % MLP_JBLK;
    const int s  = blockIdx.x / MLP_JBLK;
    const int j = jb * 256 + threadIdx.x;
    if (j >= H1DIM) return;
    const float invN = 1.0f / (float)N;
    const int k0 = s * (2 * HD / MLP_KSPLIT);
    float acc = 0.f;
#pragma unroll 4
    for (int k = k0; k < k0 + 2 * HD / MLP_KSPLIT; k++) {
        float v = (k < HD) ? pmax[k] : psum[k - HD] * invN;
        acc += v * W1[(size_t)k * H1DIM + j];
    }
    atomicAdd(&h1[j], acc);
}

__global__ void k_mlp2(const float* __restrict__ h1, const float* __restrict__ W2,
                       const float* __restrict__ b2, float* __restrict__ out) {
    __shared__ float acc[10];
    int tid = threadIdx.x;
    if (tid < 10) acc[tid] = 0.0f;
    __syncthreads();
    float part[10];
#pragma unroll
    for (int j = 0; j < 10; j++) part[j] = 0.0f;
    for (int k = tid; k < H1DIM; k += 256) {
        float hv = fmaxf(h1[k], 0.0f);
#pragma unroll
        for (int j = 0; j < 10; j++) part[j] += hv * W2[k * 10 + j];
    }
#pragma unroll
    for (int j = 0; j < 10; j++) atomicAdd(&acc[j], part[j]);
    __syncthreads();
    if (tid < 10) out[tid] = acc[tid] + b2[tid];
}

// ----------------------------- launch -----------------------------------------
static inline int cdiv(int a, int b) { return (a + b - 1) / b; }

extern "C" void kernel_launch(void* const* d_in, const int* in_sizes, int n_in,
                              void* d_out, int out_size) {
    const float* x       = (const float*)d_in[0];
    const float* W_gat   = (const float*)d_in[1];
    const float* att_src = (const float*)d_in[2];
    const float* att_dst = (const float*)d_in[3];
    const float* b_gat   = (const float*)d_in[4];
    const float* W_gcn   = (const float*)d_in[5];
    const float* b_gcn   = (const float*)d_in[6];
    const float* W1      = (const float*)d_in[7];
    const float* b1      = (const float*)d_in[8];
    const float* W2      = (const float*)d_in[9];
    const float* b2      = (const float*)d_in[10];
    const int*   ei      = (const int*)d_in[11];

    const int N  = in_sizes[0] / D;
    const int E  = in_sizes[11] / 2;
    const int EP = E + N;
    float* out = (float*)d_out;

    __half *p_xlh, *p_x1h, *p_xwh, *p_wth;
    float *p_asrc, *p_adst, *p_pmax, *p_psum, *p_h1;
    int *p_cnt, *p_rowptr, *p_cursor, *p_csrc;
    cudaGetSymbolAddress((void**)&p_xlh,    g_xlh);
    cudaGetSymbolAddress((void**)&p_x1h,    g_x1h);
    cudaGetSymbolAddress((void**)&p_xwh,    g_xwh);
    cudaGetSymbolAddress((void**)&p_wth,    g_wth);
    cudaGetSymbolAddress((void**)&p_asrc,   g_asrc);
    cudaGetSymbolAddress((void**)&p_adst,   g_adst);
    cudaGetSymbolAddress((void**)&p_pmax,   g_pmax);
    cudaGetSymbolAddress((void**)&p_psum,   g_psum);
    cudaGetSymbolAddress((void**)&p_h1,     g_h1);
    cudaGetSymbolAddress((void**)&p_cnt,    g_cnt);
    cudaGetSymbolAddress((void**)&p_rowptr, g_rowptr);
    cudaGetSymbolAddress((void**)&p_cursor, g_cursor);
    cudaGetSymbolAddress((void**)&p_csrc,   g_csrc);

    // side stream + events for GEMM1 || CSR overlap (leaked by design; capture-safe)
    cudaStream_t s2;
    cudaStreamCreate(&s2);
    cudaEvent_t evF, evJ;
    cudaEventCreateWithFlags(&evF, cudaEventDisableTiming);
    cudaEventCreateWithFlags(&evJ, cudaEventDisableTiming);

    // fork: GEMM1 (fp16 output + att scores) on s2
    cudaEventRecord(evF, 0);
    cudaStreamWaitEvent(s2, evF, 0);
    k_gemm1_h<<<cdiv(N, 128) * (HD / 128), 256, 0, s2>>>(
        x, W_gat, p_xlh, N, HD, D, att_src, att_dst, p_asrc, p_adst);
    cudaEventRecord(evJ, s2);

    // main stream: setup (incl. W_gcn^T fp16) + CSR build
    const int setupN = N + 2 * HD + H1DIM + HD * HD;
    k_setup<<<cdiv(setupN, 256), 256>>>(p_cnt, p_pmax, p_psum, p_h1, b1, W_gcn, p_wth, N);
    k_count<<<cdiv(EP, 256), 256>>>(ei, p_cnt, E, N);
    k_scan<<<1, 1024>>>(p_cnt, p_rowptr, p_cursor, N, EP);
    k_scatter<<<cdiv(EP, 256), 256>>>(ei, p_cursor, p_csrc, E, N);

    // join: k_gat needs both CSR and GEMM1 outputs
    cudaStreamWaitEvent(0, evJ, 0);
    k_gat<<<cdiv(N * 32, 256), 256>>>(p_rowptr, p_csrc, p_xlh, p_asrc, p_adst,
                                      b_gat, p_x1h, N);
    // GEMM2 (fp16 mma.sync m16n8k16, 3-stage cp.async, fp16 in/out)
    cudaFuncSetAttribute(k_gemm2_h, cudaFuncAttributeMaxDynamicSharedMemorySize, G2H_SMEM);
    k_gemm2_h<<<cdiv(N, 128) * (HD / 128), 256, G2H_SMEM>>>(p_x1h, p_wth, p_xwh, N, HD, HD);
    // GCN aggregation + fused global pooling (fp16 gather)
    k_gcn_pool<<<cdiv(N * 32, 256), 256>>>(p_rowptr, p_csrc, p_cnt, p_xwh, b_gcn,
                                           p_pmax, p_psum, N);
    // MLP head
    k_mlp1<<<MLP_JBLK * MLP_KSPLIT, 256>>>(p_pmax, p_psum, W1, p_h1, N);
    k_mlp2<<<1, 256>>>(p_h1, W2, b2, out);
}

// round 16
// speedup vs baseline: 1.8396x; 1.0147x over previous
#include <cuda_runtime.h>
#include <cuda_fp16.h>
#include <float.h>
#include <stdint.h>

// Problem constants (fixed by the dataset)
#define MAXN 20000
#define MAXE 320000
#define MAXEP (MAXE + MAXN)
#define D  64
#define H  10
#define HD 640
#define H1DIM 1500

// ----------------------------- scratch (static, allocation-free) ------------
__device__ __align__(16) __half g_xlh[(size_t)MAXN * HD];  // GAT features, fp16
__device__ __align__(16) __half g_x1h[(size_t)MAXN * HD];  // GAT output, fp16
__device__ __align__(16) __half g_xwh[(size_t)MAXN * HD];  // GCN pre-agg feats, fp16
__device__ __align__(16) __half g_wth[(size_t)HD * HD];    // W_gcn^T fp16: [n][k]
__device__ __align__(16) float g_asrc[(size_t)MAXN * H];
__device__ __align__(16) float g_adst[(size_t)MAXN * H];
__device__ __align__(16) float g_pmax[HD];
__device__ __align__(16) float g_psum[HD];
__device__ __align__(16) float g_h1  [H1DIM];
__device__ __align__(16) int g_cnt   [MAXN];
__device__ __align__(16) int g_rowptr[MAXN + 1];
__device__ __align__(16) int g_cursor[MAXN];
__device__ __align__(16) int g_csrc  [MAXEP];

__device__ __forceinline__ uint32_t f2tf32(float x) {
    uint32_t r;
    asm("cvt.rna.tf32.f32 %0, %1;" : "=r"(r) : "f"(x));
    return r;
}
__device__ __forceinline__ float rnd_tf32(float x) {
    return __uint_as_float(f2tf32(x));
}
__device__ __forceinline__ uint32_t smem_u32(const void* p) {
    uint32_t a;
    asm("{ .reg .u64 t; cvta.to.shared.u64 t, %1; cvt.u32.u64 %0, t; }" : "=r"(a) : "l"(p));
    return a;
}
#define CP_ASYNC16(dst, src, sz) \
    asm volatile("cp.async.cg.shared.global [%0], [%1], 16, %2;" \
                 :: "r"(dst), "l"(src), "r"(sz) : "memory")
#define CP_COMMIT() asm volatile("cp.async.commit_group;" ::: "memory")
#define CP_WAIT(n)  asm volatile("cp.async.wait_group %0;" :: "n"(n) : "memory")

// ----------------------------- init kernels ----------------------------------
__global__ void k_zero_cnt(int* __restrict__ cnt, int N) {
    int i = blockIdx.x * blockDim.x + threadIdx.x;
    if (i < N) cnt[i] = 0;
}

// pool/h1 init + W_gcn^T fp16 (runs on side stream; not needed by CSR build)
__global__ void k_setup_w(float* __restrict__ pmax, float* __restrict__ psum,
                          float* __restrict__ h1, const float* __restrict__ b1,
                          const float* __restrict__ w, __half* __restrict__ wth) {
    int i = blockIdx.x * blockDim.x + threadIdx.x;
    if (i < HD) { pmax[i] = 0.f; return; }
    i -= HD;
    if (i < HD) { psum[i] = 0.f; return; }
    i -= HD;
    if (i < H1DIM) { h1[i] = b1[i]; return; }
    i -= H1DIM;
    if (i < HD * HD) {
        int k = i / HD, n = i % HD;                    // coalesced read of w
        wth[(size_t)n * HD + k] = __float2half(w[i]);  // wth = W^T
    }
}

// ----------------------------- CSR build -------------------------------------
__global__ void k_count(const int* __restrict__ ei, int* __restrict__ cnt, int E, int N) {
    int e = blockIdx.x * blockDim.x + threadIdx.x;
    int EP = E + N;
    if (e >= EP) return;
    int dst = (e < E) ? ei[E + e] : (e - E);
    atomicAdd(&cnt[dst], 1);
}

// warp-shuffle block scan: 2 barriers total
__global__ __launch_bounds__(1024)
void k_scan(const int* __restrict__ cnt, int* __restrict__ rowptr,
            int* __restrict__ cursor, int N, int EP) {
    __shared__ int wsum[32];
    const int t = threadIdx.x;
    const int warp = t >> 5, lane = t & 31;
    const int per = (N + 1023) >> 10;                 // <= 20 for MAXN
    const int start = t * per;
    int vals[20];
    int cn = 0;
    const bool vec = (per % 4 == 0) && (start + per <= N);
    if (vec) {
#pragma unroll
        for (int q = 0; q < 5; q++) {
            if (q * 4 < per) {
                int4 v = *(const int4*)&cnt[start + q * 4];
                vals[q * 4 + 0] = v.x; vals[q * 4 + 1] = v.y;
                vals[q * 4 + 2] = v.z; vals[q * 4 + 3] = v.w;
            }
        }
        cn = per;
    } else if (start < N) {
        cn = min(per, N - start);
        for (int q = 0; q < cn; q++) vals[q] = cnt[start + q];
    }
    int s = 0;
    for (int q = 0; q < cn; q++) s += vals[q];

    // inclusive scan within warp
    int inc = s;
#pragma unroll
    for (int off = 1; off < 32; off <<= 1) {
        int v = __shfl_up_sync(0xffffffffu, inc, off);
        if (lane >= off) inc += v;
    }
    if (lane == 31) wsum[warp] = inc;
    __syncthreads();
    if (warp == 0) {
        int v = wsum[lane];
        int iv = v;
#pragma unroll
        for (int off = 1; off < 32; off <<= 1) {
            int u = __shfl_up_sync(0xffffffffu, iv, off);
            if (lane >= off) iv += u;
        }
        wsum[lane] = iv - v;                          // exclusive warp prefix
    }
    __syncthreads();
    int run = wsum[warp] + (inc - s);                 // exclusive thread prefix
    for (int q = 0; q < cn; q++) {
        int tmp = vals[q];
        vals[q] = run;
        run += tmp;
    }
    if (vec) {
#pragma unroll
        for (int q = 0; q < 5; q++) {
            if (q * 4 < per) {
                int4 v = make_int4(vals[q * 4 + 0], vals[q * 4 + 1],
                                   vals[q * 4 + 2], vals[q * 4 + 3]);
                *(int4*)&rowptr[start + q * 4] = v;
                *(int4*)&cursor[start + q * 4] = v;
            }
        }
    } else {
        for (int q = 0; q < cn; q++) {
            rowptr[start + q] = vals[q];
            cursor[start + q] = vals[q];
        }
    }
    if (t == 0) rowptr[N] = EP;
}

__global__ void k_scatter(const int* __restrict__ ei, int* __restrict__ cursor,
                          int* __restrict__ csrc, int E, int N) {
    int e = blockIdx.x * blockDim.x + threadIdx.x;
    int EP = E + N;
    if (e >= EP) return;
    int src, dst;
    if (e < E) { src = ei[e]; dst = ei[E + e]; }
    else       { src = dst = e - E; }
    int pos = atomicAdd(&cursor[dst], 1);
    csrc[pos] = src;
}

// ----------------------------- tf32 mma.sync GEMM1 (half output + att) -------
#define GAPAD 20
#define GBPAD 136
__global__ __launch_bounds__(256)
void k_gemm1_h(const float* __restrict__ A, const float* __restrict__ B,
               __half* __restrict__ Ch, int M, int Nn, int K,
               const float* __restrict__ att_src, const float* __restrict__ att_dst,
               float* __restrict__ asrc, float* __restrict__ adst) {
    __shared__ float As[2][128][GAPAD];
    __shared__ float Bs[2][16][GBPAD];
    const int tid = threadIdx.x;
    const int warp = tid >> 5, lane = tid & 31;
    const int wm = warp & 3, wn = warp >> 2;
    const int nTilesX = Nn / 128;
    const int bx = blockIdx.x % nTilesX;
    const int by = blockIdx.x / nTilesX;
    const int rowBase = by * 128, colBase = bx * 128;

    const int gID = lane >> 2;
    const int tIG = lane & 3;

    float acc[2][8][4];
#pragma unroll
    for (int mt = 0; mt < 2; mt++)
#pragma unroll
        for (int nt = 0; nt < 8; nt++)
#pragma unroll
            for (int r = 0; r < 4; r++) acc[mt][nt][r] = 0.0f;

    const int aR  = tid >> 2;
    const int aC4 = (tid & 3) * 4;
    const int bR  = tid >> 5;
    const int bC4 = lane * 4;

    float4 avr[2], bvr[2];
#pragma unroll
    for (int half_ = 0; half_ < 2; half_++) {
        int gr = rowBase + aR + half_ * 64;
        avr[half_] = (gr < M) ? *(const float4*)&A[(size_t)gr * K + aC4]
                              : make_float4(0.f, 0.f, 0.f, 0.f);
        bvr[half_] = *(const float4*)&B[(size_t)(bR + half_ * 8) * Nn + colBase + bC4];
    }

    int buf = 0;
    for (int k0 = 0; k0 < K; k0 += 16) {
#pragma unroll
        for (int half_ = 0; half_ < 2; half_++) {
            int r = aR + half_ * 64;
            As[buf][r][aC4 + 0] = rnd_tf32(avr[half_].x);
            As[buf][r][aC4 + 1] = rnd_tf32(avr[half_].y);
            As[buf][r][aC4 + 2] = rnd_tf32(avr[half_].z);
            As[buf][r][aC4 + 3] = rnd_tf32(avr[half_].w);
            int rb = bR + half_ * 8;
            Bs[buf][rb][bC4 + 0] = rnd_tf32(bvr[half_].x);
            Bs[buf][rb][bC4 + 1] = rnd_tf32(bvr[half_].y);
            Bs[buf][rb][bC4 + 2] = rnd_tf32(bvr[half_].z);
            Bs[buf][rb][bC4 + 3] = rnd_tf32(bvr[half_].w);
        }
        __syncthreads();

        if (k0 + 16 < K) {
#pragma unroll
            for (int half_ = 0; half_ < 2; half_++) {
                int gr = rowBase + aR + half_ * 64;
                avr[half_] = (gr < M) ? *(const float4*)&A[(size_t)gr * K + k0 + 16 + aC4]
                                      : make_float4(0.f, 0.f, 0.f, 0.f);
                bvr[half_] = *(const float4*)&B[(size_t)(k0 + 16 + bR + half_ * 8) * Nn + colBase + bC4];
            }
        }

#pragma unroll
        for (int ks = 0; ks < 16; ks += 8) {
            uint32_t af[2][4];
#pragma unroll
            for (int mt = 0; mt < 2; mt++) {
                int r0 = wm * 32 + mt * 16 + gID;
                int kc = ks + tIG;
                af[mt][0] = __float_as_uint(As[buf][r0][kc]);
                af[mt][1] = __float_as_uint(As[buf][r0 + 8][kc]);
                af[mt][2] = __float_as_uint(As[buf][r0][kc + 4]);
                af[mt][3] = __float_as_uint(As[buf][r0 + 8][kc + 4]);
            }
#pragma unroll
            for (int nt = 0; nt < 8; nt++) {
                int col = wn * 64 + nt * 8 + gID;
                uint32_t b0 = __float_as_uint(Bs[buf][ks + tIG][col]);
                uint32_t b1 = __float_as_uint(Bs[buf][ks + tIG + 4][col]);
#pragma unroll
                for (int mt = 0; mt < 2; mt++) {
                    asm volatile(
                        "mma.sync.aligned.m16n8k8.row.col.f32.tf32.tf32.f32 "
                        "{%0,%1,%2,%3}, {%4,%5,%6,%7}, {%8,%9}, {%0,%1,%2,%3};\n"
                        : "+f"(acc[mt][nt][0]), "+f"(acc[mt][nt][1]),
                          "+f"(acc[mt][nt][2]), "+f"(acc[mt][nt][3])
                        : "r"(af[mt][0]), "r"(af[mt][1]), "r"(af[mt][2]), "r"(af[mt][3]),
                          "r"(b0), "r"(b1));
                }
            }
        }
        __syncthreads();
        buf ^= 1;
    }

#pragma unroll
    for (int mt = 0; mt < 2; mt++) {
        int r0 = rowBase + wm * 32 + mt * 16 + gID;
#pragma unroll
        for (int nt = 0; nt < 8; nt++) {
            int c0 = colBase + wn * 64 + nt * 8 + tIG * 2;
            if (r0 < M)
                *(__half2*)&Ch[(size_t)r0 * Nn + c0] =
                    __floats2half2_rn(acc[mt][nt][0], acc[mt][nt][1]);
            if (r0 + 8 < M)
                *(__half2*)&Ch[(size_t)(r0 + 8) * Nn + c0] =
                    __floats2half2_rn(acc[mt][nt][2], acc[mt][nt][3]);
        }
    }

    {
        const int h = bx * 2 + wn;
        float as[16], ad[16];
#pragma unroll
        for (int nt = 0; nt < 8; nt++)
#pragma unroll
            for (int p = 0; p < 2; p++) {
                int cih = nt * 8 + tIG * 2 + p;
                as[nt * 2 + p] = att_src[h * D + cih];
                ad[nt * 2 + p] = att_dst[h * D + cih];
            }
#pragma unroll
        for (int mt = 0; mt < 2; mt++) {
#pragma unroll
            for (int pair = 0; pair < 2; pair++) {
                float ps = 0.f, pd = 0.f;
#pragma unroll
                for (int nt = 0; nt < 8; nt++)
#pragma unroll
                    for (int p = 0; p < 2; p++) {
                        float v = acc[mt][nt][pair * 2 + p];
                        ps += v * as[nt * 2 + p];
                        pd += v * ad[nt * 2 + p];
                    }
                ps += __shfl_down_sync(0xffffffffu, ps, 2, 4);
                ps += __shfl_down_sync(0xffffffffu, ps, 1, 4);
                pd += __shfl_down_sync(0xffffffffu, pd, 2, 4);
                pd += __shfl_down_sync(0xffffffffu, pd, 1, 4);
                int gr = rowBase + wm * 32 + mt * 16 + gID + pair * 8;
                if (tIG == 0 && gr < M) {
                    asrc[gr * H + h] = ps;
                    adst[gr * H + h] = pd;
                }
            }
        }
    }
}

// ----------------------------- GEMM2: fp16 mma.sync m16n8k16 + cp.async ------
#define HSTRIDE 40
#define HTILE   (128 * HSTRIDE)
#define G2H_SMEM (3 * 2 * HTILE * 2)
__global__ __launch_bounds__(256)
void k_gemm2_h(const __half* __restrict__ A, const __half* __restrict__ Bt,
               __half* __restrict__ Ch, int M, int Nn, int K) {
    extern __shared__ __align__(16) __half hsm[];
    __half* Ah = hsm;
    __half* Bh = hsm + 3 * HTILE;

    const int tid = threadIdx.x;
    const int warp = tid >> 5, lane = tid & 31;
    const int wm = warp & 3, wn = warp >> 2;
    const int nTilesX = Nn / 128;
    const int bx = blockIdx.x % nTilesX;
    const int by = blockIdx.x / nTilesX;
    const int rowBase = by * 128, colBase = bx * 128;

    const int gID = lane >> 2;
    const int tIG = lane & 3;

    float acc[2][8][4];
#pragma unroll
    for (int mt = 0; mt < 2; mt++)
#pragma unroll
        for (int nt = 0; nt < 8; nt++)
#pragma unroll
            for (int r = 0; r < 4; r++) acc[mt][nt][r] = 0.0f;

    auto issue = [&](int st, int kk) {
#pragma unroll
        for (int q = 0; q < 2; q++) {
            int f = tid + q * 256;
            int r = f >> 2;
            int c8 = (f & 3) * 8;
            uint32_t da = smem_u32(&Ah[(size_t)st * HTILE + r * HSTRIDE + c8]);
            int gr = rowBase + r;
            const __half* sa = &A[(size_t)gr * K + kk + c8];
            CP_ASYNC16(da, sa, (gr < M) ? 16 : 0);
            uint32_t db = smem_u32(&Bh[(size_t)st * HTILE + r * HSTRIDE + c8]);
            const __half* sb = &Bt[(size_t)(colBase + r) * K + kk + c8];
            CP_ASYNC16(db, sb, 16);
        }
        CP_COMMIT();
    };

    const int NCH = K / 32;
    issue(0, 0);
    issue(1, 32);
    for (int ch = 0; ch < NCH; ch++) {
        CP_WAIT(1);
        __syncthreads();
        if (ch + 2 < NCH) issue((ch + 2) % 3, (ch + 2) * 32);

        const __half* As = Ah + (size_t)(ch % 3) * HTILE;
        const __half* Bs = Bh + (size_t)(ch % 3) * HTILE;
#pragma unroll
        for (int ks = 0; ks < 32; ks += 16) {
            uint32_t af[2][4];
#pragma unroll
            for (int mt = 0; mt < 2; mt++) {
                int r0 = wm * 32 + mt * 16 + gID;
                int kc = ks + 2 * tIG;
                af[mt][0] = *(const uint32_t*)&As[r0 * HSTRIDE + kc];
                af[mt][1] = *(const uint32_t*)&As[(r0 + 8) * HSTRIDE + kc];
                af[mt][2] = *(const uint32_t*)&As[r0 * HSTRIDE + kc + 8];
                af[mt][3] = *(const uint32_t*)&As[(r0 + 8) * HSTRIDE + kc + 8];
            }
#pragma unroll
            for (int nt = 0; nt < 8; nt++) {
                int col = wn * 64 + nt * 8 + gID;
                int kc = ks + 2 * tIG;
                uint32_t b0 = *(const uint32_t*)&Bs[col * HSTRIDE + kc];
                uint32_t b1 = *(const uint32_t*)&Bs[col * HSTRIDE + kc + 8];
#pragma unroll
                for (int mt = 0; mt < 2; mt++) {
                    asm volatile(
                        "mma.sync.aligned.m16n8k16.row.col.f32.f16.f16.f32 "
                        "{%0,%1,%2,%3}, {%4,%5,%6,%7}, {%8,%9}, {%0,%1,%2,%3};\n"
                        : "+f"(acc[mt][nt][0]), "+f"(acc[mt][nt][1]),
                          "+f"(acc[mt][nt][2]), "+f"(acc[mt][nt][3])
                        : "r"(af[mt][0]), "r"(af[mt][1]), "r"(af[mt][2]), "r"(af[mt][3]),
                          "r"(b0), "r"(b1));
                }
            }
        }
    }

#pragma unroll
    for (int mt = 0; mt < 2; mt++) {
        int r0 = rowBase + wm * 32 + mt * 16 + gID;
#pragma unroll
        for (int nt = 0; nt < 8; nt++) {
            int c0 = colBase + wn * 64 + nt * 8 + tIG * 2;
            if (r0 < M)
                *(__half2*)&Ch[(size_t)r0 * Nn + c0] =
                    __floats2half2_rn(acc[mt][nt][0], acc[mt][nt][1]);
            if (r0 + 8 < M)
                *(__half2*)&Ch[(size_t)(r0 + 8) * Nn + c0] =
                    __floats2half2_rn(acc[mt][nt][2], acc[mt][nt][3]);
        }
    }
}

// ----------------------------- GAT: one warp per node (fp16 in/out) ----------
__global__ __launch_bounds__(256)
void k_gat(const int* __restrict__ rowptr, const int* __restrict__ csrc,
           const __half* __restrict__ xlh,
           const float* __restrict__ asrc, const float* __restrict__ adst,
           const float* __restrict__ bias, __half* __restrict__ x1h, int N) {
    int w = (blockIdx.x * blockDim.x + threadIdx.x) >> 5;
    int lane = threadIdx.x & 31;
    if (w >= N) return;
    const int row = rowptr[w];
    const int end = rowptr[w + 1];

    const int h = lane % H;
    const int c = lane / H;
    const float adst_h = (lane < 30) ? adst[w * H + h] : 0.f;

    float m = -FLT_MAX, den = 0.f;
    if (lane < 30) {
        for (int i = row + c; i < end; i += 3) {
            int s = csrc[i];
            float a = asrc[s * H + h] + adst_h;
            a = a > 0.f ? a : 0.2f * a;
            float nm = fmaxf(m, a);
            den = den * __expf(m - nm) + __expf(a - nm);
            m = nm;
        }
    }
    {
        float mA = __shfl_sync(0xffffffffu, m,   lane + 10);
        float dA = __shfl_sync(0xffffffffu, den, lane + 10);
        float mB = __shfl_sync(0xffffffffu, m,   lane + 20);
        float dB = __shfl_sync(0xffffffffu, den, lane + 20);
        float M2 = fmaxf(m, fmaxf(mA, mB));
        den = den * __expf(m - M2) + dA * __expf(mA - M2) + dB * __expf(mB - M2);
        m = M2;
    }
    const float invden = 1.0f / (den + 1e-16f);

    float4 acc4[5];
#pragma unroll
    for (int j = 0; j < 5; j++) acc4[j] = make_float4(0.f, 0.f, 0.f, 0.f);

    const int hsel = lane >> 4;
    int i = row;
    for (; i + 1 < end; i += 2) {
        int s0 = csrc[i];
        int s1 = csrc[i + 1];
        float wv0 = 0.f, wv1 = 0.f;
        if (lane < H) {
            float a0 = asrc[s0 * H + lane] + adst_h;
            float a1 = asrc[s1 * H + lane] + adst_h;
            a0 = a0 > 0.f ? a0 : 0.2f * a0;
            a1 = a1 > 0.f ? a1 : 0.2f * a1;
            wv0 = __expf(a0 - m) * invden;
            wv1 = __expf(a1 - m) * invden;
        }
        const uint2* xs0 = (const uint2*)(xlh + (size_t)s0 * HD);
        const uint2* xs1 = (const uint2*)(xlh + (size_t)s1 * HD);
        uint2 u0[5], u1[5];
#pragma unroll
        for (int j = 0; j < 5; j++) { u0[j] = xs0[lane + 32 * j]; u1[j] = xs1[lane + 32 * j]; }
#pragma unroll
        for (int j = 0; j < 5; j++) {
            float w0 = __shfl_sync(0xffffffffu, wv0, 2 * j + hsel);
            float w1 = __shfl_sync(0xffffffffu, wv1, 2 * j + hsel);
            float2 a0 = __half22float2(*(const __half2*)&u0[j].x);
            float2 b0 = __half22float2(*(const __half2*)&u0[j].y);
            float2 a1 = __half22float2(*(const __half2*)&u1[j].x);
            float2 b1 = __half22float2(*(const __half2*)&u1[j].y);
            acc4[j].x += a0.x * w0 + a1.x * w1;
            acc4[j].y += a0.y * w0 + a1.y * w1;
            acc4[j].z += b0.x * w0 + b1.x * w1;
            acc4[j].w += b0.y * w0 + b1.y * w1;
        }
    }
    if (i < end) {
        int s = csrc[i];
        float wv = 0.f;
        if (lane < H) {
            float a = asrc[s * H + lane] + adst_h;
            a = a > 0.f ? a : 0.2f * a;
            wv = __expf(a - m) * invden;
        }
        const uint2* xs = (const uint2*)(xlh + (size_t)s * HD);
#pragma unroll
        for (int j = 0; j < 5; j++) {
            float wj = __shfl_sync(0xffffffffu, wv, 2 * j + hsel);
            uint2 u = xs[lane + 32 * j];
            float2 a0 = __half22float2(*(const __half2*)&u.x);
            float2 b0 = __half22float2(*(const __half2*)&u.y);
            acc4[j].x += a0.x * wj;
            acc4[j].y += a0.y * wj;
            acc4[j].z += b0.x * wj;
            acc4[j].w += b0.y * wj;
        }
    }

    uint2* xo = (uint2*)(x1h + (size_t)w * HD);
    const float4* b4 = (const float4*)bias;
#pragma unroll
    for (int j = 0; j < 5; j++) {
        int idx = lane + 32 * j;
        float4 bb = b4[idx];
        float4 v = acc4[j];
        v.x = fmaxf(v.x + bb.x, 0.f);
        v.y = fmaxf(v.y + bb.y, 0.f);
        v.z = fmaxf(v.z + bb.z, 0.f);
        v.w = fmaxf(v.w + bb.w, 0.f);
        uint2 o;
        *(__half2*)&o.x = __floats2half2_rn(v.x, v.y);
        *(__half2*)&o.y = __floats2half2_rn(v.z, v.w);
        xo[idx] = o;
    }
}

// ----------------------------- GCN + pooling (fp16 gather) -------------------
__global__ __launch_bounds__(256)
void k_gcn_pool(const int* __restrict__ rowptr, const int* __restrict__ csrc,
                const int* __restrict__ cnt, const __half* __restrict__ xwh,
                const float* __restrict__ bias,
                float* __restrict__ pmax, float* __restrict__ psum, int N) {
    __shared__ float smax[HD];
    __shared__ float ssum[HD];
    const int tid = threadIdx.x;
    for (int i = tid; i < HD; i += 256) { smax[i] = 0.f; ssum[i] = 0.f; }
    __syncthreads();

    const int w = (blockIdx.x * blockDim.x + tid) >> 5;
    const int lane = tid & 31;

    if (w < N) {
        const int row = rowptr[w];
        const int end = rowptr[w + 1];
        const float dn = rsqrtf((float)(end - row));

        float4 acc4[5];
#pragma unroll
        for (int j = 0; j < 5; j++) acc4[j] = make_float4(0.f, 0.f, 0.f, 0.f);

        int i = row;
        for (; i + 1 < end; i += 2) {
            int s0 = csrc[i];
            int s1 = csrc[i + 1];
            float n0 = dn * rsqrtf((float)cnt[s0]);
            float n1 = dn * rsqrtf((float)cnt[s1]);
            const uint2* xs0 = (const uint2*)(xwh + (size_t)s0 * HD);
            const uint2* xs1 = (const uint2*)(xwh + (size_t)s1 * HD);
            uint2 u0[5], u1[5];
#pragma unroll
            for (int j = 0; j < 5; j++) { u0[j] = xs0[lane + 32 * j]; u1[j] = xs1[lane + 32 * j]; }
#pragma unroll
            for (int j = 0; j < 5; j++) {
                float2 a0 = __half22float2(*(const __half2*)&u0[j].x);
                float2 b0 = __half22float2(*(const __half2*)&u0[j].y);
                float2 a1 = __half22float2(*(const __half2*)&u1[j].x);
                float2 b1 = __half22float2(*(const __half2*)&u1[j].y);
                acc4[j].x += a0.x * n0 + a1.x * n1;
                acc4[j].y += a0.y * n0 + a1.y * n1;
                acc4[j].z += b0.x * n0 + b1.x * n1;
                acc4[j].w += b0.y * n0 + b1.y * n1;
            }
        }
        if (i < end) {
            int s = csrc[i];
            float nrm = dn * rsqrtf((float)cnt[s]);
            const uint2* xs = (const uint2*)(xwh + (size_t)s * HD);
#pragma unroll
            for (int j = 0; j < 5; j++) {
                uint2 u = xs[lane + 32 * j];
                float2 a0 = __half22float2(*(const __half2*)&u.x);
                float2 b0 = __half22float2(*(const __half2*)&u.y);
                acc4[j].x += a0.x * nrm;
                acc4[j].y += a0.y * nrm;
                acc4[j].z += b0.x * nrm;
                acc4[j].w += b0.y * nrm;
            }
        }

        const float4* b4 = (const float4*)bias;
#pragma unroll
        for (int j = 0; j < 5; j++) {
            int idx = lane + 32 * j;
            float4 bb = b4[idx];
            float4 v = acc4[j];
            v.x = fmaxf(v.x + bb.x, 0.f);
            v.y = fmaxf(v.y + bb.y, 0.f);
            v.z = fmaxf(v.z + bb.z, 0.f);
            v.w = fmaxf(v.w + bb.w, 0.f);
            int col = idx * 4;
            atomicMax((int*)&smax[col + 0], __float_as_int(v.x));
            atomicMax((int*)&smax[col + 1], __float_as_int(v.y));
            atomicMax((int*)&smax[col + 2], __float_as_int(v.z));
            atomicMax((int*)&smax[col + 3], __float_as_int(v.w));
            atomicAdd(&ssum[col + 0], v.x);
            atomicAdd(&ssum[col + 1], v.y);
            atomicAdd(&ssum[col + 2], v.z);
            atomicAdd(&ssum[col + 3], v.w);
        }
    }
    __syncthreads();

    for (int i = tid; i < HD; i += 256) {
        atomicMax((int*)&pmax[i], __float_as_int(smax[i]));
        atomicAdd(&psum[i], ssum[i]);
    }
}

// ----------------------------- MLP (k-split parallel) ------------------------
#define MLP_KSPLIT 10
#define MLP_JBLK   6
__global__ void k_mlp1(const float* __restrict__ pmax, const float* __restrict__ psum,
                       const float* __restrict__ W1, float* __restrict__ h1, int N) {
    const int jb = blockIdx.x % MLP_JBLK;
    const int s  = blockIdx.x / MLP_JBLK;
    const int j = jb * 256 + threadIdx.x;
    if (j >= H1DIM) return;
    const float invN = 1.0f / (float)N;
    const int k0 = s * (2 * HD / MLP_KSPLIT);
    float acc = 0.f;
#pragma unroll 4
    for (int k = k0; k < k0 + 2 * HD / MLP_KSPLIT; k++) {
        float v = (k < HD) ? pmax[k] : psum[k - HD] * invN;
        acc += v * W1[(size_t)k * H1DIM + j];
    }
    atomicAdd(&h1[j], acc);
}

__global__ void k_mlp2(const float* __restrict__ h1, const float* __restrict__ W2,
                       const float* __restrict__ b2, float* __restrict__ out) {
    __shared__ float acc[10];
    int tid = threadIdx.x;
    if (tid < 10) acc[tid] = 0.0f;
    __syncthreads();
    float part[10];
#pragma unroll
    for (int j = 0; j < 10; j++) part[j] = 0.0f;
    for (int k = tid; k < H1DIM; k += 256) {
        float hv = fmaxf(h1[k], 0.0f);
#pragma unroll
        for (int j = 0; j < 10; j++) part[j] += hv * W2[k * 10 + j];
    }
#pragma unroll
    for (int j = 0; j < 10; j++) atomicAdd(&acc[j], part[j]);
    __syncthreads();
    if (tid < 10) out[tid] = acc[tid] + b2[tid];
}

// ----------------------------- launch -----------------------------------------
static inline int cdiv(int a, int b) { return (a + b - 1) / b; }

extern "C" void kernel_launch(void* const* d_in, const int* in_sizes, int n_in,
                              void* d_out, int out_size) {
    const float* x       = (const float*)d_in[0];
    const float* W_gat   = (const float*)d_in[1];
    const float* att_src = (const float*)d_in[2];
    const float* att_dst = (const float*)d_in[3];
    const float* b_gat   = (const float*)d_in[4];
    const float* W_gcn   = (const float*)d_in[5];
    const float* b_gcn   = (const float*)d_in[6];
    const float* W1      = (const float*)d_in[7];
    const float* b1      = (const float*)d_in[8];
    const float* W2      = (const float*)d_in[9];
    const float* b2      = (const float*)d_in[10];
    const int*   ei      = (const int*)d_in[11];

    const int N  = in_sizes[0] / D;
    const int E  = in_sizes[11] / 2;
    const int EP = E + N;
    float* out = (float*)d_out;

    __half *p_xlh, *p_x1h, *p_xwh, *p_wth;
    float *p_asrc, *p_adst, *p_pmax, *p_psum, *p_h1;
    int *p_cnt, *p_rowptr, *p_cursor, *p_csrc;
    cudaGetSymbolAddress((void**)&p_xlh,    g_xlh);
    cudaGetSymbolAddress((void**)&p_x1h,    g_x1h);
    cudaGetSymbolAddress((void**)&p_xwh,    g_xwh);
    cudaGetSymbolAddress((void**)&p_wth,    g_wth);
    cudaGetSymbolAddress((void**)&p_asrc,   g_asrc);
    cudaGetSymbolAddress((void**)&p_adst,   g_adst);
    cudaGetSymbolAddress((void**)&p_pmax,   g_pmax);
    cudaGetSymbolAddress((void**)&p_psum,   g_psum);
    cudaGetSymbolAddress((void**)&p_h1,     g_h1);
    cudaGetSymbolAddress((void**)&p_cnt,    g_cnt);
    cudaGetSymbolAddress((void**)&p_rowptr, g_rowptr);
    cudaGetSymbolAddress((void**)&p_cursor, g_cursor);
    cudaGetSymbolAddress((void**)&p_csrc,   g_csrc);

    // side stream + events (leaked by design; capture-safe)
    cudaStream_t s2;
    cudaStreamCreate(&s2);
    cudaEvent_t evF, evJ;
    cudaEventCreateWithFlags(&evF, cudaEventDisableTiming);
    cudaEventCreateWithFlags(&evJ, cudaEventDisableTiming);

    // fork: side stream runs GEMM1 + the heavy setup (W^T fp16, pool/h1 init)
    cudaEventRecord(evF, 0);
    cudaStreamWaitEvent(s2, evF, 0);
    k_gemm1_h<<<cdiv(N, 128) * (HD / 128), 256, 0, s2>>>(
        x, W_gat, p_xlh, N, HD, D, att_src, att_dst, p_asrc, p_adst);
    k_setup_w<<<cdiv(2 * HD + H1DIM + HD * HD, 256), 256, 0, s2>>>(
        p_pmax, p_psum, p_h1, b1, W_gcn, p_wth);
    cudaEventRecord(evJ, s2);

    // main stream: minimal CSR critical path
    k_zero_cnt<<<cdiv(N, 256), 256>>>(p_cnt, N);
    k_count<<<cdiv(EP, 256), 256>>>(ei, p_cnt, E, N);
    k_scan<<<1, 1024>>>(p_cnt, p_rowptr, p_cursor, N, EP);
    k_scatter<<<cdiv(EP, 256), 256>>>(ei, p_cursor, p_csrc, E, N);

    // join: k_gat needs CSR + GEMM1 outputs (and later kernels need setup_w)
    cudaStreamWaitEvent(0, evJ, 0);
    k_gat<<<cdiv(N * 32, 256), 256>>>(p_rowptr, p_csrc, p_xlh, p_asrc, p_adst,
                                      b_gat, p_x1h, N);
    // GEMM2 (fp16 mma.sync m16n8k16, 3-stage cp.async)
    cudaFuncSetAttribute(k_gemm2_h, cudaFuncAttributeMaxDynamicSharedMemorySize, G2H_SMEM);
    k_gemm2_h<<<cdiv(N, 128) * (HD / 128), 256, G2H_SMEM>>>(p_x1h, p_wth, p_xwh, N, HD, HD);
    // GCN aggregation + fused global pooling (fp16 gather)
    k_gcn_pool<<<cdiv(N * 32, 256), 256>>>(p_rowptr, p_csrc, p_cnt, p_xwh, b_gcn,
                                           p_pmax, p_psum, N);
    // MLP head
    k_mlp1<<<MLP_JBLK * MLP_KSPLIT, 256>>>(p_pmax, p_psum, W1, p_h1, N);
    k_mlp2<<<1, 256>>>(p_h1, W2, b2, out);
}